// round 1
// baseline (speedup 1.0000x reference)
#include <cuda_runtime.h>
#include <cuda_bf16.h>
#include <math.h>

// ============================================================================
// ILCMDecoder: flow log-prob (16 tiny per-dim MLPs) + shared 3-layer decoder
// applied to e1 and e2 (fused as one M=16384 batch).
//
// Inputs (metadata order):
//  0 e1   (8192,16) f32      1 e2  (8192,16) f32    2 intervention (8192,17)
//  3 W1 (16,16,64)  4 b1 (16,64)  5 W2 (16,64,64)  6 b2 (16,64)
//  7 W3 (16,64,2)   8 b3 (16,2)
//  9 Wd1 (16,1024) 10 bd1 (1024) 11 Wd2 (1024,1024) 12 bd2 (1024)
// 13 Wd3 (1024,3072) 14 bd3 (3072)
// Output: x1_hat (8192*3072) | x2_hat (8192*3072) | log_p (1)  — all f32
// ============================================================================

#define B_TOT   16384          // 2 * 8192 (e1 rows then e2 rows)
#define B_HALF  8192
#define DIMZ    16
#define HDIM    64
#define DECH    1024
#define DIMX    3072
#define LOG2PI  1.8378770664093453f
#define MIN_STD 0.2f
#define CLAMP_V 1000000.0f

// scratch (device globals: allocation-free per harness rules)
__device__ float g_hbuf1[(size_t)B_TOT * DECH];   // 64 MB
__device__ float g_hbuf2[(size_t)B_TOT * DECH];   // 64 MB
__device__ float g_partial[1024];

__device__ __forceinline__ float clean_clamp(float x) {
    if (isnan(x)) x = 0.0f;
    return fminf(fmaxf(x, -CLAMP_V), CLAMP_V);
}

// ----------------------------------------------------------------------------
// Layer 1 of decoder: H = relu(E @ Wd1 + bd1), E = concat(e1, e2) rows, K=16.
// One block per row; Wd1 (64KB) stays L1-resident.
// ----------------------------------------------------------------------------
__global__ void dec1_kernel(const float* __restrict__ e1,
                            const float* __restrict__ e2,
                            const float* __restrict__ Wd1,
                            const float* __restrict__ bd1) {
    __shared__ float se[DIMZ];
    int b = blockIdx.x;
    const float* src = (b < B_HALF) ? (e1 + (size_t)b * DIMZ)
                                    : (e2 + (size_t)(b - B_HALF) * DIMZ);
    if (threadIdx.x < DIMZ) se[threadIdx.x] = src[threadIdx.x];
    __syncthreads();

    int tid = threadIdx.x; // 256 threads, 4 cols each (stride 256 for coalescing)
    float acc[4];
#pragma unroll
    for (int c = 0; c < 4; c++) acc[c] = bd1[tid + c * 256];
#pragma unroll
    for (int d = 0; d < DIMZ; d++) {
        float ed = se[d];
#pragma unroll
        for (int c = 0; c < 4; c++)
            acc[c] = fmaf(ed, Wd1[d * DECH + tid + c * 256], acc[c]);
    }
    float* Hrow = g_hbuf1 + (size_t)b * DECH;
#pragma unroll
    for (int c = 0; c < 4; c++) Hrow[tid + c * 256] = fmaxf(acc[c], 0.0f);
}

// ----------------------------------------------------------------------------
// Tiled fp32 SGEMM: C[M,N] = (relu?)(A[M,K] @ B[K,N] + bias[N])
// 128x128 block tile, BK=8, 256 threads, 8x8 per-thread, 2-stage smem buffer.
// All dims divisible by tile sizes (M=16384, N in {1024,3072}, K=1024).
// ----------------------------------------------------------------------------
template <bool RELU>
__global__ __launch_bounds__(256, 1)
void sgemm_kernel(const float* __restrict__ A, const float* __restrict__ B,
                  const float* __restrict__ bias, float* __restrict__ C,
                  int M, int N, int K) {
    __shared__ float As[2][8][128];
    __shared__ float Bs[2][8][128];

    const int tid = threadIdx.x;
    const int tx = tid & 15;       // 0..15 (n)
    const int ty = tid >> 4;       // 0..15 (m)
    const int m0 = blockIdx.y * 128;
    const int n0 = blockIdx.x * 128;

    // A-tile load map: 128 rows x 8 cols, one float4 per thread
    const int arow = tid >> 1;             // 0..127
    const int acol = (tid & 1) * 4;        // 0 or 4
    // B-tile load map: 8 rows x 128 cols, one float4 per thread
    const int brow = tid >> 5;             // 0..7
    const int bcol = (tid & 31) * 4;       // 0..124

    const float* Aptr = A + (size_t)(m0 + arow) * K + acol;
    const float* Bptr = B + (size_t)brow * N + n0 + bcol;

    float acc[8][8];
#pragma unroll
    for (int i = 0; i < 8; i++)
#pragma unroll
        for (int j = 0; j < 8; j++) acc[i][j] = 0.0f;

    // preload tile 0
    {
        float4 a4 = *(const float4*)(Aptr);
        float4 b4 = *(const float4*)(Bptr);
        As[0][acol + 0][arow] = a4.x;
        As[0][acol + 1][arow] = a4.y;
        As[0][acol + 2][arow] = a4.z;
        As[0][acol + 3][arow] = a4.w;
        *(float4*)&Bs[0][brow][bcol] = b4;
    }
    __syncthreads();

    const int KT = K >> 3;
    int buf = 0;
    for (int kt = 0; kt < KT; kt++) {
        float4 na, nb;
        const bool more = (kt + 1 < KT);
        if (more) {
            na = *(const float4*)(Aptr + (size_t)(kt + 1) * 8);
            nb = *(const float4*)(Bptr + (size_t)(kt + 1) * 8 * N);
        }
#pragma unroll
        for (int kk = 0; kk < 8; kk++) {
            float af[8], bf[8];
#pragma unroll
            for (int q = 0; q < 8; q++) af[q] = As[buf][kk][ty * 8 + q];
#pragma unroll
            for (int q = 0; q < 8; q++) bf[q] = Bs[buf][kk][tx * 8 + q];
#pragma unroll
            for (int i = 0; i < 8; i++)
#pragma unroll
                for (int j = 0; j < 8; j++)
                    acc[i][j] = fmaf(af[i], bf[j], acc[i][j]);
        }
        if (more) {
            int nb2 = buf ^ 1;
            As[nb2][acol + 0][arow] = na.x;
            As[nb2][acol + 1][arow] = na.y;
            As[nb2][acol + 2][arow] = na.z;
            As[nb2][acol + 3][arow] = na.w;
            *(float4*)&Bs[nb2][brow][bcol] = nb;
            __syncthreads();
            buf = nb2;
        }
    }

    // epilogue: bias (+ optional relu), vectorized stores
    float bv[8];
#pragma unroll
    for (int j = 0; j < 8; j++) bv[j] = bias[n0 + tx * 8 + j];
#pragma unroll
    for (int i = 0; i < 8; i++) {
        int m = m0 + ty * 8 + i;
        float* Crow = C + (size_t)m * N + n0 + tx * 8;
        float v[8];
#pragma unroll
        for (int j = 0; j < 8; j++) {
            float t = acc[i][j] + bv[j];
            v[j] = RELU ? fmaxf(t, 0.0f) : t;
        }
        *(float4*)(Crow + 0) = make_float4(v[0], v[1], v[2], v[3]);
        *(float4*)(Crow + 4) = make_float4(v[4], v[5], v[6], v[7]);
    }
}

// ----------------------------------------------------------------------------
// Flow: per-dim MLP 16->64->64->2, shift/scale, masked logprob of e2,
// plus the e1 std-normal logprob terms. Block-partial sums -> g_partial.
// grid = (64 batch-blocks, 16 dims), 128 threads (one batch elem per thread).
// ----------------------------------------------------------------------------
__global__ __launch_bounds__(128)
void flow_kernel(const float* __restrict__ e1, const float* __restrict__ e2,
                 const float* __restrict__ interv,
                 const float* __restrict__ W1, const float* __restrict__ b1,
                 const float* __restrict__ W2, const float* __restrict__ b2,
                 const float* __restrict__ W3, const float* __restrict__ b3) {
    __shared__ float sW1[DIMZ * HDIM];     // 16*64
    __shared__ float sW2[HDIM * HDIM];     // 64*64
    __shared__ float sW3[HDIM * 2];
    __shared__ float sb1[HDIM], sb2[HDIM], sb3v[2];
    __shared__ float red[128];

    const int i = blockIdx.y;
    const int tid = threadIdx.x;

    for (int t = tid; t < DIMZ * HDIM; t += 128) sW1[t] = W1[i * DIMZ * HDIM + t];
    for (int t = tid; t < HDIM * HDIM; t += 128) sW2[t] = W2[i * HDIM * HDIM + t];
    if (tid < HDIM * 2) sW3[tid] = W3[i * HDIM * 2 + tid];
    if (tid < HDIM) { sb1[tid] = b1[i * HDIM + tid]; sb2[tid] = b2[i * HDIM + tid]; }
    if (tid < 2) sb3v[tid] = b3[i * 2 + tid];
    __syncthreads();

    const int b = blockIdx.x * 128 + tid;

    // ctx = e1 row with element i zeroed; keep e1[b][i] for its logprob term
    float ctx[DIMZ];
    float e1_i = 0.0f;
#pragma unroll
    for (int d = 0; d < DIMZ; d++) {
        float v = e1[(size_t)b * DIMZ + d];
        if (d == i) { e1_i = v; v = 0.0f; }
        ctx[d] = v;
    }

    // layer 1 (fully unrolled so h1 stays in registers)
    float h1[HDIM];
#pragma unroll
    for (int j = 0; j < HDIM; j++) {
        float a = sb1[j];
#pragma unroll
        for (int d = 0; d < DIMZ; d++) a = fmaf(ctx[d], sW1[d * HDIM + j], a);
        h1[j] = fmaxf(a, 0.0f);
    }

    // layer 2 + 3 fused: accumulate p0/p1 as each h2_k is produced
    float p0 = sb3v[0], p1 = sb3v[1];
    for (int k = 0; k < HDIM; k++) {
        float t = sb2[k];
#pragma unroll
        for (int j = 0; j < HDIM; j++) t = fmaf(h1[j], sW2[j * HDIM + k], t);
        t = fmaxf(t, 0.0f);
        p0 = fmaf(t, sW3[k * 2 + 0], p0);
        p1 = fmaf(t, sW3[k * 2 + 1], p1);
    }

    // scale = softplus(p1) + MIN_STD  (stable: max(x,0) + log1p(exp(-|x|)))
    float sp = fmaxf(p1, 0.0f) + log1pf(expf(-fabsf(p1)));
    float scale = sp + MIN_STD;

    float z = (e2[(size_t)b * DIMZ + i] - p0) / scale;
    z = clean_clamp(z);
    float mask = interv[(size_t)b * (DIMZ + 1) + 1 + i];
    float lp2 = (-0.5f * z * z - 0.5f * LOG2PI - logf(scale)) * mask;

    float lp1 = clean_clamp(-0.5f * e1_i * e1_i - 0.5f * LOG2PI);

    red[tid] = lp1 + lp2;
    __syncthreads();
#pragma unroll
    for (int s = 64; s > 0; s >>= 1) {
        if (tid < s) red[tid] += red[tid + s];
        __syncthreads();
    }
    if (tid == 0) g_partial[blockIdx.y * gridDim.x + blockIdx.x] = red[0];
}

// Final deterministic reduce of 1024 partials + log_p_I constant
__global__ void reduce_final_kernel(float* __restrict__ out_scalar) {
    __shared__ float red[256];
    int tid = threadIdx.x;
    float s = 0.0f;
    for (int t = tid; t < 1024; t += 256) s += g_partial[t];
    red[tid] = s;
    __syncthreads();
#pragma unroll
    for (int st = 128; st > 0; st >>= 1) {
        if (tid < st) red[tid] += red[tid + st];
        __syncthreads();
    }
    if (tid == 0) {
        float log_p_I = -logf((float)(DIMZ + 1)) * (float)B_HALF;
        *out_scalar = red[0] + log_p_I;
    }
}

// ----------------------------------------------------------------------------
extern "C" void kernel_launch(void* const* d_in, const int* in_sizes, int n_in,
                              void* d_out, int out_size) {
    const float* e1   = (const float*)d_in[0];
    const float* e2   = (const float*)d_in[1];
    const float* itv  = (const float*)d_in[2];
    const float* W1   = (const float*)d_in[3];
    const float* b1   = (const float*)d_in[4];
    const float* W2   = (const float*)d_in[5];
    const float* b2   = (const float*)d_in[6];
    const float* W3   = (const float*)d_in[7];
    const float* b3   = (const float*)d_in[8];
    const float* Wd1  = (const float*)d_in[9];
    const float* bd1  = (const float*)d_in[10];
    const float* Wd2  = (const float*)d_in[11];
    const float* bd2  = (const float*)d_in[12];
    const float* Wd3  = (const float*)d_in[13];
    const float* bd3  = (const float*)d_in[14];
    float* out = (float*)d_out;

    void *p_h1, *p_h2;
    cudaGetSymbolAddress(&p_h1, g_hbuf1);
    cudaGetSymbolAddress(&p_h2, g_hbuf2);
    float* h1 = (float*)p_h1;
    float* h2 = (float*)p_h2;

    // flow log-prob (independent of decoder chain)
    flow_kernel<<<dim3(64, 16), 128>>>(e1, e2, itv, W1, b1, W2, b2, W3, b3);
    reduce_final_kernel<<<1, 256>>>(out + ((size_t)out_size - 1));

    // decoder chain: h1 = relu(E@Wd1+bd1); h2 = relu(h1@Wd2+bd2); out = h2@Wd3+bd3
    dec1_kernel<<<B_TOT, 256>>>(e1, e2, Wd1, bd1);
    sgemm_kernel<true ><<<dim3(DECH / 128, B_TOT / 128), 256>>>(h1, Wd2, bd2, h2,
                                                                B_TOT, DECH, DECH);
    sgemm_kernel<false><<<dim3(DIMX / 128, B_TOT / 128), 256>>>(h2, Wd3, bd3, out,
                                                                B_TOT, DIMX, DECH);
}

// round 3
// speedup vs baseline: 2.7385x; 2.7385x over previous
#include <cuda_runtime.h>
#include <cuda_bf16.h>
#include <math.h>
#include <stdint.h>

// ============================================================================
// ILCMDecoder on GB300 (family-baseline PTX path: mma.sync HMMA + ldmatrix +
// cp.async — tcgen05 is rejected by this harness's ptxas target sm_103).
//
// Decoder GEMMs (M=16384, K=1024, N=1024/3072) use bf16x3 split precision:
//   v = hi + lo (bf16 each),  D += Ah*Bh + Al*Bh + Ah*Bl  (fp32 accum)
// Error ~2^-16 relative. Flow log-prob computed by a small fused kernel.
// ============================================================================

#define B_TOT   16384
#define B_HALF  8192
#define DIMZ    16
#define HDIM    64
#define DECH    1024
#define DIMX    3072
#define KTOT    1024
#define LOG2PI  1.8378770664093453f
#define MIN_STD 0.2f
#define CLAMP_V 1000000.0f

// ---------------- device scratch (allocation-free) ----------------
__device__ __nv_bfloat16 g_h1h[(size_t)B_TOT * DECH];
__device__ __nv_bfloat16 g_h1l[(size_t)B_TOT * DECH];
__device__ __nv_bfloat16 g_h2h[(size_t)B_TOT * DECH];
__device__ __nv_bfloat16 g_h2l[(size_t)B_TOT * DECH];
__device__ __nv_bfloat16 g_w2h[(size_t)DECH * DECH];   // Wd2^T hi  [N,K]
__device__ __nv_bfloat16 g_w2l[(size_t)DECH * DECH];
__device__ __nv_bfloat16 g_w3h[(size_t)DIMX * DECH];   // Wd3^T hi  [N,K]
__device__ __nv_bfloat16 g_w3l[(size_t)DIMX * DECH];
__device__ float g_partial[1024];

// ---------------- PTX helpers (baseline family features only) --------------
__device__ __forceinline__ uint32_t smem_u32(const void* p) {
    uint32_t a;
    asm("{ .reg .u64 t; cvta.to.shared.u64 t, %1; cvt.u32.u64 %0, t; }"
        : "=r"(a) : "l"(p));
    return a;
}

#define CP_ASYNC16(smem, gptr) \
    asm volatile("cp.async.cg.shared.global [%0], [%1], 16;" \
        :: "r"((uint32_t)(smem)), "l"(gptr) : "memory")
#define CP_COMMIT() asm volatile("cp.async.commit_group;" ::: "memory")
#define CP_WAIT1()  asm volatile("cp.async.wait_group 1;" ::: "memory")
#define CP_WAIT0()  asm volatile("cp.async.wait_group 0;" ::: "memory")

__device__ __forceinline__ void ldsm_x4(uint32_t* r, uint32_t addr) {
    asm volatile("ldmatrix.sync.aligned.m8n8.x4.shared.b16 {%0,%1,%2,%3}, [%4];"
        : "=r"(r[0]), "=r"(r[1]), "=r"(r[2]), "=r"(r[3]) : "r"(addr));
}

__device__ __forceinline__ void mma_bf16(float* d, const uint32_t* a, const uint32_t* b) {
    asm volatile(
        "mma.sync.aligned.m16n8k16.row.col.f32.bf16.bf16.f32 "
        "{%0,%1,%2,%3}, {%4,%5,%6,%7}, {%8,%9}, {%0,%1,%2,%3};"
        : "+f"(d[0]), "+f"(d[1]), "+f"(d[2]), "+f"(d[3])
        : "r"(a[0]), "r"(a[1]), "r"(a[2]), "r"(a[3]), "r"(b[0]), "r"(b[1]));
}

__device__ __forceinline__ float clean_clamp(float x) {
    if (isnan(x)) x = 0.0f;
    return fminf(fmaxf(x, -CLAMP_V), CLAMP_V);
}

__device__ __forceinline__ void split2(float v, __nv_bfloat16& h, __nv_bfloat16& l) {
    h = __float2bfloat16(v);
    l = __float2bfloat16(v - __bfloat162float(h));
}

// ============================================================================
// Weight transpose + bf16 split:  W[K,N] fp32 -> Th/Tl[N,K] bf16
// ============================================================================
__global__ void tsplit_kernel(const float* __restrict__ W,
                              __nv_bfloat16* __restrict__ Th,
                              __nv_bfloat16* __restrict__ Tl, int K, int N) {
    __shared__ float tile[32][33];
    int nb = blockIdx.x * 32, kb = blockIdx.y * 32;
    int tx = threadIdx.x & 31, ty0 = threadIdx.x >> 5;
    for (int i = ty0; i < 32; i += 8)
        tile[i][tx] = W[(size_t)(kb + i) * N + nb + tx];
    __syncthreads();
    for (int i = ty0; i < 32; i += 8) {
        float v = tile[tx][i];
        __nv_bfloat16 h, l; split2(v, h, l);
        size_t o = (size_t)(nb + i) * K + kb + tx;
        Th[o] = h; Tl[o] = l;
    }
}

// ============================================================================
// Decoder layer 1: H1 = relu(E @ Wd1 + bd1), split to bf16 hi/lo.
// ============================================================================
__global__ void dec1_kernel(const float* __restrict__ e1, const float* __restrict__ e2,
                            const float* __restrict__ Wd1, const float* __restrict__ bd1,
                            __nv_bfloat16* __restrict__ Hh, __nv_bfloat16* __restrict__ Hl) {
    __shared__ float se[DIMZ];
    int b = blockIdx.x;
    const float* src = (b < B_HALF) ? (e1 + (size_t)b * DIMZ)
                                    : (e2 + (size_t)(b - B_HALF) * DIMZ);
    if (threadIdx.x < DIMZ) se[threadIdx.x] = src[threadIdx.x];
    __syncthreads();
    int tid = threadIdx.x;   // 256 threads
#pragma unroll
    for (int c = 0; c < 2; c++) {
        int col = c * 512 + tid * 2;
        float a0 = bd1[col], a1 = bd1[col + 1];
#pragma unroll
        for (int d = 0; d < DIMZ; d++) {
            float ed = se[d];
            a0 = fmaf(ed, Wd1[d * DECH + col],     a0);
            a1 = fmaf(ed, Wd1[d * DECH + col + 1], a1);
        }
        a0 = fmaxf(a0, 0.0f); a1 = fmaxf(a1, 0.0f);
        __nv_bfloat16 h0, l0, h1, l1;
        split2(a0, h0, l0); split2(a1, h1, l1);
        __nv_bfloat162 hh; hh.x = h0; hh.y = h1;
        __nv_bfloat162 ll; ll.x = l0; ll.y = l1;
        *(__nv_bfloat162*)(Hh + (size_t)b * DECH + col) = hh;
        *(__nv_bfloat162*)(Hl + (size_t)b * DECH + col) = ll;
    }
}

// ============================================================================
// bf16x3 HMMA GEMM:  C[M, Ntot] = epi(A @ B^T + bias)
//   A hi/lo [M,1024] bf16 row-major; B hi/lo [Ntot,1024] bf16 row-major.
// CTA 128x128, 8 warps (warp tile 64x32), BK=64, 3-stage cp.async pipeline.
// EPI=0: fp32 out.  EPI=1: relu + bf16 hi/lo split out.
// ============================================================================
#define BK       64
#define NCHUNK  (KTOT / BK)       // 16
#define MAT_BYTES 16384           // 128 rows x 128B
#define AH_OFF  0
#define AL_OFF  16384
#define BH_OFF  32768
#define BL_OFF  49152
#define STG_BYTES 65536
#define NSTG    3
#define SMEM_DYN (NSTG * STG_BYTES + 1024)

__device__ __forceinline__ uint32_t sw128(uint32_t byte) {
    return byte ^ ((byte >> 3) & 0x70);
}

// 256 threads: load one 128(M)x64 + 128(N)x64 chunk (hi+lo) into a stage.
__device__ __forceinline__ void load_stage(
    uint32_t stg,
    const __nv_bfloat16* __restrict__ Ah, const __nv_bfloat16* __restrict__ Al,
    const __nv_bfloat16* __restrict__ Bh, const __nv_bfloat16* __restrict__ Bl,
    int m0, int n0, int kBase, int tid)
{
    const int c16 = tid & 7;        // 16B column within 128B row
    const int rg  = tid >> 3;       // 0..31
    const int kOff = kBase + c16 * 8;
#pragma unroll
    for (int j = 0; j < 4; j++) {
        int row = rg + j * 32;
        uint32_t sw = sw128((uint32_t)row * 128 + c16 * 16);
        CP_ASYNC16(stg + AH_OFF + sw, Ah + (size_t)(m0 + row) * KTOT + kOff);
        CP_ASYNC16(stg + AL_OFF + sw, Al + (size_t)(m0 + row) * KTOT + kOff);
        CP_ASYNC16(stg + BH_OFF + sw, Bh + (size_t)(n0 + row) * KTOT + kOff);
        CP_ASYNC16(stg + BL_OFF + sw, Bl + (size_t)(n0 + row) * KTOT + kOff);
    }
}

template <int EPI>
__global__ __launch_bounds__(256, 1)
void gemm_kernel(const __nv_bfloat16* __restrict__ Ah, const __nv_bfloat16* __restrict__ Al,
                 const __nv_bfloat16* __restrict__ Bh, const __nv_bfloat16* __restrict__ Bl,
                 const float* __restrict__ bias,
                 float* __restrict__ Cf,
                 __nv_bfloat16* __restrict__ Ch, __nv_bfloat16* __restrict__ Cl,
                 int Ntot)
{
    extern __shared__ char dsm[];
    const uint32_t sbase = (smem_u32(dsm) + 1023) & ~1023u;

    const int tid  = threadIdx.x;
    const int warp = tid >> 5;
    const int lane = tid & 31;
    const int wm   = warp & 1;          // 2 M-slices of 64
    const int wn   = warp >> 1;         // 4 N-slices of 32
    const int m0   = blockIdx.y * 128;
    const int n0   = blockIdx.x * 128;

    const int lrow = lane & 7;
    const int quad = lane >> 3;
    // A ldmatrix per-thread row/col components (tiles: m0k0, m8k0, m0k8, m8k8)
    const int aRow = wm * 64 + (quad & 1) * 8 + lrow;
    const int aKb  = (quad >> 1) * 16;
    // B ldmatrix per-thread components (tiles: n0k0, n0k8, n8k0, n8k8)
    const int bRow = wn * 32 + (quad >> 1) * 8 + lrow;
    const int bKb  = (quad & 1) * 16;

    float acc[4][4][4];
#pragma unroll
    for (int i = 0; i < 4; i++)
#pragma unroll
        for (int j = 0; j < 4; j++)
#pragma unroll
            for (int q = 0; q < 4; q++) acc[i][j][q] = 0.0f;

    // prologue: chunks 0,1
    load_stage(sbase,             Ah, Al, Bh, Bl, m0, n0, 0,  tid); CP_COMMIT();
    load_stage(sbase + STG_BYTES, Ah, Al, Bh, Bl, m0, n0, BK, tid); CP_COMMIT();

#pragma unroll 1
    for (int c = 0; c < NCHUNK; c++) {
        if (c + 2 < NCHUNK) { CP_WAIT1(); } else { CP_WAIT0(); }
        __syncthreads();
        if (c + 2 < NCHUNK) {
            load_stage(sbase + ((c + 2) % NSTG) * STG_BYTES,
                       Ah, Al, Bh, Bl, m0, n0, (c + 2) * BK, tid);
            CP_COMMIT();
        }
        const uint32_t stg = sbase + (c % NSTG) * STG_BYTES;

#pragma unroll
        for (int kk = 0; kk < 4; kk++) {
            uint32_t a_h[4][4], a_l[4][4], b_h[2][4], b_l[2][4];
#pragma unroll
            for (int i = 0; i < 4; i++) {
                uint32_t sw = sw128((uint32_t)(aRow + i * 16) * 128 + kk * 32 + aKb);
                ldsm_x4(a_h[i], stg + AH_OFF + sw);
                ldsm_x4(a_l[i], stg + AL_OFF + sw);
            }
#pragma unroll
            for (int g = 0; g < 2; g++) {
                uint32_t sw = sw128((uint32_t)(bRow + g * 16) * 128 + kk * 32 + bKb);
                ldsm_x4(b_h[g], stg + BH_OFF + sw);
                ldsm_x4(b_l[g], stg + BL_OFF + sw);
            }
#pragma unroll
            for (int i = 0; i < 4; i++)
#pragma unroll
                for (int j = 0; j < 4; j++) {
                    const uint32_t* bh = &b_h[j >> 1][(j & 1) * 2];
                    const uint32_t* bl = &b_l[j >> 1][(j & 1) * 2];
                    mma_bf16(acc[i][j], a_h[i], bh);
                    mma_bf16(acc[i][j], a_l[i], bh);
                    mma_bf16(acc[i][j], a_h[i], bl);
                }
        }
    }

    // ---------------- epilogue (register direct) ----------------
    const int er = lane >> 2;            // 0..7 (row within atom)
    const int ec = (lane & 3) * 2;       // 0,2,4,6 (col pair)
#pragma unroll
    for (int i = 0; i < 4; i++) {
        int mrow = m0 + wm * 64 + i * 16 + er;
#pragma unroll
        for (int j = 0; j < 4; j++) {
            int n = n0 + wn * 32 + j * 8 + ec;
            float b0 = bias[n], b1 = bias[n + 1];
            float v0 = acc[i][j][0] + b0, v1 = acc[i][j][1] + b1;
            float v2 = acc[i][j][2] + b0, v3 = acc[i][j][3] + b1;
            size_t g0 = (size_t)mrow * Ntot + n;
            size_t g1 = (size_t)(mrow + 8) * Ntot + n;
            if (EPI == 0) {
                *(float2*)(Cf + g0) = make_float2(v0, v1);
                *(float2*)(Cf + g1) = make_float2(v2, v3);
            } else {
                v0 = fmaxf(v0, 0.0f); v1 = fmaxf(v1, 0.0f);
                v2 = fmaxf(v2, 0.0f); v3 = fmaxf(v3, 0.0f);
                __nv_bfloat16 h0,l0,h1,l1,h2,l2,h3,l3;
                split2(v0,h0,l0); split2(v1,h1,l1);
                split2(v2,h2,l2); split2(v3,h3,l3);
                __nv_bfloat162 p; __nv_bfloat162 q;
                p.x = h0; p.y = h1; q.x = l0; q.y = l1;
                *(__nv_bfloat162*)(Ch + g0) = p;
                *(__nv_bfloat162*)(Cl + g0) = q;
                p.x = h2; p.y = h3; q.x = l2; q.y = l3;
                *(__nv_bfloat162*)(Ch + g1) = p;
                *(__nv_bfloat162*)(Cl + g1) = q;
            }
        }
    }
}

// ============================================================================
// Flow: per-dim MLP 16->64->64->2 + masked logprob + e1 logprob
// ============================================================================
__global__ __launch_bounds__(128)
void flow_kernel(const float* __restrict__ e1, const float* __restrict__ e2,
                 const float* __restrict__ interv,
                 const float* __restrict__ W1, const float* __restrict__ b1,
                 const float* __restrict__ W2, const float* __restrict__ b2,
                 const float* __restrict__ W3, const float* __restrict__ b3) {
    __shared__ float sW1[DIMZ * HDIM];
    __shared__ float sW2[HDIM * HDIM];
    __shared__ float sW3[HDIM * 2];
    __shared__ float sb1[HDIM], sb2[HDIM], sb3v[2];
    __shared__ float red[128];

    const int i = blockIdx.y;
    const int tid = threadIdx.x;

    for (int t = tid; t < DIMZ * HDIM; t += 128) sW1[t] = W1[i * DIMZ * HDIM + t];
    for (int t = tid; t < HDIM * HDIM; t += 128) sW2[t] = W2[i * HDIM * HDIM + t];
    if (tid < HDIM * 2) sW3[tid] = W3[i * HDIM * 2 + tid];
    if (tid < HDIM) { sb1[tid] = b1[i * HDIM + tid]; sb2[tid] = b2[i * HDIM + tid]; }
    if (tid < 2) sb3v[tid] = b3[i * 2 + tid];
    __syncthreads();

    const int b = blockIdx.x * 128 + tid;

    float ctx[DIMZ];
    float e1_i = 0.0f;
#pragma unroll
    for (int d = 0; d < DIMZ; d++) {
        float v = e1[(size_t)b * DIMZ + d];
        if (d == i) { e1_i = v; v = 0.0f; }
        ctx[d] = v;
    }

    float h1[HDIM];
#pragma unroll
    for (int j = 0; j < HDIM; j++) {
        float a = sb1[j];
#pragma unroll
        for (int d = 0; d < DIMZ; d++) a = fmaf(ctx[d], sW1[d * HDIM + j], a);
        h1[j] = fmaxf(a, 0.0f);
    }

    float p0 = sb3v[0], p1 = sb3v[1];
    for (int k = 0; k < HDIM; k++) {
        float t = sb2[k];
#pragma unroll
        for (int j = 0; j < HDIM; j++) t = fmaf(h1[j], sW2[j * HDIM + k], t);
        t = fmaxf(t, 0.0f);
        p0 = fmaf(t, sW3[k * 2 + 0], p0);
        p1 = fmaf(t, sW3[k * 2 + 1], p1);
    }

    float sp = fmaxf(p1, 0.0f) + log1pf(expf(-fabsf(p1)));
    float scale = sp + MIN_STD;

    float z = (e2[(size_t)b * DIMZ + i] - p0) / scale;
    z = clean_clamp(z);
    float mask = interv[(size_t)b * (DIMZ + 1) + 1 + i];
    float lp2 = (-0.5f * z * z - 0.5f * LOG2PI - logf(scale)) * mask;
    float lp1 = clean_clamp(-0.5f * e1_i * e1_i - 0.5f * LOG2PI);

    red[tid] = lp1 + lp2;
    __syncthreads();
#pragma unroll
    for (int s = 64; s > 0; s >>= 1) {
        if (tid < s) red[tid] += red[tid + s];
        __syncthreads();
    }
    if (tid == 0) g_partial[blockIdx.y * gridDim.x + blockIdx.x] = red[0];
}

__global__ void reduce_final_kernel(float* __restrict__ out_scalar) {
    __shared__ float red[256];
    int tid = threadIdx.x;
    float s = 0.0f;
    for (int t = tid; t < 1024; t += 256) s += g_partial[t];
    red[tid] = s;
    __syncthreads();
#pragma unroll
    for (int st = 128; st > 0; st >>= 1) {
        if (tid < st) red[tid] += red[tid + st];
        __syncthreads();
    }
    if (tid == 0) {
        float log_p_I = -logf((float)(DIMZ + 1)) * (float)B_HALF;
        *out_scalar = red[0] + log_p_I;
    }
}

// ============================================================================
extern "C" void kernel_launch(void* const* d_in, const int* in_sizes, int n_in,
                              void* d_out, int out_size) {
    const float* e1  = (const float*)d_in[0];
    const float* e2  = (const float*)d_in[1];
    const float* itv = (const float*)d_in[2];
    const float* W1  = (const float*)d_in[3];
    const float* b1  = (const float*)d_in[4];
    const float* W2  = (const float*)d_in[5];
    const float* b2  = (const float*)d_in[6];
    const float* W3  = (const float*)d_in[7];
    const float* b3  = (const float*)d_in[8];
    const float* Wd1 = (const float*)d_in[9];
    const float* bd1 = (const float*)d_in[10];
    const float* Wd2 = (const float*)d_in[11];
    const float* bd2 = (const float*)d_in[12];
    const float* Wd3 = (const float*)d_in[13];
    const float* bd3 = (const float*)d_in[14];
    float* out = (float*)d_out;

    void *p;
    cudaGetSymbolAddress(&p, g_h1h); __nv_bfloat16* h1h = (__nv_bfloat16*)p;
    cudaGetSymbolAddress(&p, g_h1l); __nv_bfloat16* h1l = (__nv_bfloat16*)p;
    cudaGetSymbolAddress(&p, g_h2h); __nv_bfloat16* h2h = (__nv_bfloat16*)p;
    cudaGetSymbolAddress(&p, g_h2l); __nv_bfloat16* h2l = (__nv_bfloat16*)p;
    cudaGetSymbolAddress(&p, g_w2h); __nv_bfloat16* w2h = (__nv_bfloat16*)p;
    cudaGetSymbolAddress(&p, g_w2l); __nv_bfloat16* w2l = (__nv_bfloat16*)p;
    cudaGetSymbolAddress(&p, g_w3h); __nv_bfloat16* w3h = (__nv_bfloat16*)p;
    cudaGetSymbolAddress(&p, g_w3l); __nv_bfloat16* w3l = (__nv_bfloat16*)p;

    cudaFuncSetAttribute(gemm_kernel<0>, cudaFuncAttributeMaxDynamicSharedMemorySize, SMEM_DYN);
    cudaFuncSetAttribute(gemm_kernel<1>, cudaFuncAttributeMaxDynamicSharedMemorySize, SMEM_DYN);

    // flow log-prob (independent)
    flow_kernel<<<dim3(64, 16), 128>>>(e1, e2, itv, W1, b1, W2, b2, W3, b3);
    reduce_final_kernel<<<1, 256>>>(out + ((size_t)out_size - 1));

    // weight prep: transpose + split
    tsplit_kernel<<<dim3(DECH / 32, DECH / 32), 256>>>(Wd2, w2h, w2l, DECH, DECH);
    tsplit_kernel<<<dim3(DIMX / 32, DECH / 32), 256>>>(Wd3, w3h, w3l, DECH, DIMX);

    // decoder
    dec1_kernel<<<B_TOT, 256>>>(e1, e2, Wd1, bd1, h1h, h1l);
    gemm_kernel<1><<<dim3(DECH / 128, B_TOT / 128), 256, SMEM_DYN>>>(
        h1h, h1l, w2h, w2l, bd2, nullptr, h2h, h2l, DECH);
    gemm_kernel<0><<<dim3(DIMX / 128, B_TOT / 128), 256, SMEM_DYN>>>(
        h2h, h2l, w3h, w3l, bd3, out, nullptr, nullptr, DIMX);
}

// round 5
// speedup vs baseline: 5.4670x; 1.9964x over previous
#include <cuda_runtime.h>
#include <cuda_fp16.h>
#include <math.h>
#include <stdint.h>

// ============================================================================
// ILCMDecoder on GB300 (baseline-PTX tensor path: mma.sync HMMA fp16 +
// ldmatrix + cp.async; tcgen05 is rejected by this harness's ptxas target).
//
// Decoder GEMMs (M=16384, K=1024, N=1024/3072) in pure fp16 (fp32 accum).
// Round-5 fix: swizzled smem addresses compose with k-offsets via XOR, not
// add (sw128(r*128 + o) == sw128(r*128) ^ o for o < 128). The Round-4 add
// carried into bit 7 and read past the stage -> NaN.
// ============================================================================

#define B_TOT   16384
#define B_HALF  8192
#define DIMZ    16
#define HDIM    64
#define DECH    1024
#define DIMX    3072
#define KTOT    1024
#define LOG2PI  1.8378770664093453f
#define MIN_STD 0.2f
#define CLAMP_V 1000000.0f

// ---------------- device scratch (allocation-free) ----------------
__device__ __half g_h1[(size_t)B_TOT * DECH];
__device__ __half g_h2[(size_t)B_TOT * DECH];
__device__ __half g_w2[(size_t)DECH * DECH];   // Wd2^T fp16 [N,K]
__device__ __half g_w3[(size_t)DIMX * DECH];   // Wd3^T fp16 [N,K]
__device__ float g_partial[1024];

// ---------------- PTX helpers (baseline family features only) --------------
__device__ __forceinline__ uint32_t smem_u32(const void* p) {
    uint32_t a;
    asm("{ .reg .u64 t; cvta.to.shared.u64 t, %1; cvt.u32.u64 %0, t; }"
        : "=r"(a) : "l"(p));
    return a;
}

#define CP_ASYNC16(smem, gptr) \
    asm volatile("cp.async.cg.shared.global [%0], [%1], 16;" \
        :: "r"((uint32_t)(smem)), "l"(gptr) : "memory")
#define CP_COMMIT() asm volatile("cp.async.commit_group;" ::: "memory")
#define CP_WAIT2()  asm volatile("cp.async.wait_group 2;" ::: "memory")
#define CP_WAIT1()  asm volatile("cp.async.wait_group 1;" ::: "memory")
#define CP_WAIT0()  asm volatile("cp.async.wait_group 0;" ::: "memory")

__device__ __forceinline__ void ldsm_x4(uint32_t* r, uint32_t addr) {
    asm volatile("ldmatrix.sync.aligned.m8n8.x4.shared.b16 {%0,%1,%2,%3}, [%4];"
        : "=r"(r[0]), "=r"(r[1]), "=r"(r[2]), "=r"(r[3]) : "r"(addr));
}

__device__ __forceinline__ void mma_f16(float* d, const uint32_t* a, const uint32_t* b) {
    asm volatile(
        "mma.sync.aligned.m16n8k16.row.col.f32.f16.f16.f32 "
        "{%0,%1,%2,%3}, {%4,%5,%6,%7}, {%8,%9}, {%0,%1,%2,%3};"
        : "+f"(d[0]), "+f"(d[1]), "+f"(d[2]), "+f"(d[3])
        : "r"(a[0]), "r"(a[1]), "r"(a[2]), "r"(a[3]), "r"(b[0]), "r"(b[1]));
}

__device__ __forceinline__ float clean_clamp(float x) {
    if (isnan(x)) x = 0.0f;
    return fminf(fmaxf(x, -CLAMP_V), CLAMP_V);
}

// ============================================================================
// Weight transpose to fp16:  W[K,N] fp32 -> T[N,K] fp16
// ============================================================================
__global__ void tsplit_kernel(const float* __restrict__ W,
                              __half* __restrict__ T, int K, int N) {
    __shared__ float tile[32][33];
    int nb = blockIdx.x * 32, kb = blockIdx.y * 32;
    int tx = threadIdx.x & 31, ty0 = threadIdx.x >> 5;
    for (int i = ty0; i < 32; i += 8)
        tile[i][tx] = W[(size_t)(kb + i) * N + nb + tx];
    __syncthreads();
    for (int i = ty0; i < 32; i += 8)
        T[(size_t)(nb + i) * K + kb + tx] = __float2half_rn(tile[tx][i]);
}

// ============================================================================
// Decoder layer 1: H1 = relu(E @ Wd1 + bd1) -> fp16
// ============================================================================
__global__ void dec1_kernel(const float* __restrict__ e1, const float* __restrict__ e2,
                            const float* __restrict__ Wd1, const float* __restrict__ bd1,
                            __half* __restrict__ H) {
    __shared__ float se[DIMZ];
    int b = blockIdx.x;
    const float* src = (b < B_HALF) ? (e1 + (size_t)b * DIMZ)
                                    : (e2 + (size_t)(b - B_HALF) * DIMZ);
    if (threadIdx.x < DIMZ) se[threadIdx.x] = src[threadIdx.x];
    __syncthreads();
    int tid = threadIdx.x;   // 256 threads
#pragma unroll
    for (int c = 0; c < 2; c++) {
        int col = c * 512 + tid * 2;
        float a0 = bd1[col], a1 = bd1[col + 1];
#pragma unroll
        for (int d = 0; d < DIMZ; d++) {
            float ed = se[d];
            a0 = fmaf(ed, Wd1[d * DECH + col],     a0);
            a1 = fmaf(ed, Wd1[d * DECH + col + 1], a1);
        }
        __half2 hv;
        hv.x = __float2half_rn(fmaxf(a0, 0.0f));
        hv.y = __float2half_rn(fmaxf(a1, 0.0f));
        *(__half2*)(H + (size_t)b * DECH + col) = hv;
    }
}

// ============================================================================
// fp16 HMMA GEMM:  C[M, Ntot] = epi(A @ B^T + bias)
//   A [M,1024] fp16 row-major; B [Ntot,1024] fp16 row-major (pre-transposed).
// CTA 128x128, 8 warps (warp tile 64x32), BK=64, 4-stage cp.async pipeline.
// EPI=0: fp32 out.  EPI=1: relu + fp16 out.
// ============================================================================
#define BK       64
#define NCHUNK  (KTOT / BK)       // 16
#define A_OFF   0
#define B_OFF   16384             // 128 rows x 128B
#define STG_BYTES 32768
#define NSTG    4
#define SMEM_DYN (NSTG * STG_BYTES + 1024)

__device__ __forceinline__ uint32_t sw128(uint32_t byte) {
    return byte ^ ((byte >> 3) & 0x70);
}

// 256 threads: load one 128(M)x64 + 128(N)x64 fp16 chunk into a stage.
__device__ __forceinline__ void load_stage(
    uint32_t stg,
    const __half* __restrict__ A, const __half* __restrict__ B,
    int m0, int n0, int kBase, int tid)
{
    const int c16 = tid & 7;        // 16B column within 128B row
    const int rg  = tid >> 3;       // 0..31
    const int kOff = kBase + c16 * 8;
#pragma unroll
    for (int j = 0; j < 4; j++) {
        int row = rg + j * 32;
        uint32_t sw = sw128((uint32_t)row * 128 + c16 * 16);
        CP_ASYNC16(stg + A_OFF + sw, A + (size_t)(m0 + row) * KTOT + kOff);
        CP_ASYNC16(stg + B_OFF + sw, B + (size_t)(n0 + row) * KTOT + kOff);
    }
}

template <int EPI>
__global__ __launch_bounds__(256, 1)
void gemm_kernel(const __half* __restrict__ A, const __half* __restrict__ B,
                 const float* __restrict__ bias,
                 float* __restrict__ Cf, __half* __restrict__ Ch,
                 int Ntot)
{
    extern __shared__ char dsm[];
    const uint32_t sbase = (smem_u32(dsm) + 1023) & ~1023u;

    const int tid  = threadIdx.x;
    const int warp = tid >> 5;
    const int lane = tid & 31;
    const int wm   = warp & 1;          // 2 M-slices of 64
    const int wn   = warp >> 1;         // 4 N-slices of 32
    const int m0   = blockIdx.y * 128;
    const int n0   = blockIdx.x * 128;

    const int lrow = lane & 7;
    const int quad = lane >> 3;
    // A ldmatrix fragment address components (tiles: m0k0, m8k0, m0k8, m8k8)
    const int aRow = wm * 64 + (quad & 1) * 8 + lrow;
    const int aKb  = (quad >> 1) * 16;   // byte offset within row, bits [4]
    // B ldmatrix fragment address components (tiles: n0k0, n0k8, n8k0, n8k8)
    const int bRow = wn * 32 + (quad >> 1) * 8 + lrow;
    const int bKb  = (quad & 1) * 16;

    // Precompute row-swizzled bases. For a k-offset o < 128 (row stride 128B):
    //   sw128(row*128 + o) == sw128(row*128) ^ o      (XOR-compose, NOT add)
    uint32_t aSw[4], bSw[2];
#pragma unroll
    for (int i = 0; i < 4; i++)
        aSw[i] = sw128((uint32_t)(aRow + i * 16) * 128);
#pragma unroll
    for (int g = 0; g < 2; g++)
        bSw[g] = sw128((uint32_t)(bRow + g * 16) * 128);

    float acc[4][4][4];
#pragma unroll
    for (int i = 0; i < 4; i++)
#pragma unroll
        for (int j = 0; j < 4; j++)
#pragma unroll
            for (int q = 0; q < 4; q++) acc[i][j][q] = 0.0f;

    // prologue: chunks 0..2 into stages 0..2
    load_stage(sbase,                 A, B, m0, n0, 0,      tid); CP_COMMIT();
    load_stage(sbase + STG_BYTES,     A, B, m0, n0, BK,     tid); CP_COMMIT();
    load_stage(sbase + 2 * STG_BYTES, A, B, m0, n0, 2 * BK, tid); CP_COMMIT();

#pragma unroll 1
    for (int c = 0; c < NCHUNK; c++) {
        if (c < NCHUNK - 2)       { CP_WAIT2(); }
        else if (c == NCHUNK - 2) { CP_WAIT1(); }
        else                      { CP_WAIT0(); }
        __syncthreads();
        if (c + 3 < NCHUNK) {
            load_stage(sbase + ((c + 3) & 3) * STG_BYTES,
                       A, B, m0, n0, (c + 3) * BK, tid);
            CP_COMMIT();
        }
        const uint32_t stg = sbase + (c & 3) * STG_BYTES;

#pragma unroll
        for (int kk = 0; kk < 4; kk++) {
            uint32_t a_r[4][4], b_r[2][4];
            const uint32_t ko = (uint32_t)(kk * 32);
#pragma unroll
            for (int i = 0; i < 4; i++)
                ldsm_x4(a_r[i], stg + A_OFF + (aSw[i] ^ (ko + aKb)));
#pragma unroll
            for (int g = 0; g < 2; g++)
                ldsm_x4(b_r[g], stg + B_OFF + (bSw[g] ^ (ko + bKb)));
#pragma unroll
            for (int i = 0; i < 4; i++)
#pragma unroll
                for (int j = 0; j < 4; j++)
                    mma_f16(acc[i][j], a_r[i], &b_r[j >> 1][(j & 1) * 2]);
        }
    }

    // ---------------- epilogue (register direct) ----------------
    const int er = lane >> 2;            // 0..7 (row within atom)
    const int ec = (lane & 3) * 2;       // 0,2,4,6 (col pair)
    float bv[4][2];
#pragma unroll
    for (int j = 0; j < 4; j++) {
        int n = n0 + wn * 32 + j * 8 + ec;
        bv[j][0] = bias[n]; bv[j][1] = bias[n + 1];
    }
#pragma unroll
    for (int i = 0; i < 4; i++) {
        int mrow = m0 + wm * 64 + i * 16 + er;
#pragma unroll
        for (int j = 0; j < 4; j++) {
            int n = n0 + wn * 32 + j * 8 + ec;
            float v0 = acc[i][j][0] + bv[j][0], v1 = acc[i][j][1] + bv[j][1];
            float v2 = acc[i][j][2] + bv[j][0], v3 = acc[i][j][3] + bv[j][1];
            size_t g0 = (size_t)mrow * Ntot + n;
            size_t g1 = (size_t)(mrow + 8) * Ntot + n;
            if (EPI == 0) {
                *(float2*)(Cf + g0) = make_float2(v0, v1);
                *(float2*)(Cf + g1) = make_float2(v2, v3);
            } else {
                __half2 p;
                p.x = __float2half_rn(fmaxf(v0, 0.0f));
                p.y = __float2half_rn(fmaxf(v1, 0.0f));
                *(__half2*)(Ch + g0) = p;
                p.x = __float2half_rn(fmaxf(v2, 0.0f));
                p.y = __float2half_rn(fmaxf(v3, 0.0f));
                *(__half2*)(Ch + g1) = p;
            }
        }
    }
}

// ============================================================================
// Flow: per-dim MLP 16->64->64->2 + masked logprob + e1 logprob
// ============================================================================
__global__ __launch_bounds__(128)
void flow_kernel(const float* __restrict__ e1, const float* __restrict__ e2,
                 const float* __restrict__ interv,
                 const float* __restrict__ W1, const float* __restrict__ b1,
                 const float* __restrict__ W2, const float* __restrict__ b2,
                 const float* __restrict__ W3, const float* __restrict__ b3) {
    __shared__ float sW1[DIMZ * HDIM];
    __shared__ float sW2[HDIM * HDIM];
    __shared__ float sW3[HDIM * 2];
    __shared__ float sb1[HDIM], sb2[HDIM], sb3v[2];
    __shared__ float red[128];

    const int i = blockIdx.y;
    const int tid = threadIdx.x;

    for (int t = tid; t < DIMZ * HDIM; t += 128) sW1[t] = W1[i * DIMZ * HDIM + t];
    for (int t = tid; t < HDIM * HDIM; t += 128) sW2[t] = W2[i * HDIM * HDIM + t];
    if (tid < HDIM * 2) sW3[tid] = W3[i * HDIM * 2 + tid];
    if (tid < HDIM) { sb1[tid] = b1[i * HDIM + tid]; sb2[tid] = b2[i * HDIM + tid]; }
    if (tid < 2) sb3v[tid] = b3[i * 2 + tid];
    __syncthreads();

    const int b = blockIdx.x * 128 + tid;

    float ctx[DIMZ];
    float e1_i = 0.0f;
#pragma unroll
    for (int d = 0; d < DIMZ; d++) {
        float v = e1[(size_t)b * DIMZ + d];
        if (d == i) { e1_i = v; v = 0.0f; }
        ctx[d] = v;
    }

    float h1[HDIM];
#pragma unroll
    for (int j = 0; j < HDIM; j++) {
        float a = sb1[j];
#pragma unroll
        for (int d = 0; d < DIMZ; d++) a = fmaf(ctx[d], sW1[d * HDIM + j], a);
        h1[j] = fmaxf(a, 0.0f);
    }

    float p0 = sb3v[0], p1 = sb3v[1];
    for (int k = 0; k < HDIM; k++) {
        float t = sb2[k];
#pragma unroll
        for (int j = 0; j < HDIM; j++) t = fmaf(h1[j], sW2[j * HDIM + k], t);
        t = fmaxf(t, 0.0f);
        p0 = fmaf(t, sW3[k * 2 + 0], p0);
        p1 = fmaf(t, sW3[k * 2 + 1], p1);
    }

    float sp = fmaxf(p1, 0.0f) + log1pf(expf(-fabsf(p1)));
    float scale = sp + MIN_STD;

    float z = (e2[(size_t)b * DIMZ + i] - p0) / scale;
    z = clean_clamp(z);
    float mask = interv[(size_t)b * (DIMZ + 1) + 1 + i];
    float lp2 = (-0.5f * z * z - 0.5f * LOG2PI - logf(scale)) * mask;
    float lp1 = clean_clamp(-0.5f * e1_i * e1_i - 0.5f * LOG2PI);

    red[tid] = lp1 + lp2;
    __syncthreads();
#pragma unroll
    for (int s = 64; s > 0; s >>= 1) {
        if (tid < s) red[tid] += red[tid + s];
        __syncthreads();
    }
    if (tid == 0) g_partial[blockIdx.y * gridDim.x + blockIdx.x] = red[0];
}

__global__ void reduce_final_kernel(float* __restrict__ out_scalar) {
    __shared__ float red[256];
    int tid = threadIdx.x;
    float s = 0.0f;
    for (int t = tid; t < 1024; t += 256) s += g_partial[t];
    red[tid] = s;
    __syncthreads();
#pragma unroll
    for (int st = 128; st > 0; st >>= 1) {
        if (tid < st) red[tid] += red[tid + st];
        __syncthreads();
    }
    if (tid == 0) {
        float log_p_I = -logf((float)(DIMZ + 1)) * (float)B_HALF;
        *out_scalar = red[0] + log_p_I;
    }
}

// ============================================================================
extern "C" void kernel_launch(void* const* d_in, const int* in_sizes, int n_in,
                              void* d_out, int out_size) {
    const float* e1  = (const float*)d_in[0];
    const float* e2  = (const float*)d_in[1];
    const float* itv = (const float*)d_in[2];
    const float* W1  = (const float*)d_in[3];
    const float* b1  = (const float*)d_in[4];
    const float* W2  = (const float*)d_in[5];
    const float* b2  = (const float*)d_in[6];
    const float* W3  = (const float*)d_in[7];
    const float* b3  = (const float*)d_in[8];
    const float* Wd1 = (const float*)d_in[9];
    const float* bd1 = (const float*)d_in[10];
    const float* Wd2 = (const float*)d_in[11];
    const float* bd2 = (const float*)d_in[12];
    const float* Wd3 = (const float*)d_in[13];
    const float* bd3 = (const float*)d_in[14];
    float* out = (float*)d_out;

    void *p;
    cudaGetSymbolAddress(&p, g_h1); __half* h1 = (__half*)p;
    cudaGetSymbolAddress(&p, g_h2); __half* h2 = (__half*)p;
    cudaGetSymbolAddress(&p, g_w2); __half* w2 = (__half*)p;
    cudaGetSymbolAddress(&p, g_w3); __half* w3 = (__half*)p;

    cudaFuncSetAttribute(gemm_kernel<0>, cudaFuncAttributeMaxDynamicSharedMemorySize, SMEM_DYN);
    cudaFuncSetAttribute(gemm_kernel<1>, cudaFuncAttributeMaxDynamicSharedMemorySize, SMEM_DYN);

    // flow log-prob (independent)
    flow_kernel<<<dim3(64, 16), 128>>>(e1, e2, itv, W1, b1, W2, b2, W3, b3);
    reduce_final_kernel<<<1, 256>>>(out + ((size_t)out_size - 1));

    // weight prep: transpose to fp16
    tsplit_kernel<<<dim3(DECH / 32, DECH / 32), 256>>>(Wd2, w2, DECH, DECH);
    tsplit_kernel<<<dim3(DIMX / 32, DECH / 32), 256>>>(Wd3, w3, DECH, DIMX);

    // decoder
    dec1_kernel<<<B_TOT, 256>>>(e1, e2, Wd1, bd1, h1);
    gemm_kernel<1><<<dim3(DECH / 128, B_TOT / 128), 256, SMEM_DYN>>>(
        h1, w2, bd2, nullptr, h2, DECH);
    gemm_kernel<0><<<dim3(DIMX / 128, B_TOT / 128), 256, SMEM_DYN>>>(
        h2, w3, bd3, out, nullptr, DIMX);
}

// round 6
// speedup vs baseline: 5.8462x; 1.0694x over previous
#include <cuda_runtime.h>
#include <cuda_fp16.h>
#include <math.h>
#include <stdint.h>

// ============================================================================
// ILCMDecoder on GB300 (baseline-PTX tensor path: mma.sync HMMA fp16 +
// ldmatrix + cp.async; tcgen05 is rejected by this harness's ptxas target).
//
// Decoder GEMMs (M=16384, K=1024, N=1024/3072) in pure fp16 (fp32 accum).
// Round 6: CTA tile 128x256 (warp 64x64), 4-stage cp.async pipeline.
// ============================================================================

#define B_TOT   16384
#define B_HALF  8192
#define DIMZ    16
#define HDIM    64
#define DECH    1024
#define DIMX    3072
#define KTOT    1024
#define LOG2PI  1.8378770664093453f
#define MIN_STD 0.2f
#define CLAMP_V 1000000.0f

// ---------------- device scratch (allocation-free) ----------------
__device__ __half g_h1[(size_t)B_TOT * DECH];
__device__ __half g_h2[(size_t)B_TOT * DECH];
__device__ __half g_w2[(size_t)DECH * DECH];   // Wd2^T fp16 [N,K]
__device__ __half g_w3[(size_t)DIMX * DECH];   // Wd3^T fp16 [N,K]
__device__ float g_partial[1024];

// ---------------- PTX helpers (baseline family features only) --------------
__device__ __forceinline__ uint32_t smem_u32(const void* p) {
    uint32_t a;
    asm("{ .reg .u64 t; cvta.to.shared.u64 t, %1; cvt.u32.u64 %0, t; }"
        : "=r"(a) : "l"(p));
    return a;
}

#define CP_ASYNC16(smem, gptr) \
    asm volatile("cp.async.cg.shared.global [%0], [%1], 16;" \
        :: "r"((uint32_t)(smem)), "l"(gptr) : "memory")
#define CP_COMMIT() asm volatile("cp.async.commit_group;" ::: "memory")
#define CP_WAIT2()  asm volatile("cp.async.wait_group 2;" ::: "memory")
#define CP_WAIT1()  asm volatile("cp.async.wait_group 1;" ::: "memory")
#define CP_WAIT0()  asm volatile("cp.async.wait_group 0;" ::: "memory")

__device__ __forceinline__ void ldsm_x4(uint32_t* r, uint32_t addr) {
    asm volatile("ldmatrix.sync.aligned.m8n8.x4.shared.b16 {%0,%1,%2,%3}, [%4];"
        : "=r"(r[0]), "=r"(r[1]), "=r"(r[2]), "=r"(r[3]) : "r"(addr));
}

__device__ __forceinline__ void mma_f16(float* d, const uint32_t* a, const uint32_t* b) {
    asm volatile(
        "mma.sync.aligned.m16n8k16.row.col.f32.f16.f16.f32 "
        "{%0,%1,%2,%3}, {%4,%5,%6,%7}, {%8,%9}, {%0,%1,%2,%3};"
        : "+f"(d[0]), "+f"(d[1]), "+f"(d[2]), "+f"(d[3])
        : "r"(a[0]), "r"(a[1]), "r"(a[2]), "r"(a[3]), "r"(b[0]), "r"(b[1]));
}

__device__ __forceinline__ float clean_clamp(float x) {
    if (isnan(x)) x = 0.0f;
    return fminf(fmaxf(x, -CLAMP_V), CLAMP_V);
}

// ============================================================================
// Weight transpose to fp16:  W[K,N] fp32 -> T[N,K] fp16
// ============================================================================
__global__ void tsplit_kernel(const float* __restrict__ W,
                              __half* __restrict__ T, int K, int N) {
    __shared__ float tile[32][33];
    int nb = blockIdx.x * 32, kb = blockIdx.y * 32;
    int tx = threadIdx.x & 31, ty0 = threadIdx.x >> 5;
    for (int i = ty0; i < 32; i += 8)
        tile[i][tx] = W[(size_t)(kb + i) * N + nb + tx];
    __syncthreads();
    for (int i = ty0; i < 32; i += 8)
        T[(size_t)(nb + i) * K + kb + tx] = __float2half_rn(tile[tx][i]);
}

// ============================================================================
// Decoder layer 1: H1 = relu(E @ Wd1 + bd1) -> fp16
// ============================================================================
__global__ void dec1_kernel(const float* __restrict__ e1, const float* __restrict__ e2,
                            const float* __restrict__ Wd1, const float* __restrict__ bd1,
                            __half* __restrict__ H) {
    __shared__ float se[DIMZ];
    int b = blockIdx.x;
    const float* src = (b < B_HALF) ? (e1 + (size_t)b * DIMZ)
                                    : (e2 + (size_t)(b - B_HALF) * DIMZ);
    if (threadIdx.x < DIMZ) se[threadIdx.x] = src[threadIdx.x];
    __syncthreads();
    int tid = threadIdx.x;   // 256 threads
#pragma unroll
    for (int c = 0; c < 2; c++) {
        int col = c * 512 + tid * 2;
        float a0 = bd1[col], a1 = bd1[col + 1];
#pragma unroll
        for (int d = 0; d < DIMZ; d++) {
            float ed = se[d];
            a0 = fmaf(ed, Wd1[d * DECH + col],     a0);
            a1 = fmaf(ed, Wd1[d * DECH + col + 1], a1);
        }
        __half2 hv;
        hv.x = __float2half_rn(fmaxf(a0, 0.0f));
        hv.y = __float2half_rn(fmaxf(a1, 0.0f));
        *(__half2*)(H + (size_t)b * DECH + col) = hv;
    }
}

// ============================================================================
// fp16 HMMA GEMM:  C[M, Ntot] = epi(A @ B^T + bias)
//   A [M,1024] fp16 row-major; B [Ntot,1024] fp16 row-major (pre-transposed).
// CTA 128x256, 8 warps (warp tile 64x64, 2x4 grid), BK=64, 4-stage pipeline.
// EPI=0: fp32 out.  EPI=1: relu + fp16 out.
// ============================================================================
#define BK       64
#define NCHUNK  (KTOT / BK)       // 16
#define NT       256
#define A_OFF   0
#define B_OFF   16384             // A: 128 rows x 128B
#define STG_BYTES 49152           // A 16K + B 32K
#define NSTG    4
#define SMEM_DYN (NSTG * STG_BYTES + 1024)

__device__ __forceinline__ uint32_t sw128(uint32_t byte) {
    return byte ^ ((byte >> 3) & 0x70);
}

// 256 threads: load one 128(M)x64 + 256(N)x64 fp16 chunk into a stage.
__device__ __forceinline__ void load_stage(
    uint32_t stg,
    const __half* __restrict__ A, const __half* __restrict__ B,
    int m0, int n0, int kBase, int tid)
{
    const int c16 = tid & 7;        // 16B column within 128B row
    const int rg  = tid >> 3;       // 0..31
    const int kOff = kBase + c16 * 8;
#pragma unroll
    for (int j = 0; j < 4; j++) {
        int row = rg + j * 32;
        uint32_t sw = sw128((uint32_t)row * 128 + c16 * 16);
        CP_ASYNC16(stg + A_OFF + sw, A + (size_t)(m0 + row) * KTOT + kOff);
    }
#pragma unroll
    for (int j = 0; j < 8; j++) {
        int row = rg + j * 32;
        uint32_t sw = sw128((uint32_t)row * 128 + c16 * 16);
        CP_ASYNC16(stg + B_OFF + sw, B + (size_t)(n0 + row) * KTOT + kOff);
    }
}

template <int EPI>
__global__ __launch_bounds__(256, 1)
void gemm_kernel(const __half* __restrict__ A, const __half* __restrict__ B,
                 const float* __restrict__ bias,
                 float* __restrict__ Cf, __half* __restrict__ Ch,
                 int Ntot)
{
    extern __shared__ char dsm[];
    const uint32_t sbase = (smem_u32(dsm) + 1023) & ~1023u;

    const int tid  = threadIdx.x;
    const int warp = tid >> 5;
    const int lane = tid & 31;
    const int wm   = warp & 1;          // 2 M-slices of 64
    const int wn   = warp >> 1;         // 4 N-slices of 64
    const int m0   = blockIdx.y * 128;
    const int n0   = blockIdx.x * NT;

    const int lrow = lane & 7;
    const int quad = lane >> 3;
    // A ldmatrix fragment address components (tiles: m0k0, m8k0, m0k8, m8k8)
    const int aRow = wm * 64 + (quad & 1) * 8 + lrow;
    const int aKb  = (quad >> 1) * 16;
    // B ldmatrix fragment address components (tiles: n0k0, n0k8, n8k0, n8k8)
    const int bRow = wn * 64 + (quad >> 1) * 8 + lrow;
    const int bKb  = (quad & 1) * 16;

    // Row-swizzled bases; k-offset o < 128 composes via XOR:
    //   sw128(row*128 + o) == sw128(row*128) ^ o
    uint32_t aSw[4], bSw[4];
#pragma unroll
    for (int i = 0; i < 4; i++)
        aSw[i] = sw128((uint32_t)(aRow + i * 16) * 128);
#pragma unroll
    for (int g = 0; g < 4; g++)
        bSw[g] = sw128((uint32_t)(bRow + g * 16) * 128);

    float acc[4][8][4];
#pragma unroll
    for (int i = 0; i < 4; i++)
#pragma unroll
        for (int j = 0; j < 8; j++)
#pragma unroll
            for (int q = 0; q < 4; q++) acc[i][j][q] = 0.0f;

    // prologue: chunks 0..2 into stages 0..2
    load_stage(sbase,                 A, B, m0, n0, 0,      tid); CP_COMMIT();
    load_stage(sbase + STG_BYTES,     A, B, m0, n0, BK,     tid); CP_COMMIT();
    load_stage(sbase + 2 * STG_BYTES, A, B, m0, n0, 2 * BK, tid); CP_COMMIT();

#pragma unroll 1
    for (int c = 0; c < NCHUNK; c++) {
        if (c < NCHUNK - 2)       { CP_WAIT2(); }
        else if (c == NCHUNK - 2) { CP_WAIT1(); }
        else                      { CP_WAIT0(); }
        __syncthreads();
        if (c + 3 < NCHUNK) {
            load_stage(sbase + ((c + 3) & 3) * STG_BYTES,
                       A, B, m0, n0, (c + 3) * BK, tid);
            CP_COMMIT();
        }
        const uint32_t stg = sbase + (c & 3) * STG_BYTES;

#pragma unroll
        for (int kk = 0; kk < 4; kk++) {
            uint32_t a_r[4][4], b_r[4][4];
            const uint32_t ko = (uint32_t)(kk * 32);
#pragma unroll
            for (int i = 0; i < 4; i++)
                ldsm_x4(a_r[i], stg + A_OFF + (aSw[i] ^ (ko + aKb)));
#pragma unroll
            for (int g = 0; g < 4; g++)
                ldsm_x4(b_r[g], stg + B_OFF + (bSw[g] ^ (ko + bKb)));
#pragma unroll
            for (int i = 0; i < 4; i++)
#pragma unroll
                for (int j = 0; j < 8; j++)
                    mma_f16(acc[i][j], a_r[i], &b_r[j >> 1][(j & 1) * 2]);
        }
    }

    // ---------------- epilogue (register direct) ----------------
    const int er = lane >> 2;            // 0..7 (row within atom)
    const int ec = (lane & 3) * 2;       // 0,2,4,6 (col pair)
    float bv[8][2];
#pragma unroll
    for (int j = 0; j < 8; j++) {
        int n = n0 + wn * 64 + j * 8 + ec;
        bv[j][0] = bias[n]; bv[j][1] = bias[n + 1];
    }
#pragma unroll
    for (int i = 0; i < 4; i++) {
        int mrow = m0 + wm * 64 + i * 16 + er;
#pragma unroll
        for (int j = 0; j < 8; j++) {
            int n = n0 + wn * 64 + j * 8 + ec;
            float v0 = acc[i][j][0] + bv[j][0], v1 = acc[i][j][1] + bv[j][1];
            float v2 = acc[i][j][2] + bv[j][0], v3 = acc[i][j][3] + bv[j][1];
            size_t g0 = (size_t)mrow * Ntot + n;
            size_t g1 = (size_t)(mrow + 8) * Ntot + n;
            if (EPI == 0) {
                *(float2*)(Cf + g0) = make_float2(v0, v1);
                *(float2*)(Cf + g1) = make_float2(v2, v3);
            } else {
                __half2 p;
                p.x = __float2half_rn(fmaxf(v0, 0.0f));
                p.y = __float2half_rn(fmaxf(v1, 0.0f));
                *(__half2*)(Ch + g0) = p;
                p.x = __float2half_rn(fmaxf(v2, 0.0f));
                p.y = __float2half_rn(fmaxf(v3, 0.0f));
                *(__half2*)(Ch + g1) = p;
            }
        }
    }
}

// ============================================================================
// Flow: per-dim MLP 16->64->64->2 + masked logprob + e1 logprob
// ============================================================================
__global__ __launch_bounds__(128)
void flow_kernel(const float* __restrict__ e1, const float* __restrict__ e2,
                 const float* __restrict__ interv,
                 const float* __restrict__ W1, const float* __restrict__ b1,
                 const float* __restrict__ W2, const float* __restrict__ b2,
                 const float* __restrict__ W3, const float* __restrict__ b3) {
    __shared__ float sW1[DIMZ * HDIM];
    __shared__ float sW2[HDIM * HDIM];
    __shared__ float sW3[HDIM * 2];
    __shared__ float sb1[HDIM], sb2[HDIM], sb3v[2];
    __shared__ float red[128];

    const int i = blockIdx.y;
    const int tid = threadIdx.x;

    for (int t = tid; t < DIMZ * HDIM; t += 128) sW1[t] = W1[i * DIMZ * HDIM + t];
    for (int t = tid; t < HDIM * HDIM; t += 128) sW2[t] = W2[i * HDIM * HDIM + t];
    if (tid < HDIM * 2) sW3[tid] = W3[i * HDIM * 2 + tid];
    if (tid < HDIM) { sb1[tid] = b1[i * HDIM + tid]; sb2[tid] = b2[i * HDIM + tid]; }
    if (tid < 2) sb3v[tid] = b3[i * 2 + tid];
    __syncthreads();

    const int b = blockIdx.x * 128 + tid;

    float ctx[DIMZ];
    float e1_i = 0.0f;
#pragma unroll
    for (int d = 0; d < DIMZ; d++) {
        float v = e1[(size_t)b * DIMZ + d];
        if (d == i) { e1_i = v; v = 0.0f; }
        ctx[d] = v;
    }

    float h1[HDIM];
#pragma unroll
    for (int j = 0; j < HDIM; j++) {
        float a = sb1[j];
#pragma unroll
        for (int d = 0; d < DIMZ; d++) a = fmaf(ctx[d], sW1[d * HDIM + j], a);
        h1[j] = fmaxf(a, 0.0f);
    }

    float p0 = sb3v[0], p1 = sb3v[1];
    for (int k = 0; k < HDIM; k++) {
        float t = sb2[k];
#pragma unroll
        for (int j = 0; j < HDIM; j++) t = fmaf(h1[j], sW2[j * HDIM + k], t);
        t = fmaxf(t, 0.0f);
        p0 = fmaf(t, sW3[k * 2 + 0], p0);
        p1 = fmaf(t, sW3[k * 2 + 1], p1);
    }

    float sp = fmaxf(p1, 0.0f) + log1pf(expf(-fabsf(p1)));
    float scale = sp + MIN_STD;

    float z = (e2[(size_t)b * DIMZ + i] - p0) / scale;
    z = clean_clamp(z);
    float mask = interv[(size_t)b * (DIMZ + 1) + 1 + i];
    float lp2 = (-0.5f * z * z - 0.5f * LOG2PI - logf(scale)) * mask;
    float lp1 = clean_clamp(-0.5f * e1_i * e1_i - 0.5f * LOG2PI);

    red[tid] = lp1 + lp2;
    __syncthreads();
#pragma unroll
    for (int s = 64; s > 0; s >>= 1) {
        if (tid < s) red[tid] += red[tid + s];
        __syncthreads();
    }
    if (tid == 0) g_partial[blockIdx.y * gridDim.x + blockIdx.x] = red[0];
}

__global__ void reduce_final_kernel(float* __restrict__ out_scalar) {
    __shared__ float red[256];
    int tid = threadIdx.x;
    float s = 0.0f;
    for (int t = tid; t < 1024; t += 256) s += g_partial[t];
    red[tid] = s;
    __syncthreads();
#pragma unroll
    for (int st = 128; st > 0; st >>= 1) {
        if (tid < st) red[tid] += red[tid + st];
        __syncthreads();
    }
    if (tid == 0) {
        float log_p_I = -logf((float)(DIMZ + 1)) * (float)B_HALF;
        *out_scalar = red[0] + log_p_I;
    }
}

// ============================================================================
extern "C" void kernel_launch(void* const* d_in, const int* in_sizes, int n_in,
                              void* d_out, int out_size) {
    const float* e1  = (const float*)d_in[0];
    const float* e2  = (const float*)d_in[1];
    const float* itv = (const float*)d_in[2];
    const float* W1  = (const float*)d_in[3];
    const float* b1  = (const float*)d_in[4];
    const float* W2  = (const float*)d_in[5];
    const float* b2  = (const float*)d_in[6];
    const float* W3  = (const float*)d_in[7];
    const float* b3  = (const float*)d_in[8];
    const float* Wd1 = (const float*)d_in[9];
    const float* bd1 = (const float*)d_in[10];
    const float* Wd2 = (const float*)d_in[11];
    const float* bd2 = (const float*)d_in[12];
    const float* Wd3 = (const float*)d_in[13];
    const float* bd3 = (const float*)d_in[14];
    float* out = (float*)d_out;

    void *p;
    cudaGetSymbolAddress(&p, g_h1); __half* h1 = (__half*)p;
    cudaGetSymbolAddress(&p, g_h2); __half* h2 = (__half*)p;
    cudaGetSymbolAddress(&p, g_w2); __half* w2 = (__half*)p;
    cudaGetSymbolAddress(&p, g_w3); __half* w3 = (__half*)p;

    cudaFuncSetAttribute(gemm_kernel<0>, cudaFuncAttributeMaxDynamicSharedMemorySize, SMEM_DYN);
    cudaFuncSetAttribute(gemm_kernel<1>, cudaFuncAttributeMaxDynamicSharedMemorySize, SMEM_DYN);

    // flow log-prob (independent)
    flow_kernel<<<dim3(64, 16), 128>>>(e1, e2, itv, W1, b1, W2, b2, W3, b3);
    reduce_final_kernel<<<1, 256>>>(out + ((size_t)out_size - 1));

    // weight prep: transpose to fp16
    tsplit_kernel<<<dim3(DECH / 32, DECH / 32), 256>>>(Wd2, w2, DECH, DECH);
    tsplit_kernel<<<dim3(DIMX / 32, DECH / 32), 256>>>(Wd3, w3, DECH, DIMX);

    // decoder
    dec1_kernel<<<B_TOT, 256>>>(e1, e2, Wd1, bd1, h1);
    gemm_kernel<1><<<dim3(DECH / NT, B_TOT / 128), 256, SMEM_DYN>>>(
        h1, w2, bd2, nullptr, h2, DECH);
    gemm_kernel<0><<<dim3(DIMX / NT, B_TOT / 128), 256, SMEM_DYN>>>(
        h2, w3, bd3, out, nullptr, DIMX);
}

// round 7
// speedup vs baseline: 6.2791x; 1.0740x over previous
#include <cuda_runtime.h>
#include <cuda_fp16.h>
#include <math.h>
#include <stdint.h>

// ============================================================================
// ILCMDecoder on GB300 (baseline-PTX tensor path: mma.sync HMMA fp16 +
// ldmatrix + cp.async; tcgen05 rejected by this harness's ptxas target).
//
// Round 7:
//  - gemm2+gemm3 fused into ONE kernel with per-m-block readiness counters
//    (kills gemm2's wave-tail bubble + inter-kernel gap).
//  - flow log-prob in half2 SIMD (HFMA2) — 2x fma-pipe throughput; errors
//    only enter the log_p scalar sum (rel ~1e-5).
// ============================================================================

#define B_TOT   16384
#define B_HALF  8192
#define DIMZ    16
#define HDIM    64
#define DECH    1024
#define DIMX    3072
#define KTOT    1024
#define LOG2PI  1.8378770664093453f
#define MIN_STD 0.2f
#define CLAMP_V 1000000.0f

#define G2_CTAS 512            // gemm2: 128 m-tiles x 4 n-tiles
#define G3_CTAS 1536           // gemm3: 128 m-tiles x 12 n-tiles

// ---------------- device scratch (allocation-free) ----------------
__device__ __half g_h1[(size_t)B_TOT * DECH];
__device__ __half g_h2[(size_t)B_TOT * DECH];
__device__ __half g_w2[(size_t)DECH * DECH];   // Wd2^T fp16 [N,K]
__device__ __half g_w3[(size_t)DIMX * DECH];   // Wd3^T fp16 [N,K]
__device__ float g_partial[512];
__device__ int   g_ready[128];                 // per-m-block h2 readiness (0..4)

// ---------------- PTX helpers (baseline family features only) --------------
__device__ __forceinline__ uint32_t smem_u32(const void* p) {
    uint32_t a;
    asm("{ .reg .u64 t; cvta.to.shared.u64 t, %1; cvt.u32.u64 %0, t; }"
        : "=r"(a) : "l"(p));
    return a;
}

#define CP_ASYNC16(smem, gptr) \
    asm volatile("cp.async.cg.shared.global [%0], [%1], 16;" \
        :: "r"((uint32_t)(smem)), "l"(gptr) : "memory")
#define CP_COMMIT() asm volatile("cp.async.commit_group;" ::: "memory")
#define CP_WAIT2()  asm volatile("cp.async.wait_group 2;" ::: "memory")
#define CP_WAIT1()  asm volatile("cp.async.wait_group 1;" ::: "memory")
#define CP_WAIT0()  asm volatile("cp.async.wait_group 0;" ::: "memory")

__device__ __forceinline__ void ldsm_x4(uint32_t* r, uint32_t addr) {
    asm volatile("ldmatrix.sync.aligned.m8n8.x4.shared.b16 {%0,%1,%2,%3}, [%4];"
        : "=r"(r[0]), "=r"(r[1]), "=r"(r[2]), "=r"(r[3]) : "r"(addr));
}

__device__ __forceinline__ void mma_f16(float* d, const uint32_t* a, const uint32_t* b) {
    asm volatile(
        "mma.sync.aligned.m16n8k16.row.col.f32.f16.f16.f32 "
        "{%0,%1,%2,%3}, {%4,%5,%6,%7}, {%8,%9}, {%0,%1,%2,%3};"
        : "+f"(d[0]), "+f"(d[1]), "+f"(d[2]), "+f"(d[3])
        : "r"(a[0]), "r"(a[1]), "r"(a[2]), "r"(a[3]), "r"(b[0]), "r"(b[1]));
}

__device__ __forceinline__ int ld_acq(const int* p) {
    int v;
    asm volatile("ld.acquire.gpu.s32 %0, [%1];" : "=r"(v) : "l"(p) : "memory");
    return v;
}
__device__ __forceinline__ void red_release_add1(int* p) {
    asm volatile("red.release.gpu.global.add.s32 [%0], %1;" :: "l"(p), "r"(1) : "memory");
}

__device__ __forceinline__ float clean_clamp(float x) {
    if (isnan(x)) x = 0.0f;
    return fminf(fmaxf(x, -CLAMP_V), CLAMP_V);
}

// ============================================================================
// Weight transpose to fp16:  W[K,N] fp32 -> T[N,K] fp16
// ============================================================================
__global__ void tsplit_kernel(const float* __restrict__ W,
                              __half* __restrict__ T, int K, int N) {
    __shared__ float tile[32][33];
    int nb = blockIdx.x * 32, kb = blockIdx.y * 32;
    int tx = threadIdx.x & 31, ty0 = threadIdx.x >> 5;
    for (int i = ty0; i < 32; i += 8)
        tile[i][tx] = W[(size_t)(kb + i) * N + nb + tx];
    __syncthreads();
    for (int i = ty0; i < 32; i += 8)
        T[(size_t)(nb + i) * K + kb + tx] = __float2half_rn(tile[tx][i]);
}

// ============================================================================
// Decoder layer 1: H1 = relu(E @ Wd1 + bd1) -> fp16 (fp32 compute).
// Also zeroes the g_ready counters for the fused GEMM (replay-safe).
// ============================================================================
__global__ void dec1_kernel(const float* __restrict__ e1, const float* __restrict__ e2,
                            const float* __restrict__ Wd1, const float* __restrict__ bd1,
                            __half* __restrict__ H) {
    __shared__ float se[DIMZ];
    int b = blockIdx.x;
    if (b < 128 && threadIdx.x == 32) g_ready[b] = 0;
    const float* src = (b < B_HALF) ? (e1 + (size_t)b * DIMZ)
                                    : (e2 + (size_t)(b - B_HALF) * DIMZ);
    if (threadIdx.x < DIMZ) se[threadIdx.x] = src[threadIdx.x];
    __syncthreads();
    int tid = threadIdx.x;   // 256 threads
#pragma unroll
    for (int c = 0; c < 2; c++) {
        int col = c * 512 + tid * 2;
        float a0 = bd1[col], a1 = bd1[col + 1];
#pragma unroll
        for (int d = 0; d < DIMZ; d++) {
            float ed = se[d];
            a0 = fmaf(ed, Wd1[d * DECH + col],     a0);
            a1 = fmaf(ed, Wd1[d * DECH + col + 1], a1);
        }
        __half2 hv;
        hv.x = __float2half_rn(fmaxf(a0, 0.0f));
        hv.y = __float2half_rn(fmaxf(a1, 0.0f));
        *(__half2*)(H + (size_t)b * DECH + col) = hv;
    }
}

// ============================================================================
// fp16 HMMA GEMM core:  C[M, Ntot] = epi(A @ B^T + bias)
// CTA 128x256, 8 warps (warp tile 64x64), BK=64, 4-stage cp.async pipeline.
// EPI=0: fp32 out.  EPI=1: relu + fp16 out.
// ============================================================================
#define BK       64
#define NCHUNK  (KTOT / BK)       // 16
#define NT       256
#define A_OFF   0
#define B_OFF   16384             // A: 128 rows x 128B
#define STG_BYTES 49152           // A 16K + B 32K
#define NSTG    4
#define SMEM_DYN (NSTG * STG_BYTES + 1024)

__device__ __forceinline__ uint32_t sw128(uint32_t byte) {
    return byte ^ ((byte >> 3) & 0x70);
}

__device__ __forceinline__ void load_stage(
    uint32_t stg,
    const __half* __restrict__ A, const __half* __restrict__ B,
    int m0, int n0, int kBase, int tid)
{
    const int c16 = tid & 7;
    const int rg  = tid >> 3;
    const int kOff = kBase + c16 * 8;
#pragma unroll
    for (int j = 0; j < 4; j++) {
        int row = rg + j * 32;
        uint32_t sw = sw128((uint32_t)row * 128 + c16 * 16);
        CP_ASYNC16(stg + A_OFF + sw, A + (size_t)(m0 + row) * KTOT + kOff);
    }
#pragma unroll
    for (int j = 0; j < 8; j++) {
        int row = rg + j * 32;
        uint32_t sw = sw128((uint32_t)row * 128 + c16 * 16);
        CP_ASYNC16(stg + B_OFF + sw, B + (size_t)(n0 + row) * KTOT + kOff);
    }
}

template <int EPI>
__device__ __forceinline__ void run_gemm(
    const __half* __restrict__ A, const __half* __restrict__ B,
    const float* __restrict__ bias,
    float* __restrict__ Cf, __half* __restrict__ Ch,
    int Ntot, int m0, int n0, uint32_t sbase, int tid)
{
    const int warp = tid >> 5;
    const int lane = tid & 31;
    const int wm   = warp & 1;
    const int wn   = warp >> 1;

    const int lrow = lane & 7;
    const int quad = lane >> 3;
    const int aRow = wm * 64 + (quad & 1) * 8 + lrow;
    const int aKb  = (quad >> 1) * 16;
    const int bRow = wn * 64 + (quad >> 1) * 8 + lrow;
    const int bKb  = (quad & 1) * 16;

    // sw128(row*128 + o) == sw128(row*128) ^ o  for o < 128
    uint32_t aSw[4], bSw[4];
#pragma unroll
    for (int i = 0; i < 4; i++)
        aSw[i] = sw128((uint32_t)(aRow + i * 16) * 128);
#pragma unroll
    for (int g = 0; g < 4; g++)
        bSw[g] = sw128((uint32_t)(bRow + g * 16) * 128);

    float acc[4][8][4];
#pragma unroll
    for (int i = 0; i < 4; i++)
#pragma unroll
        for (int j = 0; j < 8; j++)
#pragma unroll
            for (int q = 0; q < 4; q++) acc[i][j][q] = 0.0f;

    load_stage(sbase,                 A, B, m0, n0, 0,      tid); CP_COMMIT();
    load_stage(sbase + STG_BYTES,     A, B, m0, n0, BK,     tid); CP_COMMIT();
    load_stage(sbase + 2 * STG_BYTES, A, B, m0, n0, 2 * BK, tid); CP_COMMIT();

#pragma unroll 1
    for (int c = 0; c < NCHUNK; c++) {
        if (c < NCHUNK - 2)       { CP_WAIT2(); }
        else if (c == NCHUNK - 2) { CP_WAIT1(); }
        else                      { CP_WAIT0(); }
        __syncthreads();
        if (c + 3 < NCHUNK) {
            load_stage(sbase + ((c + 3) & 3) * STG_BYTES,
                       A, B, m0, n0, (c + 3) * BK, tid);
            CP_COMMIT();
        }
        const uint32_t stg = sbase + (c & 3) * STG_BYTES;

#pragma unroll
        for (int kk = 0; kk < 4; kk++) {
            uint32_t a_r[4][4], b_r[4][4];
            const uint32_t ko = (uint32_t)(kk * 32);
#pragma unroll
            for (int i = 0; i < 4; i++)
                ldsm_x4(a_r[i], stg + A_OFF + (aSw[i] ^ (ko + aKb)));
#pragma unroll
            for (int g = 0; g < 4; g++)
                ldsm_x4(b_r[g], stg + B_OFF + (bSw[g] ^ (ko + bKb)));
#pragma unroll
            for (int i = 0; i < 4; i++)
#pragma unroll
                for (int j = 0; j < 8; j++)
                    mma_f16(acc[i][j], a_r[i], &b_r[j >> 1][(j & 1) * 2]);
        }
    }

    const int er = lane >> 2;
    const int ec = (lane & 3) * 2;
    float bv[8][2];
#pragma unroll
    for (int j = 0; j < 8; j++) {
        int n = n0 + wn * 64 + j * 8 + ec;
        bv[j][0] = bias[n]; bv[j][1] = bias[n + 1];
    }
#pragma unroll
    for (int i = 0; i < 4; i++) {
        int mrow = m0 + wm * 64 + i * 16 + er;
#pragma unroll
        for (int j = 0; j < 8; j++) {
            int n = n0 + wn * 64 + j * 8 + ec;
            float v0 = acc[i][j][0] + bv[j][0], v1 = acc[i][j][1] + bv[j][1];
            float v2 = acc[i][j][2] + bv[j][0], v3 = acc[i][j][3] + bv[j][1];
            size_t g0 = (size_t)mrow * Ntot + n;
            size_t g1 = (size_t)(mrow + 8) * Ntot + n;
            if (EPI == 0) {
                *(float2*)(Cf + g0) = make_float2(v0, v1);
                *(float2*)(Cf + g1) = make_float2(v2, v3);
            } else {
                __half2 p;
                p.x = __float2half_rn(fmaxf(v0, 0.0f));
                p.y = __float2half_rn(fmaxf(v1, 0.0f));
                *(__half2*)(Ch + g0) = p;
                p.x = __float2half_rn(fmaxf(v2, 0.0f));
                p.y = __float2half_rn(fmaxf(v3, 0.0f));
                *(__half2*)(Ch + g1) = p;
            }
        }
    }
}

// ============================================================================
// Fused gemm2 (h1 @ w2^T -> h2, relu, fp16) + gemm3 (h2 @ w3^T -> out, fp32).
// Producers (bids 0..511, m-major) publish per-m-block counters; consumers
// (bids 512.., m-major) acquire-spin until their m-block's 4 tiles are done.
// Producer bids are strictly lower -> dispatched first -> no deadlock.
// ============================================================================
__global__ __launch_bounds__(256, 1)
void gemm_fused(const float* __restrict__ bd2, const float* __restrict__ bd3,
                float* __restrict__ out)
{
    extern __shared__ char dsm[];
    const uint32_t sbase = (smem_u32(dsm) + 1023) & ~1023u;
    const int tid = threadIdx.x;
    const int bid = blockIdx.x;

    if (bid < G2_CTAS) {
        const int mi = bid >> 2, ni = bid & 3;
        run_gemm<1>(g_h1, g_w2, bd2, nullptr, g_h2, DECH,
                    mi * 128, ni * NT, sbase, tid);
        __threadfence();
        __syncthreads();
        if (tid == 0) red_release_add1(&g_ready[mi]);
    } else {
        const int b2 = bid - G2_CTAS;
        const int mi = b2 / 12, nj = b2 % 12;
        if (tid == 0) {
            while (ld_acq(&g_ready[mi]) < 4) __nanosleep(128);
        }
        __syncthreads();
        run_gemm<0>(g_h2, g_w3, bd3, out, nullptr, DIMX,
                    mi * 128, nj * NT, sbase, tid);
    }
}

// ============================================================================
// Flow: per-dim MLP 16->64->64->2 in half2 SIMD over batch pairs.
// lp1 (e1 logprob) stays exact fp32. grid (32, 16), 128 threads.
// ============================================================================
__global__ __launch_bounds__(128)
void flow_kernel(const float* __restrict__ e1, const float* __restrict__ e2,
                 const float* __restrict__ interv,
                 const float* __restrict__ W1, const float* __restrict__ b1,
                 const float* __restrict__ W2, const float* __restrict__ b2,
                 const float* __restrict__ W3, const float* __restrict__ b3) {
    __shared__ __half sW1h[DIMZ * HDIM];
    __shared__ __half sW2h[HDIM * HDIM];
    __shared__ __half sW3h[HDIM * 2];
    __shared__ float sb1[HDIM], sb2[HDIM], sb3v[2];
    __shared__ float red[128];

    const int i = blockIdx.y;
    const int tid = threadIdx.x;

    for (int t = tid; t < DIMZ * HDIM; t += 128)
        sW1h[t] = __float2half_rn(W1[i * DIMZ * HDIM + t]);
    for (int t = tid; t < HDIM * HDIM; t += 128)
        sW2h[t] = __float2half_rn(W2[i * HDIM * HDIM + t]);
    if (tid < HDIM * 2) sW3h[tid] = __float2half_rn(W3[i * HDIM * 2 + tid]);
    if (tid < HDIM) { sb1[tid] = b1[i * HDIM + tid]; sb2[tid] = b2[i * HDIM + tid]; }
    if (tid < 2) sb3v[tid] = b3[i * 2 + tid];
    __syncthreads();

    const int b = (blockIdx.x * 128 + tid) * 2;   // batch pair (b, b+1)

    __half2 ctx2[DIMZ];
    float e1i0 = 0.0f, e1i1 = 0.0f;
#pragma unroll
    for (int d = 0; d < DIMZ; d++) {
        float v0 = e1[(size_t)b * DIMZ + d];
        float v1 = e1[(size_t)(b + 1) * DIMZ + d];
        if (d == i) { e1i0 = v0; e1i1 = v1; v0 = 0.0f; v1 = 0.0f; }
        ctx2[d] = __floats2half2_rn(v0, v1);
    }

    const __half2 z2 = __float2half2_rn(0.0f);
    __half2 h1v[HDIM];
#pragma unroll 8
    for (int j = 0; j < HDIM; j++) {
        __half2 a = __float2half2_rn(sb1[j]);
#pragma unroll
        for (int d = 0; d < DIMZ; d++)
            a = __hfma2(ctx2[d], __half2half2(sW1h[d * HDIM + j]), a);
        h1v[j] = __hmax2(a, z2);
    }

    __half2 p0 = __float2half2_rn(sb3v[0]);
    __half2 p1 = __float2half2_rn(sb3v[1]);
#pragma unroll 4
    for (int k = 0; k < HDIM; k++) {
        __half2 t = __float2half2_rn(sb2[k]);
#pragma unroll
        for (int j = 0; j < HDIM; j++)
            t = __hfma2(h1v[j], __half2half2(sW2h[j * HDIM + k]), t);
        t = __hmax2(t, z2);
        p0 = __hfma2(t, __half2half2(sW3h[k * 2 + 0]), p0);
        p1 = __hfma2(t, __half2half2(sW3h[k * 2 + 1]), p1);
    }

    float lpsum = 0.0f;
#pragma unroll
    for (int s = 0; s < 2; s++) {
        float shift = s ? __high2float(p0) : __low2float(p0);
        float pv1   = s ? __high2float(p1) : __low2float(p1);
        float sp = fmaxf(pv1, 0.0f) + log1pf(expf(-fabsf(pv1)));
        float scale = sp + MIN_STD;
        float z = (e2[(size_t)(b + s) * DIMZ + i] - shift) / scale;
        z = clean_clamp(z);
        float mask = interv[(size_t)(b + s) * (DIMZ + 1) + 1 + i];
        float lp2 = (-0.5f * z * z - 0.5f * LOG2PI - logf(scale)) * mask;
        float e1i = s ? e1i1 : e1i0;
        float lp1 = clean_clamp(-0.5f * e1i * e1i - 0.5f * LOG2PI);
        lpsum += lp1 + lp2;
    }

    red[tid] = lpsum;
    __syncthreads();
#pragma unroll
    for (int st = 64; st > 0; st >>= 1) {
        if (tid < st) red[tid] += red[tid + st];
        __syncthreads();
    }
    if (tid == 0) g_partial[blockIdx.y * gridDim.x + blockIdx.x] = red[0];
}

__global__ void reduce_final_kernel(float* __restrict__ out_scalar) {
    __shared__ float red[256];
    int tid = threadIdx.x;
    float s = 0.0f;
    for (int t = tid; t < 512; t += 256) s += g_partial[t];
    red[tid] = s;
    __syncthreads();
#pragma unroll
    for (int st = 128; st > 0; st >>= 1) {
        if (tid < st) red[tid] += red[tid + st];
        __syncthreads();
    }
    if (tid == 0) {
        float log_p_I = -logf((float)(DIMZ + 1)) * (float)B_HALF;
        *out_scalar = red[0] + log_p_I;
    }
}

// ============================================================================
extern "C" void kernel_launch(void* const* d_in, const int* in_sizes, int n_in,
                              void* d_out, int out_size) {
    const float* e1  = (const float*)d_in[0];
    const float* e2  = (const float*)d_in[1];
    const float* itv = (const float*)d_in[2];
    const float* W1  = (const float*)d_in[3];
    const float* b1  = (const float*)d_in[4];
    const float* W2  = (const float*)d_in[5];
    const float* b2  = (const float*)d_in[6];
    const float* W3  = (const float*)d_in[7];
    const float* b3  = (const float*)d_in[8];
    const float* Wd1 = (const float*)d_in[9];
    const float* bd1 = (const float*)d_in[10];
    const float* Wd2 = (const float*)d_in[11];
    const float* bd2 = (const float*)d_in[12];
    const float* Wd3 = (const float*)d_in[13];
    const float* bd3 = (const float*)d_in[14];
    float* out = (float*)d_out;

    void *p;
    cudaGetSymbolAddress(&p, g_h1); __half* h1 = (__half*)p;
    cudaGetSymbolAddress(&p, g_w2); __half* w2 = (__half*)p;
    cudaGetSymbolAddress(&p, g_w3); __half* w3 = (__half*)p;

    cudaFuncSetAttribute(gemm_fused, cudaFuncAttributeMaxDynamicSharedMemorySize, SMEM_DYN);

    // flow log-prob (independent chain)
    flow_kernel<<<dim3(32, 16), 128>>>(e1, e2, itv, W1, b1, W2, b2, W3, b3);
    reduce_final_kernel<<<1, 256>>>(out + ((size_t)out_size - 1));

    // weight prep: transpose to fp16
    tsplit_kernel<<<dim3(DECH / 32, DECH / 32), 256>>>(Wd2, w2, DECH, DECH);
    tsplit_kernel<<<dim3(DIMX / 32, DECH / 32), 256>>>(Wd3, w3, DECH, DIMX);

    // decoder layer 1 (also zeroes g_ready)
    dec1_kernel<<<B_TOT, 256>>>(e1, e2, Wd1, bd1, h1);

    // fused gemm2 + gemm3
    gemm_fused<<<G2_CTAS + G3_CTAS, 256, SMEM_DYN>>>(bd2, bd3, out);
}

// round 8
// speedup vs baseline: 6.5120x; 1.0371x over previous
#include <cuda_runtime.h>
#include <cuda_fp16.h>
#include <math.h>
#include <stdint.h>

// ============================================================================
// ILCMDecoder on GB300 (baseline-PTX tensor path: mma.sync HMMA fp16 +
// ldmatrix + cp.async; tcgen05 rejected by this harness's ptxas target).
//
// Round 8: ALL prologue work (flow logprob, 2x weight transpose, decoder
// layer 1) fused into one prep_kernel with role dispatch -> components run
// concurrently instead of serially. reduce_final folded into gemm_fused.
// Launch graph: prep_kernel -> gemm_fused. GEMM core unchanged (at HMMA
// pipe roofline).
// ============================================================================

#define B_TOT   16384
#define B_HALF  8192
#define DIMZ    16
#define HDIM    64
#define DECH    1024
#define DIMX    3072
#define KTOT    1024
#define LOG2PI  1.8378770664093453f
#define MIN_STD 0.2f
#define CLAMP_V 1000000.0f

#define G2_CTAS 512            // gemm2: 128 m-tiles x 4 n-tiles
#define G3_CTAS 1536           // gemm3: 128 m-tiles x 12 n-tiles

// prep_kernel role ranges
#define PREP_FLOW  0
#define N_FLOW     256          // 16 dims x 16 chunks (256 batch-pairs each)
#define PREP_TS3   (PREP_FLOW + N_FLOW)
#define N_TS3      3072         // (3072/32) x (1024/32)
#define PREP_TS2   (PREP_TS3 + N_TS3)
#define N_TS2      1024         // (1024/32) x (1024/32)
#define PREP_DEC1  (PREP_TS2 + N_TS2)
#define N_DEC1     1024         // 16 rows per block
#define PREP_TOTAL (PREP_DEC1 + N_DEC1)

// ---------------- device scratch (allocation-free) ----------------
__device__ __half g_h1[(size_t)B_TOT * DECH];
__device__ __half g_h2[(size_t)B_TOT * DECH];
__device__ __half g_w2[(size_t)DECH * DECH];   // Wd2^T fp16 [N,K]
__device__ __half g_w3[(size_t)DIMX * DECH];   // Wd3^T fp16 [N,K]
__device__ float g_partial[256];
__device__ int   g_ready[128];                 // per-m-block h2 readiness (0..4)

// ---------------- PTX helpers (baseline family features only) --------------
__device__ __forceinline__ uint32_t smem_u32(const void* p) {
    uint32_t a;
    asm("{ .reg .u64 t; cvta.to.shared.u64 t, %1; cvt.u32.u64 %0, t; }"
        : "=r"(a) : "l"(p));
    return a;
}

#define CP_ASYNC16(smem, gptr) \
    asm volatile("cp.async.cg.shared.global [%0], [%1], 16;" \
        :: "r"((uint32_t)(smem)), "l"(gptr) : "memory")
#define CP_COMMIT() asm volatile("cp.async.commit_group;" ::: "memory")
#define CP_WAIT2()  asm volatile("cp.async.wait_group 2;" ::: "memory")
#define CP_WAIT1()  asm volatile("cp.async.wait_group 1;" ::: "memory")
#define CP_WAIT0()  asm volatile("cp.async.wait_group 0;" ::: "memory")

__device__ __forceinline__ void ldsm_x4(uint32_t* r, uint32_t addr) {
    asm volatile("ldmatrix.sync.aligned.m8n8.x4.shared.b16 {%0,%1,%2,%3}, [%4];"
        : "=r"(r[0]), "=r"(r[1]), "=r"(r[2]), "=r"(r[3]) : "r"(addr));
}

__device__ __forceinline__ void mma_f16(float* d, const uint32_t* a, const uint32_t* b) {
    asm volatile(
        "mma.sync.aligned.m16n8k16.row.col.f32.f16.f16.f32 "
        "{%0,%1,%2,%3}, {%4,%5,%6,%7}, {%8,%9}, {%0,%1,%2,%3};"
        : "+f"(d[0]), "+f"(d[1]), "+f"(d[2]), "+f"(d[3])
        : "r"(a[0]), "r"(a[1]), "r"(a[2]), "r"(a[3]), "r"(b[0]), "r"(b[1]));
}

__device__ __forceinline__ int ld_acq(const int* p) {
    int v;
    asm volatile("ld.acquire.gpu.s32 %0, [%1];" : "=r"(v) : "l"(p) : "memory");
    return v;
}
__device__ __forceinline__ void red_release_add1(int* p) {
    asm volatile("red.release.gpu.global.add.s32 [%0], %1;" :: "l"(p), "r"(1) : "memory");
}

__device__ __forceinline__ float clean_clamp(float x) {
    if (isnan(x)) x = 0.0f;
    return fminf(fmaxf(x, -CLAMP_V), CLAMP_V);
}

// ============================================================================
// prep_kernel: role dispatch by blockIdx.x
//   flow (256) | tsplit w3 (3072) | tsplit w2 (1024) | dec1 (1024)
// All independent -> run concurrently. 256 threads/block.
// ============================================================================
__device__ __forceinline__ void do_tsplit(const float* __restrict__ W,
                                          __half* __restrict__ T,
                                          int K, int N, int t, int ntx,
                                          char* smbuf, int tid) {
    float* tile = (float*)smbuf;          // [32][33]
    int nb = (t % ntx) * 32, kb = (t / ntx) * 32;
    int tx = tid & 31, ty0 = tid >> 5;    // 8 row-groups
    for (int i2 = ty0; i2 < 32; i2 += 8)
        tile[i2 * 33 + tx] = W[(size_t)(kb + i2) * N + nb + tx];
    __syncthreads();
    for (int i2 = ty0; i2 < 32; i2 += 8)
        T[(size_t)(nb + i2) * K + kb + tx] = __float2half_rn(tile[tx * 33 + i2]);
}

__global__ __launch_bounds__(256)
void prep_kernel(const float* __restrict__ e1, const float* __restrict__ e2,
                 const float* __restrict__ interv,
                 const float* __restrict__ W1, const float* __restrict__ b1,
                 const float* __restrict__ W2, const float* __restrict__ b2,
                 const float* __restrict__ W3, const float* __restrict__ b3,
                 const float* __restrict__ Wd1, const float* __restrict__ bd1,
                 const float* __restrict__ Wd2, const float* __restrict__ Wd3)
{
    __shared__ __align__(16) char smbuf[12288];
    const int bid = blockIdx.x;
    const int tid = threadIdx.x;

    if (bid < PREP_TS3) {
        // ---------------- FLOW role (+ g_ready zeroing) ----------------
        if (bid < 128 && tid == 0) g_ready[bid] = 0;

        const int i  = bid >> 4;     // dim 0..15
        const int bx = bid & 15;     // batch chunk

        __half* sW1h = (__half*)(smbuf);
        __half* sW2h = (__half*)(smbuf + 2048);
        __half* sW3h = (__half*)(smbuf + 10240);
        float*  sb1  = (float*)(smbuf + 10496);
        float*  sb2  = (float*)(smbuf + 10752);
        float*  sb3v = (float*)(smbuf + 11008);
        float*  red  = (float*)(smbuf + 11040);

        for (int t = tid; t < DIMZ * HDIM; t += 256)
            sW1h[t] = __float2half_rn(W1[i * DIMZ * HDIM + t]);
        for (int t = tid; t < HDIM * HDIM; t += 256)
            sW2h[t] = __float2half_rn(W2[i * HDIM * HDIM + t]);
        if (tid < HDIM * 2) sW3h[tid] = __float2half_rn(W3[i * HDIM * 2 + tid]);
        if (tid < HDIM) { sb1[tid] = b1[i * HDIM + tid]; sb2[tid] = b2[i * HDIM + tid]; }
        if (tid < 2) sb3v[tid] = b3[i * 2 + tid];
        __syncthreads();

        const int b = (bx * 256 + tid) * 2;   // batch pair (b, b+1)

        __half2 ctx2[DIMZ];
        float e1i0 = 0.0f, e1i1 = 0.0f;
#pragma unroll
        for (int d = 0; d < DIMZ; d++) {
            float v0 = e1[(size_t)b * DIMZ + d];
            float v1 = e1[(size_t)(b + 1) * DIMZ + d];
            if (d == i) { e1i0 = v0; e1i1 = v1; v0 = 0.0f; v1 = 0.0f; }
            ctx2[d] = __floats2half2_rn(v0, v1);
        }

        const __half2 z2 = __float2half2_rn(0.0f);
        __half2 h1v[HDIM];
#pragma unroll 8
        for (int j = 0; j < HDIM; j++) {
            __half2 a = __float2half2_rn(sb1[j]);
#pragma unroll
            for (int d = 0; d < DIMZ; d++)
                a = __hfma2(ctx2[d], __half2half2(sW1h[d * HDIM + j]), a);
            h1v[j] = __hmax2(a, z2);
        }

        __half2 p0 = __float2half2_rn(sb3v[0]);
        __half2 p1 = __float2half2_rn(sb3v[1]);
#pragma unroll 4
        for (int k = 0; k < HDIM; k++) {
            __half2 t = __float2half2_rn(sb2[k]);
#pragma unroll
            for (int j = 0; j < HDIM; j++)
                t = __hfma2(h1v[j], __half2half2(sW2h[j * HDIM + k]), t);
            t = __hmax2(t, z2);
            p0 = __hfma2(t, __half2half2(sW3h[k * 2 + 0]), p0);
            p1 = __hfma2(t, __half2half2(sW3h[k * 2 + 1]), p1);
        }

        float lpsum = 0.0f;
#pragma unroll
        for (int s = 0; s < 2; s++) {
            float shift = s ? __high2float(p0) : __low2float(p0);
            float pv1   = s ? __high2float(p1) : __low2float(p1);
            float sp = fmaxf(pv1, 0.0f) + log1pf(expf(-fabsf(pv1)));
            float scale = sp + MIN_STD;
            float z = (e2[(size_t)(b + s) * DIMZ + i] - shift) / scale;
            z = clean_clamp(z);
            float mask = interv[(size_t)(b + s) * (DIMZ + 1) + 1 + i];
            float lp2 = (-0.5f * z * z - 0.5f * LOG2PI - logf(scale)) * mask;
            float e1i = s ? e1i1 : e1i0;
            float lp1 = clean_clamp(-0.5f * e1i * e1i - 0.5f * LOG2PI);
            lpsum += lp1 + lp2;
        }

        red[tid] = lpsum;
        __syncthreads();
#pragma unroll
        for (int st = 128; st > 0; st >>= 1) {
            if (tid < st) red[tid] += red[tid + st];
            __syncthreads();
        }
        if (tid == 0) g_partial[i * 16 + bx] = red[0];

    } else if (bid < PREP_TS2) {
        // ---------------- tsplit Wd3 -> g_w3 [DIMX, DECH] ----------------
        do_tsplit(Wd3, g_w3, DECH, DIMX, bid - PREP_TS3, DIMX / 32, smbuf, tid);

    } else if (bid < PREP_DEC1) {
        // ---------------- tsplit Wd2 -> g_w2 [DECH, DECH] ----------------
        do_tsplit(Wd2, g_w2, DECH, DECH, bid - PREP_TS2, DECH / 32, smbuf, tid);

    } else {
        // ---------------- dec1: 16 rows of H1 = relu(E@Wd1+bd1) ----------
        const int rb = (bid - PREP_DEC1) * 16;
        float* se = (float*)smbuf;   // [16][16]
        {
            int r = tid >> 4, d = tid & 15;
            int row = rb + r;
            se[tid] = (row < B_HALF) ? e1[(size_t)row * DIMZ + d]
                                     : e2[(size_t)(row - B_HALF) * DIMZ + d];
        }
        __syncthreads();

        const int c0 = tid * 4;
        float4 bv = *(const float4*)&bd1[c0];
        float acc[16][4];
#pragma unroll
        for (int r = 0; r < 16; r++) {
            acc[r][0] = bv.x; acc[r][1] = bv.y; acc[r][2] = bv.z; acc[r][3] = bv.w;
        }
#pragma unroll
        for (int d = 0; d < DIMZ; d++) {
            float4 w = *(const float4*)&Wd1[d * DECH + c0];
#pragma unroll
            for (int r = 0; r < 16; r++) {
                float ed = se[r * 16 + d];
                acc[r][0] = fmaf(ed, w.x, acc[r][0]);
                acc[r][1] = fmaf(ed, w.y, acc[r][1]);
                acc[r][2] = fmaf(ed, w.z, acc[r][2]);
                acc[r][3] = fmaf(ed, w.w, acc[r][3]);
            }
        }
#pragma unroll
        for (int r = 0; r < 16; r++) {
            __half2 ha, hb;
            ha.x = __float2half_rn(fmaxf(acc[r][0], 0.0f));
            ha.y = __float2half_rn(fmaxf(acc[r][1], 0.0f));
            hb.x = __float2half_rn(fmaxf(acc[r][2], 0.0f));
            hb.y = __float2half_rn(fmaxf(acc[r][3], 0.0f));
            __half* dst = g_h1 + (size_t)(rb + r) * DECH + c0;
            *(__half2*)(dst)     = ha;
            *(__half2*)(dst + 2) = hb;
        }
    }
}

// ============================================================================
// fp16 HMMA GEMM core:  C[M, Ntot] = epi(A @ B^T + bias)
// CTA 128x256, 8 warps (warp tile 64x64), BK=64, 4-stage cp.async pipeline.
// EPI=0: fp32 out.  EPI=1: relu + fp16 out.
// ============================================================================
#define BK       64
#define NCHUNK  (KTOT / BK)       // 16
#define NT       256
#define A_OFF   0
#define B_OFF   16384             // A: 128 rows x 128B
#define STG_BYTES 49152           // A 16K + B 32K
#define NSTG    4
#define SMEM_DYN (NSTG * STG_BYTES + 1024)

__device__ __forceinline__ uint32_t sw128(uint32_t byte) {
    return byte ^ ((byte >> 3) & 0x70);
}

__device__ __forceinline__ void load_stage(
    uint32_t stg,
    const __half* __restrict__ A, const __half* __restrict__ B,
    int m0, int n0, int kBase, int tid)
{
    const int c16 = tid & 7;
    const int rg  = tid >> 3;
    const int kOff = kBase + c16 * 8;
#pragma unroll
    for (int j = 0; j < 4; j++) {
        int row = rg + j * 32;
        uint32_t sw = sw128((uint32_t)row * 128 + c16 * 16);
        CP_ASYNC16(stg + A_OFF + sw, A + (size_t)(m0 + row) * KTOT + kOff);
    }
#pragma unroll
    for (int j = 0; j < 8; j++) {
        int row = rg + j * 32;
        uint32_t sw = sw128((uint32_t)row * 128 + c16 * 16);
        CP_ASYNC16(stg + B_OFF + sw, B + (size_t)(n0 + row) * KTOT + kOff);
    }
}

template <int EPI>
__device__ __forceinline__ void run_gemm(
    const __half* __restrict__ A, const __half* __restrict__ B,
    const float* __restrict__ bias,
    float* __restrict__ Cf, __half* __restrict__ Ch,
    int Ntot, int m0, int n0, uint32_t sbase, int tid)
{
    const int warp = tid >> 5;
    const int lane = tid & 31;
    const int wm   = warp & 1;
    const int wn   = warp >> 1;

    const int lrow = lane & 7;
    const int quad = lane >> 3;
    const int aRow = wm * 64 + (quad & 1) * 8 + lrow;
    const int aKb  = (quad >> 1) * 16;
    const int bRow = wn * 64 + (quad >> 1) * 8 + lrow;
    const int bKb  = (quad & 1) * 16;

    // sw128(row*128 + o) == sw128(row*128) ^ o  for o < 128
    uint32_t aSw[4], bSw[4];
#pragma unroll
    for (int i = 0; i < 4; i++)
        aSw[i] = sw128((uint32_t)(aRow + i * 16) * 128);
#pragma unroll
    for (int g = 0; g < 4; g++)
        bSw[g] = sw128((uint32_t)(bRow + g * 16) * 128);

    float acc[4][8][4];
#pragma unroll
    for (int i = 0; i < 4; i++)
#pragma unroll
        for (int j = 0; j < 8; j++)
#pragma unroll
            for (int q = 0; q < 4; q++) acc[i][j][q] = 0.0f;

    load_stage(sbase,                 A, B, m0, n0, 0,      tid); CP_COMMIT();
    load_stage(sbase + STG_BYTES,     A, B, m0, n0, BK,     tid); CP_COMMIT();
    load_stage(sbase + 2 * STG_BYTES, A, B, m0, n0, 2 * BK, tid); CP_COMMIT();

#pragma unroll 1
    for (int c = 0; c < NCHUNK; c++) {
        if (c < NCHUNK - 2)       { CP_WAIT2(); }
        else if (c == NCHUNK - 2) { CP_WAIT1(); }
        else                      { CP_WAIT0(); }
        __syncthreads();
        if (c + 3 < NCHUNK) {
            load_stage(sbase + ((c + 3) & 3) * STG_BYTES,
                       A, B, m0, n0, (c + 3) * BK, tid);
            CP_COMMIT();
        }
        const uint32_t stg = sbase + (c & 3) * STG_BYTES;

#pragma unroll
        for (int kk = 0; kk < 4; kk++) {
            uint32_t a_r[4][4], b_r[4][4];
            const uint32_t ko = (uint32_t)(kk * 32);
#pragma unroll
            for (int i = 0; i < 4; i++)
                ldsm_x4(a_r[i], stg + A_OFF + (aSw[i] ^ (ko + aKb)));
#pragma unroll
            for (int g = 0; g < 4; g++)
                ldsm_x4(b_r[g], stg + B_OFF + (bSw[g] ^ (ko + bKb)));
#pragma unroll
            for (int i = 0; i < 4; i++)
#pragma unroll
                for (int j = 0; j < 8; j++)
                    mma_f16(acc[i][j], a_r[i], &b_r[j >> 1][(j & 1) * 2]);
        }
    }

    const int er = lane >> 2;
    const int ec = (lane & 3) * 2;
    float bv[8][2];
#pragma unroll
    for (int j = 0; j < 8; j++) {
        int n = n0 + wn * 64 + j * 8 + ec;
        bv[j][0] = bias[n]; bv[j][1] = bias[n + 1];
    }
#pragma unroll
    for (int i = 0; i < 4; i++) {
        int mrow = m0 + wm * 64 + i * 16 + er;
#pragma unroll
        for (int j = 0; j < 8; j++) {
            int n = n0 + wn * 64 + j * 8 + ec;
            float v0 = acc[i][j][0] + bv[j][0], v1 = acc[i][j][1] + bv[j][1];
            float v2 = acc[i][j][2] + bv[j][0], v3 = acc[i][j][3] + bv[j][1];
            size_t g0 = (size_t)mrow * Ntot + n;
            size_t g1 = (size_t)(mrow + 8) * Ntot + n;
            if (EPI == 0) {
                *(float2*)(Cf + g0) = make_float2(v0, v1);
                *(float2*)(Cf + g1) = make_float2(v2, v3);
            } else {
                __half2 p;
                p.x = __float2half_rn(fmaxf(v0, 0.0f));
                p.y = __float2half_rn(fmaxf(v1, 0.0f));
                *(__half2*)(Ch + g0) = p;
                p.x = __float2half_rn(fmaxf(v2, 0.0f));
                p.y = __float2half_rn(fmaxf(v3, 0.0f));
                *(__half2*)(Ch + g1) = p;
            }
        }
    }
}

// ============================================================================
// Fused gemm2 (h1 @ w2^T -> h2, relu, fp16) + gemm3 (h2 @ w3^T -> out, fp32)
// + final log_p reduction (one extra CTA; flow finished in prep_kernel).
// Producers (bids 0..511) publish per-m-block counters; consumers acquire-
// spin until their m-block's 4 tiles are done. Producer bids are lower ->
// dispatched first -> no deadlock.
// ============================================================================
__global__ __launch_bounds__(256, 1)
void gemm_fused(const float* __restrict__ bd2, const float* __restrict__ bd3,
                float* __restrict__ out, float* __restrict__ out_scalar)
{
    extern __shared__ char dsm[];
    const uint32_t sbase = (smem_u32(dsm) + 1023) & ~1023u;
    const int tid = threadIdx.x;
    const int bid = blockIdx.x;

    if (bid < G2_CTAS) {
        const int mi = bid >> 2, ni = bid & 3;
        run_gemm<1>(g_h1, g_w2, bd2, nullptr, g_h2, DECH,
                    mi * 128, ni * NT, sbase, tid);
        __threadfence();
        __syncthreads();
        if (tid == 0) red_release_add1(&g_ready[mi]);
    } else if (bid < G2_CTAS + G3_CTAS) {
        const int b2 = bid - G2_CTAS;
        const int mi = b2 / 12, nj = b2 % 12;
        if (tid == 0) {
            while (ld_acq(&g_ready[mi]) < 4) __nanosleep(128);
        }
        __syncthreads();
        run_gemm<0>(g_h2, g_w3, bd3, out, nullptr, DIMX,
                    mi * 128, nj * NT, sbase, tid);
    } else {
        // final log_p reduction (g_partial written by prep_kernel)
        __shared__ float red2[256];
        red2[tid] = g_partial[tid];
        __syncthreads();
#pragma unroll
        for (int st = 128; st > 0; st >>= 1) {
            if (tid < st) red2[tid] += red2[tid + st];
            __syncthreads();
        }
        if (tid == 0) {
            float log_p_I = -logf((float)(DIMZ + 1)) * (float)B_HALF;
            *out_scalar = red2[0] + log_p_I;
        }
    }
}

// ============================================================================
extern "C" void kernel_launch(void* const* d_in, const int* in_sizes, int n_in,
                              void* d_out, int out_size) {
    const float* e1  = (const float*)d_in[0];
    const float* e2  = (const float*)d_in[1];
    const float* itv = (const float*)d_in[2];
    const float* W1  = (const float*)d_in[3];
    const float* b1  = (const float*)d_in[4];
    const float* W2  = (const float*)d_in[5];
    const float* b2  = (const float*)d_in[6];
    const float* W3  = (const float*)d_in[7];
    const float* b3  = (const float*)d_in[8];
    const float* Wd1 = (const float*)d_in[9];
    const float* bd1 = (const float*)d_in[10];
    const float* Wd2 = (const float*)d_in[11];
    const float* bd2 = (const float*)d_in[12];
    const float* Wd3 = (const float*)d_in[13];
    const float* bd3 = (const float*)d_in[14];
    float* out = (float*)d_out;

    cudaFuncSetAttribute(gemm_fused, cudaFuncAttributeMaxDynamicSharedMemorySize, SMEM_DYN);

    // one prep kernel: flow + tsplit(w3) + tsplit(w2) + dec1, concurrent
    prep_kernel<<<PREP_TOTAL, 256>>>(e1, e2, itv, W1, b1, W2, b2, W3, b3,
                                     Wd1, bd1, Wd2, Wd3);

    // fused gemm2 + gemm3 + log_p finalize
    gemm_fused<<<G2_CTAS + G3_CTAS + 1, 256, SMEM_DYN>>>(
        bd2, bd3, out, out + ((size_t)out_size - 1));
}

// round 9
// speedup vs baseline: 7.1884x; 1.1039x over previous
#include <cuda_runtime.h>
#include <cuda_fp16.h>
#include <math.h>
#include <stdint.h>

// ============================================================================
// ILCMDecoder on GB300 (baseline-PTX tensor path: mma.sync HMMA fp16 +
// ldmatrix + cp.async; tcgen05 rejected by this harness's ptxas target).
//
// Round 9: prep restructured for occupancy, grouped by register footprint:
//   prepA (heavy regs, 2 blk/SM): flow logprob + dec1 (8 rows/block)
//   prepB (light regs, high occ): both weight transposes
//   gemm_fused: UNCHANGED from Round 8 (365us, tensor 62%)
// ============================================================================

#define B_TOT   16384
#define B_HALF  8192
#define DIMZ    16
#define HDIM    64
#define DECH    1024
#define DIMX    3072
#define KTOT    1024
#define LOG2PI  1.8378770664093453f
#define MIN_STD 0.2f
#define CLAMP_V 1000000.0f

#define G2_CTAS 512            // gemm2: 128 m-tiles x 4 n-tiles
#define G3_CTAS 1536           // gemm3: 128 m-tiles x 12 n-tiles

// prepA roles: flow (256) | dec1 (2048, 8 rows each)
#define PA_FLOW   0
#define PA_DEC1   256
#define PA_TOTAL  (256 + 2048)
// prepB roles: ts3 (3072) | ts2 (1024)
#define PB_TS3    0
#define PB_TS2    3072
#define PB_TOTAL  4096

// ---------------- device scratch (allocation-free) ----------------
__device__ __half g_h1[(size_t)B_TOT * DECH];
__device__ __half g_h2[(size_t)B_TOT * DECH];
__device__ __half g_w2[(size_t)DECH * DECH];   // Wd2^T fp16 [N,K]
__device__ __half g_w3[(size_t)DIMX * DECH];   // Wd3^T fp16 [N,K]
__device__ float g_partial[256];
__device__ int   g_ready[128];                 // per-m-block h2 readiness (0..4)

// ---------------- PTX helpers (baseline family features only) --------------
__device__ __forceinline__ uint32_t smem_u32(const void* p) {
    uint32_t a;
    asm("{ .reg .u64 t; cvta.to.shared.u64 t, %1; cvt.u32.u64 %0, t; }"
        : "=r"(a) : "l"(p));
    return a;
}

#define CP_ASYNC16(smem, gptr) \
    asm volatile("cp.async.cg.shared.global [%0], [%1], 16;" \
        :: "r"((uint32_t)(smem)), "l"(gptr) : "memory")
#define CP_COMMIT() asm volatile("cp.async.commit_group;" ::: "memory")
#define CP_WAIT2()  asm volatile("cp.async.wait_group 2;" ::: "memory")
#define CP_WAIT1()  asm volatile("cp.async.wait_group 1;" ::: "memory")
#define CP_WAIT0()  asm volatile("cp.async.wait_group 0;" ::: "memory")

__device__ __forceinline__ void ldsm_x4(uint32_t* r, uint32_t addr) {
    asm volatile("ldmatrix.sync.aligned.m8n8.x4.shared.b16 {%0,%1,%2,%3}, [%4];"
        : "=r"(r[0]), "=r"(r[1]), "=r"(r[2]), "=r"(r[3]) : "r"(addr));
}

__device__ __forceinline__ void mma_f16(float* d, const uint32_t* a, const uint32_t* b) {
    asm volatile(
        "mma.sync.aligned.m16n8k16.row.col.f32.f16.f16.f32 "
        "{%0,%1,%2,%3}, {%4,%5,%6,%7}, {%8,%9}, {%0,%1,%2,%3};"
        : "+f"(d[0]), "+f"(d[1]), "+f"(d[2]), "+f"(d[3])
        : "r"(a[0]), "r"(a[1]), "r"(a[2]), "r"(a[3]), "r"(b[0]), "r"(b[1]));
}

__device__ __forceinline__ int ld_acq(const int* p) {
    int v;
    asm volatile("ld.acquire.gpu.s32 %0, [%1];" : "=r"(v) : "l"(p) : "memory");
    return v;
}
__device__ __forceinline__ void red_release_add1(int* p) {
    asm volatile("red.release.gpu.global.add.s32 [%0], %1;" :: "l"(p), "r"(1) : "memory");
}

__device__ __forceinline__ float clean_clamp(float x) {
    if (isnan(x)) x = 0.0f;
    return fminf(fmaxf(x, -CLAMP_V), CLAMP_V);
}

// ============================================================================
// prepA: flow (256 blocks) + dec1 (2048 blocks x 8 rows) + g_ready zeroing.
// Both roles ~similar (high) register footprint -> 2 blocks/SM.
// ============================================================================
__global__ __launch_bounds__(256)
void prepA_kernel(const float* __restrict__ e1, const float* __restrict__ e2,
                  const float* __restrict__ interv,
                  const float* __restrict__ W1, const float* __restrict__ b1,
                  const float* __restrict__ W2, const float* __restrict__ b2,
                  const float* __restrict__ W3, const float* __restrict__ b3,
                  const float* __restrict__ Wd1, const float* __restrict__ bd1)
{
    __shared__ __align__(16) char smbuf[12288];
    const int bid = blockIdx.x;
    const int tid = threadIdx.x;

    if (bid < PA_DEC1) {
        // ---------------- FLOW role ----------------
        const int i  = bid >> 4;     // dim 0..15
        const int bx = bid & 15;     // batch chunk

        __half* sW1h = (__half*)(smbuf);
        __half* sW2h = (__half*)(smbuf + 2048);
        __half* sW3h = (__half*)(smbuf + 10240);
        float*  sb1  = (float*)(smbuf + 10496);
        float*  sb2  = (float*)(smbuf + 10752);
        float*  sb3v = (float*)(smbuf + 11008);
        float*  red  = (float*)(smbuf + 11040);

        for (int t = tid; t < DIMZ * HDIM; t += 256)
            sW1h[t] = __float2half_rn(W1[i * DIMZ * HDIM + t]);
        for (int t = tid; t < HDIM * HDIM; t += 256)
            sW2h[t] = __float2half_rn(W2[i * HDIM * HDIM + t]);
        if (tid < HDIM * 2) sW3h[tid] = __float2half_rn(W3[i * HDIM * 2 + tid]);
        if (tid < HDIM) { sb1[tid] = b1[i * HDIM + tid]; sb2[tid] = b2[i * HDIM + tid]; }
        if (tid < 2) sb3v[tid] = b3[i * 2 + tid];
        __syncthreads();

        const int b = (bx * 256 + tid) * 2;   // batch pair (b, b+1)

        __half2 ctx2[DIMZ];
        float e1i0 = 0.0f, e1i1 = 0.0f;
#pragma unroll
        for (int d = 0; d < DIMZ; d++) {
            float v0 = e1[(size_t)b * DIMZ + d];
            float v1 = e1[(size_t)(b + 1) * DIMZ + d];
            if (d == i) { e1i0 = v0; e1i1 = v1; v0 = 0.0f; v1 = 0.0f; }
            ctx2[d] = __floats2half2_rn(v0, v1);
        }

        const __half2 z2 = __float2half2_rn(0.0f);
        __half2 h1v[HDIM];
#pragma unroll 8
        for (int j = 0; j < HDIM; j++) {
            __half2 a = __float2half2_rn(sb1[j]);
#pragma unroll
            for (int d = 0; d < DIMZ; d++)
                a = __hfma2(ctx2[d], __half2half2(sW1h[d * HDIM + j]), a);
            h1v[j] = __hmax2(a, z2);
        }

        __half2 p0 = __float2half2_rn(sb3v[0]);
        __half2 p1 = __float2half2_rn(sb3v[1]);
#pragma unroll 4
        for (int k = 0; k < HDIM; k++) {
            __half2 t = __float2half2_rn(sb2[k]);
#pragma unroll
            for (int j = 0; j < HDIM; j++)
                t = __hfma2(h1v[j], __half2half2(sW2h[j * HDIM + k]), t);
            t = __hmax2(t, z2);
            p0 = __hfma2(t, __half2half2(sW3h[k * 2 + 0]), p0);
            p1 = __hfma2(t, __half2half2(sW3h[k * 2 + 1]), p1);
        }

        float lpsum = 0.0f;
#pragma unroll
        for (int s = 0; s < 2; s++) {
            float shift = s ? __high2float(p0) : __low2float(p0);
            float pv1   = s ? __high2float(p1) : __low2float(p1);
            float sp = fmaxf(pv1, 0.0f) + log1pf(expf(-fabsf(pv1)));
            float scale = sp + MIN_STD;
            float z = (e2[(size_t)(b + s) * DIMZ + i] - shift) / scale;
            z = clean_clamp(z);
            float mask = interv[(size_t)(b + s) * (DIMZ + 1) + 1 + i];
            float lp2 = (-0.5f * z * z - 0.5f * LOG2PI - logf(scale)) * mask;
            float e1i = s ? e1i1 : e1i0;
            float lp1 = clean_clamp(-0.5f * e1i * e1i - 0.5f * LOG2PI);
            lpsum += lp1 + lp2;
        }

        red[tid] = lpsum;
        __syncthreads();
#pragma unroll
        for (int st = 128; st > 0; st >>= 1) {
            if (tid < st) red[tid] += red[tid + st];
            __syncthreads();
        }
        if (tid == 0) g_partial[i * 16 + bx] = red[0];

    } else {
        // ---------------- dec1 role: 8 rows of H1 = relu(E@Wd1+bd1) ------
        const int db = bid - PA_DEC1;
        if (db < 128 && tid == 0) g_ready[db] = 0;   // zero counters (pre-gemm)

        const int rb = db * 8;
        float* se = (float*)smbuf;   // [8][16]
        if (tid < 128) {
            int r = tid >> 4, d = tid & 15;
            int row = rb + r;
            se[tid] = (row < B_HALF) ? e1[(size_t)row * DIMZ + d]
                                     : e2[(size_t)(row - B_HALF) * DIMZ + d];
        }
        __syncthreads();

        const int c0 = tid * 4;
        float4 bv = *(const float4*)&bd1[c0];
        float acc[8][4];
#pragma unroll
        for (int r = 0; r < 8; r++) {
            acc[r][0] = bv.x; acc[r][1] = bv.y; acc[r][2] = bv.z; acc[r][3] = bv.w;
        }
#pragma unroll
        for (int d = 0; d < DIMZ; d++) {
            float4 w = *(const float4*)&Wd1[d * DECH + c0];
#pragma unroll
            for (int r = 0; r < 8; r++) {
                float ed = se[r * 16 + d];
                acc[r][0] = fmaf(ed, w.x, acc[r][0]);
                acc[r][1] = fmaf(ed, w.y, acc[r][1]);
                acc[r][2] = fmaf(ed, w.z, acc[r][2]);
                acc[r][3] = fmaf(ed, w.w, acc[r][3]);
            }
        }
#pragma unroll
        for (int r = 0; r < 8; r++) {
            __half2 ha, hb;
            ha.x = __float2half_rn(fmaxf(acc[r][0], 0.0f));
            ha.y = __float2half_rn(fmaxf(acc[r][1], 0.0f));
            hb.x = __float2half_rn(fmaxf(acc[r][2], 0.0f));
            hb.y = __float2half_rn(fmaxf(acc[r][3], 0.0f));
            __half* dst = g_h1 + (size_t)(rb + r) * DECH + c0;
            *(__half2*)(dst)     = ha;
            *(__half2*)(dst + 2) = hb;
        }
    }
}

// ============================================================================
// prepB: weight transposes (lightweight, high occupancy).
//   ts3 (3072): Wd3[K,N] -> g_w3[N,K];  ts2 (1024): Wd2 -> g_w2
// ============================================================================
__device__ __forceinline__ void do_tsplit(const float* __restrict__ W,
                                          __half* __restrict__ T,
                                          int K, int N, int t, int ntx,
                                          float* tile, int tid) {
    int nb = (t % ntx) * 32, kb = (t / ntx) * 32;
    int tx = tid & 31, ty0 = tid >> 5;    // 8 row-groups
    for (int i2 = ty0; i2 < 32; i2 += 8)
        tile[i2 * 33 + tx] = W[(size_t)(kb + i2) * N + nb + tx];
    __syncthreads();
    for (int i2 = ty0; i2 < 32; i2 += 8)
        T[(size_t)(nb + i2) * K + kb + tx] = __float2half_rn(tile[tx * 33 + i2]);
}

__global__ __launch_bounds__(256)
void prepB_kernel(const float* __restrict__ Wd2, const float* __restrict__ Wd3)
{
    __shared__ float tile[32 * 33];
    const int bid = blockIdx.x;
    const int tid = threadIdx.x;
    if (bid < PB_TS2)
        do_tsplit(Wd3, g_w3, DECH, DIMX, bid,          DIMX / 32, tile, tid);
    else
        do_tsplit(Wd2, g_w2, DECH, DECH, bid - PB_TS2, DECH / 32, tile, tid);
}

// ============================================================================
// fp16 HMMA GEMM core (UNCHANGED from Round 8)
// ============================================================================
#define BK       64
#define NCHUNK  (KTOT / BK)       // 16
#define NT       256
#define A_OFF   0
#define B_OFF   16384             // A: 128 rows x 128B
#define STG_BYTES 49152           // A 16K + B 32K
#define NSTG    4
#define SMEM_DYN (NSTG * STG_BYTES + 1024)

__device__ __forceinline__ uint32_t sw128(uint32_t byte) {
    return byte ^ ((byte >> 3) & 0x70);
}

__device__ __forceinline__ void load_stage(
    uint32_t stg,
    const __half* __restrict__ A, const __half* __restrict__ B,
    int m0, int n0, int kBase, int tid)
{
    const int c16 = tid & 7;
    const int rg  = tid >> 3;
    const int kOff = kBase + c16 * 8;
#pragma unroll
    for (int j = 0; j < 4; j++) {
        int row = rg + j * 32;
        uint32_t sw = sw128((uint32_t)row * 128 + c16 * 16);
        CP_ASYNC16(stg + A_OFF + sw, A + (size_t)(m0 + row) * KTOT + kOff);
    }
#pragma unroll
    for (int j = 0; j < 8; j++) {
        int row = rg + j * 32;
        uint32_t sw = sw128((uint32_t)row * 128 + c16 * 16);
        CP_ASYNC16(stg + B_OFF + sw, B + (size_t)(n0 + row) * KTOT + kOff);
    }
}

template <int EPI>
__device__ __forceinline__ void run_gemm(
    const __half* __restrict__ A, const __half* __restrict__ B,
    const float* __restrict__ bias,
    float* __restrict__ Cf, __half* __restrict__ Ch,
    int Ntot, int m0, int n0, uint32_t sbase, int tid)
{
    const int warp = tid >> 5;
    const int lane = tid & 31;
    const int wm   = warp & 1;
    const int wn   = warp >> 1;

    const int lrow = lane & 7;
    const int quad = lane >> 3;
    const int aRow = wm * 64 + (quad & 1) * 8 + lrow;
    const int aKb  = (quad >> 1) * 16;
    const int bRow = wn * 64 + (quad >> 1) * 8 + lrow;
    const int bKb  = (quad & 1) * 16;

    // sw128(row*128 + o) == sw128(row*128) ^ o  for o < 128
    uint32_t aSw[4], bSw[4];
#pragma unroll
    for (int i = 0; i < 4; i++)
        aSw[i] = sw128((uint32_t)(aRow + i * 16) * 128);
#pragma unroll
    for (int g = 0; g < 4; g++)
        bSw[g] = sw128((uint32_t)(bRow + g * 16) * 128);

    float acc[4][8][4];
#pragma unroll
    for (int i = 0; i < 4; i++)
#pragma unroll
        for (int j = 0; j < 8; j++)
#pragma unroll
            for (int q = 0; q < 4; q++) acc[i][j][q] = 0.0f;

    load_stage(sbase,                 A, B, m0, n0, 0,      tid); CP_COMMIT();
    load_stage(sbase + STG_BYTES,     A, B, m0, n0, BK,     tid); CP_COMMIT();
    load_stage(sbase + 2 * STG_BYTES, A, B, m0, n0, 2 * BK, tid); CP_COMMIT();

#pragma unroll 1
    for (int c = 0; c < NCHUNK; c++) {
        if (c < NCHUNK - 2)       { CP_WAIT2(); }
        else if (c == NCHUNK - 2) { CP_WAIT1(); }
        else                      { CP_WAIT0(); }
        __syncthreads();
        if (c + 3 < NCHUNK) {
            load_stage(sbase + ((c + 3) & 3) * STG_BYTES,
                       A, B, m0, n0, (c + 3) * BK, tid);
            CP_COMMIT();
        }
        const uint32_t stg = sbase + (c & 3) * STG_BYTES;

#pragma unroll
        for (int kk = 0; kk < 4; kk++) {
            uint32_t a_r[4][4], b_r[4][4];
            const uint32_t ko = (uint32_t)(kk * 32);
#pragma unroll
            for (int i = 0; i < 4; i++)
                ldsm_x4(a_r[i], stg + A_OFF + (aSw[i] ^ (ko + aKb)));
#pragma unroll
            for (int g = 0; g < 4; g++)
                ldsm_x4(b_r[g], stg + B_OFF + (bSw[g] ^ (ko + bKb)));
#pragma unroll
            for (int i = 0; i < 4; i++)
#pragma unroll
                for (int j = 0; j < 8; j++)
                    mma_f16(acc[i][j], a_r[i], &b_r[j >> 1][(j & 1) * 2]);
        }
    }

    const int er = lane >> 2;
    const int ec = (lane & 3) * 2;
    float bv[8][2];
#pragma unroll
    for (int j = 0; j < 8; j++) {
        int n = n0 + wn * 64 + j * 8 + ec;
        bv[j][0] = bias[n]; bv[j][1] = bias[n + 1];
    }
#pragma unroll
    for (int i = 0; i < 4; i++) {
        int mrow = m0 + wm * 64 + i * 16 + er;
#pragma unroll
        for (int j = 0; j < 8; j++) {
            int n = n0 + wn * 64 + j * 8 + ec;
            float v0 = acc[i][j][0] + bv[j][0], v1 = acc[i][j][1] + bv[j][1];
            float v2 = acc[i][j][2] + bv[j][0], v3 = acc[i][j][3] + bv[j][1];
            size_t g0 = (size_t)mrow * Ntot + n;
            size_t g1 = (size_t)(mrow + 8) * Ntot + n;
            if (EPI == 0) {
                *(float2*)(Cf + g0) = make_float2(v0, v1);
                *(float2*)(Cf + g1) = make_float2(v2, v3);
            } else {
                __half2 p;
                p.x = __float2half_rn(fmaxf(v0, 0.0f));
                p.y = __float2half_rn(fmaxf(v1, 0.0f));
                *(__half2*)(Ch + g0) = p;
                p.x = __float2half_rn(fmaxf(v2, 0.0f));
                p.y = __float2half_rn(fmaxf(v3, 0.0f));
                *(__half2*)(Ch + g1) = p;
            }
        }
    }
}

// ============================================================================
// Fused gemm2 + gemm3 + log_p finalize (UNCHANGED from Round 8)
// ============================================================================
__global__ __launch_bounds__(256, 1)
void gemm_fused(const float* __restrict__ bd2, const float* __restrict__ bd3,
                float* __restrict__ out, float* __restrict__ out_scalar)
{
    extern __shared__ char dsm[];
    const uint32_t sbase = (smem_u32(dsm) + 1023) & ~1023u;
    const int tid = threadIdx.x;
    const int bid = blockIdx.x;

    if (bid < G2_CTAS) {
        const int mi = bid >> 2, ni = bid & 3;
        run_gemm<1>(g_h1, g_w2, bd2, nullptr, g_h2, DECH,
                    mi * 128, ni * NT, sbase, tid);
        __threadfence();
        __syncthreads();
        if (tid == 0) red_release_add1(&g_ready[mi]);
    } else if (bid < G2_CTAS + G3_CTAS) {
        const int b2 = bid - G2_CTAS;
        const int mi = b2 / 12, nj = b2 % 12;
        if (tid == 0) {
            while (ld_acq(&g_ready[mi]) < 4) __nanosleep(128);
        }
        __syncthreads();
        run_gemm<0>(g_h2, g_w3, bd3, out, nullptr, DIMX,
                    mi * 128, nj * NT, sbase, tid);
    } else {
        __shared__ float red2[256];
        red2[tid] = g_partial[tid];
        __syncthreads();
#pragma unroll
        for (int st = 128; st > 0; st >>= 1) {
            if (tid < st) red2[tid] += red2[tid + st];
            __syncthreads();
        }
        if (tid == 0) {
            float log_p_I = -logf((float)(DIMZ + 1)) * (float)B_HALF;
            *out_scalar = red2[0] + log_p_I;
        }
    }
}

// ============================================================================
extern "C" void kernel_launch(void* const* d_in, const int* in_sizes, int n_in,
                              void* d_out, int out_size) {
    const float* e1  = (const float*)d_in[0];
    const float* e2  = (const float*)d_in[1];
    const float* itv = (const float*)d_in[2];
    const float* W1  = (const float*)d_in[3];
    const float* b1  = (const float*)d_in[4];
    const float* W2  = (const float*)d_in[5];
    const float* b2  = (const float*)d_in[6];
    const float* W3  = (const float*)d_in[7];
    const float* b3  = (const float*)d_in[8];
    const float* Wd1 = (const float*)d_in[9];
    const float* bd1 = (const float*)d_in[10];
    const float* Wd2 = (const float*)d_in[11];
    const float* bd2 = (const float*)d_in[12];
    const float* Wd3 = (const float*)d_in[13];
    const float* bd3 = (const float*)d_in[14];
    float* out = (float*)d_out;

    cudaFuncSetAttribute(gemm_fused, cudaFuncAttributeMaxDynamicSharedMemorySize, SMEM_DYN);

    // prep, grouped by register footprint (occupancy!)
    prepA_kernel<<<PA_TOTAL, 256>>>(e1, e2, itv, W1, b1, W2, b2, W3, b3, Wd1, bd1);
    prepB_kernel<<<PB_TOTAL, 256>>>(Wd2, Wd3);

    // fused gemm2 + gemm3 + log_p finalize
    gemm_fused<<<G2_CTAS + G3_CTAS + 1, 256, SMEM_DYN>>>(
        bd2, bd3, out, out + ((size_t)out_size - 1));
}

// round 10
// speedup vs baseline: 7.2850x; 1.0134x over previous
#include <cuda_runtime.h>
#include <cuda_fp16.h>
#include <math.h>
#include <stdint.h>

// ============================================================================
// ILCMDecoder on GB300 (baseline-PTX tensor path: mma.sync HMMA fp16 +
// ldmatrix + cp.async; tcgen05 rejected by this harness's ptxas target).
//
// Round 10: flow re-packed as half2-over-hidden-dim (1 batch/thread,
// h1 in 32 half2 regs) -> ~70 regs, homogeneous with dec1/tsplit ->
// ONE prep kernel, __launch_bounds__(256,3) for 3 CTAs/SM.
// gemm_fused unchanged (365us, tensor 62%).
// ============================================================================

#define B_TOT   16384
#define B_HALF  8192
#define DIMZ    16
#define HDIM    64
#define DECH    1024
#define DIMX    3072
#define KTOT    1024
#define LOG2PI  1.8378770664093453f
#define MIN_STD 0.2f
#define CLAMP_V 1000000.0f

#define G2_CTAS 512            // gemm2: 128 m-tiles x 4 n-tiles
#define G3_CTAS 1536           // gemm3: 128 m-tiles x 12 n-tiles

// prep roles (one kernel): flow | dec1 | ts3 | ts2
#define PR_FLOW   0
#define N_FLOW    512           // 16 dims x 32 chunks (256 batch each)
#define PR_DEC1   (PR_FLOW + N_FLOW)
#define N_DEC1    2048          // 8 rows per block
#define PR_TS3    (PR_DEC1 + N_DEC1)
#define N_TS3     3072
#define PR_TS2    (PR_TS3 + N_TS3)
#define N_TS2     1024
#define PR_TOTAL  (PR_TS2 + N_TS2)

// ---------------- device scratch (allocation-free) ----------------
__device__ __half g_h1[(size_t)B_TOT * DECH];
__device__ __half g_h2[(size_t)B_TOT * DECH];
__device__ __half g_w2[(size_t)DECH * DECH];   // Wd2^T fp16 [N,K]
__device__ __half g_w3[(size_t)DIMX * DECH];   // Wd3^T fp16 [N,K]
__device__ float g_partial[512];
__device__ int   g_ready[128];                 // per-m-block h2 readiness (0..4)

// ---------------- PTX helpers (baseline family features only) --------------
__device__ __forceinline__ uint32_t smem_u32(const void* p) {
    uint32_t a;
    asm("{ .reg .u64 t; cvta.to.shared.u64 t, %1; cvt.u32.u64 %0, t; }"
        : "=r"(a) : "l"(p));
    return a;
}

#define CP_ASYNC16(smem, gptr) \
    asm volatile("cp.async.cg.shared.global [%0], [%1], 16;" \
        :: "r"((uint32_t)(smem)), "l"(gptr) : "memory")
#define CP_COMMIT() asm volatile("cp.async.commit_group;" ::: "memory")
#define CP_WAIT2()  asm volatile("cp.async.wait_group 2;" ::: "memory")
#define CP_WAIT1()  asm volatile("cp.async.wait_group 1;" ::: "memory")
#define CP_WAIT0()  asm volatile("cp.async.wait_group 0;" ::: "memory")

__device__ __forceinline__ void ldsm_x4(uint32_t* r, uint32_t addr) {
    asm volatile("ldmatrix.sync.aligned.m8n8.x4.shared.b16 {%0,%1,%2,%3}, [%4];"
        : "=r"(r[0]), "=r"(r[1]), "=r"(r[2]), "=r"(r[3]) : "r"(addr));
}

__device__ __forceinline__ void mma_f16(float* d, const uint32_t* a, const uint32_t* b) {
    asm volatile(
        "mma.sync.aligned.m16n8k16.row.col.f32.f16.f16.f32 "
        "{%0,%1,%2,%3}, {%4,%5,%6,%7}, {%8,%9}, {%0,%1,%2,%3};"
        : "+f"(d[0]), "+f"(d[1]), "+f"(d[2]), "+f"(d[3])
        : "r"(a[0]), "r"(a[1]), "r"(a[2]), "r"(a[3]), "r"(b[0]), "r"(b[1]));
}

__device__ __forceinline__ int ld_acq(const int* p) {
    int v;
    asm volatile("ld.acquire.gpu.s32 %0, [%1];" : "=r"(v) : "l"(p) : "memory");
    return v;
}
__device__ __forceinline__ void red_release_add1(int* p) {
    asm volatile("red.release.gpu.global.add.s32 [%0], %1;" :: "l"(p), "r"(1) : "memory");
}

__device__ __forceinline__ float clean_clamp(float x) {
    if (isnan(x)) x = 0.0f;
    return fminf(fmaxf(x, -CLAMP_V), CLAMP_V);
}

// ============================================================================
// prep kernel: flow (512) | dec1 (2048) | ts3 (3072) | ts2 (1024)
// Homogeneous ~70-reg roles; 3 CTAs/SM enforced.
// ============================================================================
__device__ __forceinline__ void do_tsplit(const float* __restrict__ W,
                                          __half* __restrict__ T,
                                          int K, int N, int t, int ntx,
                                          float* tile, int tid) {
    int nb = (t % ntx) * 32, kb = (t / ntx) * 32;
    int tx = tid & 31, ty0 = tid >> 5;
    for (int i2 = ty0; i2 < 32; i2 += 8)
        tile[i2 * 33 + tx] = W[(size_t)(kb + i2) * N + nb + tx];
    __syncthreads();
    for (int i2 = ty0; i2 < 32; i2 += 8)
        T[(size_t)(nb + i2) * K + kb + tx] = __float2half_rn(tile[tx * 33 + i2]);
}

__global__ __launch_bounds__(256, 3)
void prep_kernel(const float* __restrict__ e1, const float* __restrict__ e2,
                 const float* __restrict__ interv,
                 const float* __restrict__ W1, const float* __restrict__ b1,
                 const float* __restrict__ W2, const float* __restrict__ b2,
                 const float* __restrict__ W3, const float* __restrict__ b3,
                 const float* __restrict__ Wd1, const float* __restrict__ bd1,
                 const float* __restrict__ Wd2, const float* __restrict__ Wd3)
{
    __shared__ __align__(16) char smbuf[12288];
    const int bid = blockIdx.x;
    const int tid = threadIdx.x;

    if (bid < PR_DEC1) {
        // ---------------- FLOW: half2 packed over hidden dim j ----------
        const int i  = bid >> 5;     // dim 0..15
        const int bx = bid & 31;     // batch chunk (256 elems)

        __half* sW1h = (__half*)(smbuf);            // [d][j] 16x64
        __half* sW2t = (__half*)(smbuf + 2048);     // [k][j] 64x64 (transposed)
        __half* sW3h = (__half*)(smbuf + 10240);    // [k][2] 64x2
        __half* sb1h = (__half*)(smbuf + 10496);    // 64
        __half* sb2h = (__half*)(smbuf + 10624);    // 64
        float*  sb3v = (float*)(smbuf + 10752);     // 2
        float*  red  = (float*)(smbuf + 10784);     // 256

        for (int t = tid; t < DIMZ * HDIM; t += 256)
            sW1h[t] = __float2half_rn(W1[i * DIMZ * HDIM + t]);
        for (int t = tid; t < HDIM * HDIM; t += 256)   // W2[j][k] -> sW2t[k][j]
            sW2t[(t & 63) * 64 + (t >> 6)] = __float2half_rn(W2[i * HDIM * HDIM + t]);
        if (tid < HDIM * 2) sW3h[tid] = __float2half_rn(W3[i * HDIM * 2 + tid]);
        if (tid < HDIM) {
            sb1h[tid] = __float2half_rn(b1[i * HDIM + tid]);
            sb2h[tid] = __float2half_rn(b2[i * HDIM + tid]);
        }
        if (tid < 2) sb3v[tid] = b3[i * 2 + tid];
        __syncthreads();

        const int b = bx * 256 + tid;   // one batch element per thread

        __half ctxh[DIMZ];
        float e1i = 0.0f;
#pragma unroll
        for (int d = 0; d < DIMZ; d++) {
            float v = e1[(size_t)b * DIMZ + d];
            if (d == i) { e1i = v; v = 0.0f; }
            ctxh[d] = __float2half_rn(v);
        }

        const __half2 z2 = __float2half2_rn(0.0f);
        __half2 h1p[HDIM / 2];          // 32 half2 regs
#pragma unroll 8
        for (int j2 = 0; j2 < HDIM / 2; j2++) {
            __half2 a = *(__half2*)&sb1h[2 * j2];
#pragma unroll
            for (int d = 0; d < DIMZ; d++)
                a = __hfma2(__half2half2(ctxh[d]), *(__half2*)&sW1h[d * HDIM + 2 * j2], a);
            h1p[j2] = __hmax2(a, z2);
        }

        __half2 p = __floats2half2_rn(sb3v[0], sb3v[1]);   // (p0, p1)
        const __half zh = __float2half_rn(0.0f);
#pragma unroll 4
        for (int k = 0; k < HDIM; k++) {
            __half2 acc = z2;
#pragma unroll
            for (int j2 = 0; j2 < HDIM / 2; j2++)
                acc = __hfma2(h1p[j2], *(__half2*)&sW2t[k * HDIM + 2 * j2], acc);
            __half t = __hadd(__hadd(__low2half(acc), __high2half(acc)), sb2h[k]);
            t = __hmax(t, zh);
            p = __hfma2(__half2half2(t), *(__half2*)&sW3h[2 * k], p);
        }

        float shift = __low2float(p);
        float pv1   = __high2float(p);
        float sp = fmaxf(pv1, 0.0f) + log1pf(expf(-fabsf(pv1)));
        float scale = sp + MIN_STD;
        float z = (e2[(size_t)b * DIMZ + i] - shift) / scale;
        z = clean_clamp(z);
        float mask = interv[(size_t)b * (DIMZ + 1) + 1 + i];
        float lp2 = (-0.5f * z * z - 0.5f * LOG2PI - logf(scale)) * mask;
        float lp1 = clean_clamp(-0.5f * e1i * e1i - 0.5f * LOG2PI);

        red[tid] = lp1 + lp2;
        __syncthreads();
#pragma unroll
        for (int st = 128; st > 0; st >>= 1) {
            if (tid < st) red[tid] += red[tid + st];
            __syncthreads();
        }
        if (tid == 0) g_partial[i * 32 + bx] = red[0];

    } else if (bid < PR_TS3) {
        // ---------------- dec1: 8 rows of H1 = relu(E@Wd1+bd1) ----------
        const int db = bid - PR_DEC1;
        if (db < 128 && tid == 0) g_ready[db] = 0;

        const int rb = db * 8;
        float* se = (float*)smbuf;   // [8][16]
        if (tid < 128) {
            int r = tid >> 4, d = tid & 15;
            int row = rb + r;
            se[tid] = (row < B_HALF) ? e1[(size_t)row * DIMZ + d]
                                     : e2[(size_t)(row - B_HALF) * DIMZ + d];
        }
        __syncthreads();

        const int c0 = tid * 4;
        float4 bv = *(const float4*)&bd1[c0];
        float acc[8][4];
#pragma unroll
        for (int r = 0; r < 8; r++) {
            acc[r][0] = bv.x; acc[r][1] = bv.y; acc[r][2] = bv.z; acc[r][3] = bv.w;
        }
#pragma unroll
        for (int d = 0; d < DIMZ; d++) {
            float4 w = *(const float4*)&Wd1[d * DECH + c0];
#pragma unroll
            for (int r = 0; r < 8; r++) {
                float ed = se[r * 16 + d];
                acc[r][0] = fmaf(ed, w.x, acc[r][0]);
                acc[r][1] = fmaf(ed, w.y, acc[r][1]);
                acc[r][2] = fmaf(ed, w.z, acc[r][2]);
                acc[r][3] = fmaf(ed, w.w, acc[r][3]);
            }
        }
#pragma unroll
        for (int r = 0; r < 8; r++) {
            __half2 ha, hb;
            ha.x = __float2half_rn(fmaxf(acc[r][0], 0.0f));
            ha.y = __float2half_rn(fmaxf(acc[r][1], 0.0f));
            hb.x = __float2half_rn(fmaxf(acc[r][2], 0.0f));
            hb.y = __float2half_rn(fmaxf(acc[r][3], 0.0f));
            __half* dst = g_h1 + (size_t)(rb + r) * DECH + c0;
            *(__half2*)(dst)     = ha;
            *(__half2*)(dst + 2) = hb;
        }
    } else if (bid < PR_TS2) {
        do_tsplit(Wd3, g_w3, DECH, DIMX, bid - PR_TS3, DIMX / 32,
                  (float*)smbuf, tid);
    } else {
        do_tsplit(Wd2, g_w2, DECH, DECH, bid - PR_TS2, DECH / 32,
                  (float*)smbuf, tid);
    }
}

// ============================================================================
// fp16 HMMA GEMM core (UNCHANGED)
// ============================================================================
#define BK       64
#define NCHUNK  (KTOT / BK)       // 16
#define NT       256
#define A_OFF   0
#define B_OFF   16384             // A: 128 rows x 128B
#define STG_BYTES 49152           // A 16K + B 32K
#define NSTG    4
#define SMEM_DYN (NSTG * STG_BYTES + 1024)

__device__ __forceinline__ uint32_t sw128(uint32_t byte) {
    return byte ^ ((byte >> 3) & 0x70);
}

__device__ __forceinline__ void load_stage(
    uint32_t stg,
    const __half* __restrict__ A, const __half* __restrict__ B,
    int m0, int n0, int kBase, int tid)
{
    const int c16 = tid & 7;
    const int rg  = tid >> 3;
    const int kOff = kBase + c16 * 8;
#pragma unroll
    for (int j = 0; j < 4; j++) {
        int row = rg + j * 32;
        uint32_t sw = sw128((uint32_t)row * 128 + c16 * 16);
        CP_ASYNC16(stg + A_OFF + sw, A + (size_t)(m0 + row) * KTOT + kOff);
    }
#pragma unroll
    for (int j = 0; j < 8; j++) {
        int row = rg + j * 32;
        uint32_t sw = sw128((uint32_t)row * 128 + c16 * 16);
        CP_ASYNC16(stg + B_OFF + sw, B + (size_t)(n0 + row) * KTOT + kOff);
    }
}

template <int EPI>
__device__ __forceinline__ void run_gemm(
    const __half* __restrict__ A, const __half* __restrict__ B,
    const float* __restrict__ bias,
    float* __restrict__ Cf, __half* __restrict__ Ch,
    int Ntot, int m0, int n0, uint32_t sbase, int tid)
{
    const int warp = tid >> 5;
    const int lane = tid & 31;
    const int wm   = warp & 1;
    const int wn   = warp >> 1;

    const int lrow = lane & 7;
    const int quad = lane >> 3;
    const int aRow = wm * 64 + (quad & 1) * 8 + lrow;
    const int aKb  = (quad >> 1) * 16;
    const int bRow = wn * 64 + (quad >> 1) * 8 + lrow;
    const int bKb  = (quad & 1) * 16;

    // sw128(row*128 + o) == sw128(row*128) ^ o  for o < 128
    uint32_t aSw[4], bSw[4];
#pragma unroll
    for (int i = 0; i < 4; i++)
        aSw[i] = sw128((uint32_t)(aRow + i * 16) * 128);
#pragma unroll
    for (int g = 0; g < 4; g++)
        bSw[g] = sw128((uint32_t)(bRow + g * 16) * 128);

    float acc[4][8][4];
#pragma unroll
    for (int i = 0; i < 4; i++)
#pragma unroll
        for (int j = 0; j < 8; j++)
#pragma unroll
            for (int q = 0; q < 4; q++) acc[i][j][q] = 0.0f;

    load_stage(sbase,                 A, B, m0, n0, 0,      tid); CP_COMMIT();
    load_stage(sbase + STG_BYTES,     A, B, m0, n0, BK,     tid); CP_COMMIT();
    load_stage(sbase + 2 * STG_BYTES, A, B, m0, n0, 2 * BK, tid); CP_COMMIT();

#pragma unroll 1
    for (int c = 0; c < NCHUNK; c++) {
        if (c < NCHUNK - 2)       { CP_WAIT2(); }
        else if (c == NCHUNK - 2) { CP_WAIT1(); }
        else                      { CP_WAIT0(); }
        __syncthreads();
        if (c + 3 < NCHUNK) {
            load_stage(sbase + ((c + 3) & 3) * STG_BYTES,
                       A, B, m0, n0, (c + 3) * BK, tid);
            CP_COMMIT();
        }
        const uint32_t stg = sbase + (c & 3) * STG_BYTES;

#pragma unroll
        for (int kk = 0; kk < 4; kk++) {
            uint32_t a_r[4][4], b_r[4][4];
            const uint32_t ko = (uint32_t)(kk * 32);
#pragma unroll
            for (int i = 0; i < 4; i++)
                ldsm_x4(a_r[i], stg + A_OFF + (aSw[i] ^ (ko + aKb)));
#pragma unroll
            for (int g = 0; g < 4; g++)
                ldsm_x4(b_r[g], stg + B_OFF + (bSw[g] ^ (ko + bKb)));
#pragma unroll
            for (int i = 0; i < 4; i++)
#pragma unroll
                for (int j = 0; j < 8; j++)
                    mma_f16(acc[i][j], a_r[i], &b_r[j >> 1][(j & 1) * 2]);
        }
    }

    const int er = lane >> 2;
    const int ec = (lane & 3) * 2;
    float bv[8][2];
#pragma unroll
    for (int j = 0; j < 8; j++) {
        int n = n0 + wn * 64 + j * 8 + ec;
        bv[j][0] = bias[n]; bv[j][1] = bias[n + 1];
    }
#pragma unroll
    for (int i = 0; i < 4; i++) {
        int mrow = m0 + wm * 64 + i * 16 + er;
#pragma unroll
        for (int j = 0; j < 8; j++) {
            int n = n0 + wn * 64 + j * 8 + ec;
            float v0 = acc[i][j][0] + bv[j][0], v1 = acc[i][j][1] + bv[j][1];
            float v2 = acc[i][j][2] + bv[j][0], v3 = acc[i][j][3] + bv[j][1];
            size_t g0 = (size_t)mrow * Ntot + n;
            size_t g1 = (size_t)(mrow + 8) * Ntot + n;
            if (EPI == 0) {
                *(float2*)(Cf + g0) = make_float2(v0, v1);
                *(float2*)(Cf + g1) = make_float2(v2, v3);
            } else {
                __half2 p;
                p.x = __float2half_rn(fmaxf(v0, 0.0f));
                p.y = __float2half_rn(fmaxf(v1, 0.0f));
                *(__half2*)(Ch + g0) = p;
                p.x = __float2half_rn(fmaxf(v2, 0.0f));
                p.y = __float2half_rn(fmaxf(v3, 0.0f));
                *(__half2*)(Ch + g1) = p;
            }
        }
    }
}

// ============================================================================
// Fused gemm2 + gemm3 + log_p finalize (reduce widened to 512 partials)
// ============================================================================
__global__ __launch_bounds__(256, 1)
void gemm_fused(const float* __restrict__ bd2, const float* __restrict__ bd3,
                float* __restrict__ out, float* __restrict__ out_scalar)
{
    extern __shared__ char dsm[];
    const uint32_t sbase = (smem_u32(dsm) + 1023) & ~1023u;
    const int tid = threadIdx.x;
    const int bid = blockIdx.x;

    if (bid < G2_CTAS) {
        const int mi = bid >> 2, ni = bid & 3;
        run_gemm<1>(g_h1, g_w2, bd2, nullptr, g_h2, DECH,
                    mi * 128, ni * NT, sbase, tid);
        __threadfence();
        __syncthreads();
        if (tid == 0) red_release_add1(&g_ready[mi]);
    } else if (bid < G2_CTAS + G3_CTAS) {
        const int b2 = bid - G2_CTAS;
        const int mi = b2 / 12, nj = b2 % 12;
        if (tid == 0) {
            while (ld_acq(&g_ready[mi]) < 4) __nanosleep(128);
        }
        __syncthreads();
        run_gemm<0>(g_h2, g_w3, bd3, out, nullptr, DIMX,
                    mi * 128, nj * NT, sbase, tid);
    } else {
        __shared__ float red2[256];
        red2[tid] = g_partial[tid] + g_partial[tid + 256];
        __syncthreads();
#pragma unroll
        for (int st = 128; st > 0; st >>= 1) {
            if (tid < st) red2[tid] += red2[tid + st];
            __syncthreads();
        }
        if (tid == 0) {
            float log_p_I = -logf((float)(DIMZ + 1)) * (float)B_HALF;
            *out_scalar = red2[0] + log_p_I;
        }
    }
}

// ============================================================================
extern "C" void kernel_launch(void* const* d_in, const int* in_sizes, int n_in,
                              void* d_out, int out_size) {
    const float* e1  = (const float*)d_in[0];
    const float* e2  = (const float*)d_in[1];
    const float* itv = (const float*)d_in[2];
    const float* W1  = (const float*)d_in[3];
    const float* b1  = (const float*)d_in[4];
    const float* W2  = (const float*)d_in[5];
    const float* b2  = (const float*)d_in[6];
    const float* W3  = (const float*)d_in[7];
    const float* b3  = (const float*)d_in[8];
    const float* Wd1 = (const float*)d_in[9];
    const float* bd1 = (const float*)d_in[10];
    const float* Wd2 = (const float*)d_in[11];
    const float* bd2 = (const float*)d_in[12];
    const float* Wd3 = (const float*)d_in[13];
    const float* bd3 = (const float*)d_in[14];
    float* out = (float*)d_out;

    cudaFuncSetAttribute(gemm_fused, cudaFuncAttributeMaxDynamicSharedMemorySize, SMEM_DYN);

    // one prep kernel, homogeneous register footprint, 3 CTAs/SM
    prep_kernel<<<PR_TOTAL, 256>>>(e1, e2, itv, W1, b1, W2, b2, W3, b3,
                                   Wd1, bd1, Wd2, Wd3);

    // fused gemm2 + gemm3 + log_p finalize
    gemm_fused<<<G2_CTAS + G3_CTAS + 1, 256, SMEM_DYN>>>(
        bd2, bd3, out, out + ((size_t)out_size - 1));
}

// round 11
// speedup vs baseline: 7.3597x; 1.0103x over previous
#include <cuda_runtime.h>
#include <cuda_fp16.h>
#include <math.h>
#include <stdint.h>

// ============================================================================
// ILCMDecoder on GB300 (baseline-PTX tensor path: mma.sync HMMA fp16 +
// ldmatrix + cp.async; tcgen05 rejected by this harness's ptxas target).
//
// Round 11: gemm_fused at 512 threads/CTA (16 warps, warp tile 64x32,
// CTA tile 128x256) -> 4 warps/SMSP to hide LDSM->MMA latency.
// Same k-accumulation order -> outputs bit-identical to Round 10.
// ============================================================================

#define B_TOT   16384
#define B_HALF  8192
#define DIMZ    16
#define HDIM    64
#define DECH    1024
#define DIMX    3072
#define KTOT    1024
#define LOG2PI  1.8378770664093453f
#define MIN_STD 0.2f
#define CLAMP_V 1000000.0f

#define G2_CTAS 512            // gemm2: 128 m-tiles x 4 n-tiles
#define G3_CTAS 1536           // gemm3: 128 m-tiles x 12 n-tiles

// prep roles (one kernel): flow | dec1 | ts3 | ts2
#define PR_FLOW   0
#define N_FLOW    512           // 16 dims x 32 chunks (256 batch each)
#define PR_DEC1   (PR_FLOW + N_FLOW)
#define N_DEC1    2048          // 8 rows per block
#define PR_TS3    (PR_DEC1 + N_DEC1)
#define N_TS3     3072
#define PR_TS2    (PR_TS3 + N_TS3)
#define N_TS2     1024
#define PR_TOTAL  (PR_TS2 + N_TS2)

// ---------------- device scratch (allocation-free) ----------------
__device__ __half g_h1[(size_t)B_TOT * DECH];
__device__ __half g_h2[(size_t)B_TOT * DECH];
__device__ __half g_w2[(size_t)DECH * DECH];   // Wd2^T fp16 [N,K]
__device__ __half g_w3[(size_t)DIMX * DECH];   // Wd3^T fp16 [N,K]
__device__ float g_partial[512];
__device__ int   g_ready[128];                 // per-m-block h2 readiness (0..4)

// ---------------- PTX helpers (baseline family features only) --------------
__device__ __forceinline__ uint32_t smem_u32(const void* p) {
    uint32_t a;
    asm("{ .reg .u64 t; cvta.to.shared.u64 t, %1; cvt.u32.u64 %0, t; }"
        : "=r"(a) : "l"(p));
    return a;
}

#define CP_ASYNC16(smem, gptr) \
    asm volatile("cp.async.cg.shared.global [%0], [%1], 16;" \
        :: "r"((uint32_t)(smem)), "l"(gptr) : "memory")
#define CP_COMMIT() asm volatile("cp.async.commit_group;" ::: "memory")
#define CP_WAIT2()  asm volatile("cp.async.wait_group 2;" ::: "memory")
#define CP_WAIT1()  asm volatile("cp.async.wait_group 1;" ::: "memory")
#define CP_WAIT0()  asm volatile("cp.async.wait_group 0;" ::: "memory")

__device__ __forceinline__ void ldsm_x4(uint32_t* r, uint32_t addr) {
    asm volatile("ldmatrix.sync.aligned.m8n8.x4.shared.b16 {%0,%1,%2,%3}, [%4];"
        : "=r"(r[0]), "=r"(r[1]), "=r"(r[2]), "=r"(r[3]) : "r"(addr));
}

__device__ __forceinline__ void mma_f16(float* d, const uint32_t* a, const uint32_t* b) {
    asm volatile(
        "mma.sync.aligned.m16n8k16.row.col.f32.f16.f16.f32 "
        "{%0,%1,%2,%3}, {%4,%5,%6,%7}, {%8,%9}, {%0,%1,%2,%3};"
        : "+f"(d[0]), "+f"(d[1]), "+f"(d[2]), "+f"(d[3])
        : "r"(a[0]), "r"(a[1]), "r"(a[2]), "r"(a[3]), "r"(b[0]), "r"(b[1]));
}

__device__ __forceinline__ int ld_acq(const int* p) {
    int v;
    asm volatile("ld.acquire.gpu.s32 %0, [%1];" : "=r"(v) : "l"(p) : "memory");
    return v;
}
__device__ __forceinline__ void red_release_add1(int* p) {
    asm volatile("red.release.gpu.global.add.s32 [%0], %1;" :: "l"(p), "r"(1) : "memory");
}

__device__ __forceinline__ float clean_clamp(float x) {
    if (isnan(x)) x = 0.0f;
    return fminf(fmaxf(x, -CLAMP_V), CLAMP_V);
}

// ============================================================================
// prep kernel (UNCHANGED from Round 10)
// ============================================================================
__device__ __forceinline__ void do_tsplit(const float* __restrict__ W,
                                          __half* __restrict__ T,
                                          int K, int N, int t, int ntx,
                                          float* tile, int tid) {
    int nb = (t % ntx) * 32, kb = (t / ntx) * 32;
    int tx = tid & 31, ty0 = tid >> 5;
    for (int i2 = ty0; i2 < 32; i2 += 8)
        tile[i2 * 33 + tx] = W[(size_t)(kb + i2) * N + nb + tx];
    __syncthreads();
    for (int i2 = ty0; i2 < 32; i2 += 8)
        T[(size_t)(nb + i2) * K + kb + tx] = __float2half_rn(tile[tx * 33 + i2]);
}

__global__ __launch_bounds__(256, 3)
void prep_kernel(const float* __restrict__ e1, const float* __restrict__ e2,
                 const float* __restrict__ interv,
                 const float* __restrict__ W1, const float* __restrict__ b1,
                 const float* __restrict__ W2, const float* __restrict__ b2,
                 const float* __restrict__ W3, const float* __restrict__ b3,
                 const float* __restrict__ Wd1, const float* __restrict__ bd1,
                 const float* __restrict__ Wd2, const float* __restrict__ Wd3)
{
    __shared__ __align__(16) char smbuf[12288];
    const int bid = blockIdx.x;
    const int tid = threadIdx.x;

    if (bid < PR_DEC1) {
        // ---------------- FLOW: half2 packed over hidden dim j ----------
        const int i  = bid >> 5;
        const int bx = bid & 31;

        __half* sW1h = (__half*)(smbuf);
        __half* sW2t = (__half*)(smbuf + 2048);
        __half* sW3h = (__half*)(smbuf + 10240);
        __half* sb1h = (__half*)(smbuf + 10496);
        __half* sb2h = (__half*)(smbuf + 10624);
        float*  sb3v = (float*)(smbuf + 10752);
        float*  red  = (float*)(smbuf + 10784);

        for (int t = tid; t < DIMZ * HDIM; t += 256)
            sW1h[t] = __float2half_rn(W1[i * DIMZ * HDIM + t]);
        for (int t = tid; t < HDIM * HDIM; t += 256)
            sW2t[(t & 63) * 64 + (t >> 6)] = __float2half_rn(W2[i * HDIM * HDIM + t]);
        if (tid < HDIM * 2) sW3h[tid] = __float2half_rn(W3[i * HDIM * 2 + tid]);
        if (tid < HDIM) {
            sb1h[tid] = __float2half_rn(b1[i * HDIM + tid]);
            sb2h[tid] = __float2half_rn(b2[i * HDIM + tid]);
        }
        if (tid < 2) sb3v[tid] = b3[i * 2 + tid];
        __syncthreads();

        const int b = bx * 256 + tid;

        __half ctxh[DIMZ];
        float e1i = 0.0f;
#pragma unroll
        for (int d = 0; d < DIMZ; d++) {
            float v = e1[(size_t)b * DIMZ + d];
            if (d == i) { e1i = v; v = 0.0f; }
            ctxh[d] = __float2half_rn(v);
        }

        const __half2 z2 = __float2half2_rn(0.0f);
        __half2 h1p[HDIM / 2];
#pragma unroll 8
        for (int j2 = 0; j2 < HDIM / 2; j2++) {
            __half2 a = *(__half2*)&sb1h[2 * j2];
#pragma unroll
            for (int d = 0; d < DIMZ; d++)
                a = __hfma2(__half2half2(ctxh[d]), *(__half2*)&sW1h[d * HDIM + 2 * j2], a);
            h1p[j2] = __hmax2(a, z2);
        }

        __half2 p = __floats2half2_rn(sb3v[0], sb3v[1]);
        const __half zh = __float2half_rn(0.0f);
#pragma unroll 4
        for (int k = 0; k < HDIM; k++) {
            __half2 acc = z2;
#pragma unroll
            for (int j2 = 0; j2 < HDIM / 2; j2++)
                acc = __hfma2(h1p[j2], *(__half2*)&sW2t[k * HDIM + 2 * j2], acc);
            __half t = __hadd(__hadd(__low2half(acc), __high2half(acc)), sb2h[k]);
            t = __hmax(t, zh);
            p = __hfma2(__half2half2(t), *(__half2*)&sW3h[2 * k], p);
        }

        float shift = __low2float(p);
        float pv1   = __high2float(p);
        float sp = fmaxf(pv1, 0.0f) + log1pf(expf(-fabsf(pv1)));
        float scale = sp + MIN_STD;
        float z = (e2[(size_t)b * DIMZ + i] - shift) / scale;
        z = clean_clamp(z);
        float mask = interv[(size_t)b * (DIMZ + 1) + 1 + i];
        float lp2 = (-0.5f * z * z - 0.5f * LOG2PI - logf(scale)) * mask;
        float lp1 = clean_clamp(-0.5f * e1i * e1i - 0.5f * LOG2PI);

        red[tid] = lp1 + lp2;
        __syncthreads();
#pragma unroll
        for (int st = 128; st > 0; st >>= 1) {
            if (tid < st) red[tid] += red[tid + st];
            __syncthreads();
        }
        if (tid == 0) g_partial[i * 32 + bx] = red[0];

    } else if (bid < PR_TS3) {
        const int db = bid - PR_DEC1;
        if (db < 128 && tid == 0) g_ready[db] = 0;

        const int rb = db * 8;
        float* se = (float*)smbuf;
        if (tid < 128) {
            int r = tid >> 4, d = tid & 15;
            int row = rb + r;
            se[tid] = (row < B_HALF) ? e1[(size_t)row * DIMZ + d]
                                     : e2[(size_t)(row - B_HALF) * DIMZ + d];
        }
        __syncthreads();

        const int c0 = tid * 4;
        float4 bv = *(const float4*)&bd1[c0];
        float acc[8][4];
#pragma unroll
        for (int r = 0; r < 8; r++) {
            acc[r][0] = bv.x; acc[r][1] = bv.y; acc[r][2] = bv.z; acc[r][3] = bv.w;
        }
#pragma unroll
        for (int d = 0; d < DIMZ; d++) {
            float4 w = *(const float4*)&Wd1[d * DECH + c0];
#pragma unroll
            for (int r = 0; r < 8; r++) {
                float ed = se[r * 16 + d];
                acc[r][0] = fmaf(ed, w.x, acc[r][0]);
                acc[r][1] = fmaf(ed, w.y, acc[r][1]);
                acc[r][2] = fmaf(ed, w.z, acc[r][2]);
                acc[r][3] = fmaf(ed, w.w, acc[r][3]);
            }
        }
#pragma unroll
        for (int r = 0; r < 8; r++) {
            __half2 ha, hb;
            ha.x = __float2half_rn(fmaxf(acc[r][0], 0.0f));
            ha.y = __float2half_rn(fmaxf(acc[r][1], 0.0f));
            hb.x = __float2half_rn(fmaxf(acc[r][2], 0.0f));
            hb.y = __float2half_rn(fmaxf(acc[r][3], 0.0f));
            __half* dst = g_h1 + (size_t)(rb + r) * DECH + c0;
            *(__half2*)(dst)     = ha;
            *(__half2*)(dst + 2) = hb;
        }
    } else if (bid < PR_TS2) {
        do_tsplit(Wd3, g_w3, DECH, DIMX, bid - PR_TS3, DIMX / 32,
                  (float*)smbuf, tid);
    } else {
        do_tsplit(Wd2, g_w2, DECH, DECH, bid - PR_TS2, DECH / 32,
                  (float*)smbuf, tid);
    }
}

// ============================================================================
// fp16 HMMA GEMM core: 512 threads, 16 warps, warp tile 64x32 (2x8 grid),
// CTA tile 128x256, BK=64, 4-stage cp.async pipeline.
// ============================================================================
#define BK       64
#define NCHUNK  (KTOT / BK)       // 16
#define NT       256
#define A_OFF   0
#define B_OFF   16384             // A: 128 rows x 128B
#define STG_BYTES 49152           // A 16K + B 32K
#define NSTG    4
#define SMEM_DYN (NSTG * STG_BYTES + 1024)
#define GTHREADS 512

__device__ __forceinline__ uint32_t sw128(uint32_t byte) {
    return byte ^ ((byte >> 3) & 0x70);
}

// 512 threads: load one 128(M)x64 + 256(N)x64 fp16 chunk into a stage.
__device__ __forceinline__ void load_stage(
    uint32_t stg,
    const __half* __restrict__ A, const __half* __restrict__ B,
    int m0, int n0, int kBase, int tid)
{
    const int c16 = tid & 7;        // 16B column within 128B row
    const int rg  = tid >> 3;       // 0..63
    const int kOff = kBase + c16 * 8;
#pragma unroll
    for (int j = 0; j < 2; j++) {
        int row = rg + j * 64;
        uint32_t sw = sw128((uint32_t)row * 128 + c16 * 16);
        CP_ASYNC16(stg + A_OFF + sw, A + (size_t)(m0 + row) * KTOT + kOff);
    }
#pragma unroll
    for (int j = 0; j < 4; j++) {
        int row = rg + j * 64;
        uint32_t sw = sw128((uint32_t)row * 128 + c16 * 16);
        CP_ASYNC16(stg + B_OFF + sw, B + (size_t)(n0 + row) * KTOT + kOff);
    }
}

template <int EPI>
__device__ __forceinline__ void run_gemm(
    const __half* __restrict__ A, const __half* __restrict__ B,
    const float* __restrict__ bias,
    float* __restrict__ Cf, __half* __restrict__ Ch,
    int Ntot, int m0, int n0, uint32_t sbase, int tid)
{
    const int warp = tid >> 5;          // 0..15
    const int lane = tid & 31;
    const int wm   = warp & 1;          // 2 M-slices of 64
    const int wn   = warp >> 1;         // 8 N-slices of 32

    const int lrow = lane & 7;
    const int quad = lane >> 3;
    const int aRow = wm * 64 + (quad & 1) * 8 + lrow;
    const int aKb  = (quad >> 1) * 16;
    const int bRow = wn * 32 + (quad >> 1) * 8 + lrow;
    const int bKb  = (quad & 1) * 16;

    // sw128(row*128 + o) == sw128(row*128) ^ o  for o < 128
    uint32_t aSw[4], bSw[2];
#pragma unroll
    for (int i = 0; i < 4; i++)
        aSw[i] = sw128((uint32_t)(aRow + i * 16) * 128);
#pragma unroll
    for (int g = 0; g < 2; g++)
        bSw[g] = sw128((uint32_t)(bRow + g * 16) * 128);

    float acc[4][4][4];
#pragma unroll
    for (int i = 0; i < 4; i++)
#pragma unroll
        for (int j = 0; j < 4; j++)
#pragma unroll
            for (int q = 0; q < 4; q++) acc[i][j][q] = 0.0f;

    load_stage(sbase,                 A, B, m0, n0, 0,      tid); CP_COMMIT();
    load_stage(sbase + STG_BYTES,     A, B, m0, n0, BK,     tid); CP_COMMIT();
    load_stage(sbase + 2 * STG_BYTES, A, B, m0, n0, 2 * BK, tid); CP_COMMIT();

#pragma unroll 1
    for (int c = 0; c < NCHUNK; c++) {
        if (c < NCHUNK - 2)       { CP_WAIT2(); }
        else if (c == NCHUNK - 2) { CP_WAIT1(); }
        else                      { CP_WAIT0(); }
        __syncthreads();
        if (c + 3 < NCHUNK) {
            load_stage(sbase + ((c + 3) & 3) * STG_BYTES,
                       A, B, m0, n0, (c + 3) * BK, tid);
            CP_COMMIT();
        }
        const uint32_t stg = sbase + (c & 3) * STG_BYTES;

#pragma unroll
        for (int kk = 0; kk < 4; kk++) {
            uint32_t a_r[4][4], b_r[2][4];
            const uint32_t ko = (uint32_t)(kk * 32);
#pragma unroll
            for (int i = 0; i < 4; i++)
                ldsm_x4(a_r[i], stg + A_OFF + (aSw[i] ^ (ko + aKb)));
#pragma unroll
            for (int g = 0; g < 2; g++)
                ldsm_x4(b_r[g], stg + B_OFF + (bSw[g] ^ (ko + bKb)));
#pragma unroll
            for (int i = 0; i < 4; i++)
#pragma unroll
                for (int j = 0; j < 4; j++)
                    mma_f16(acc[i][j], a_r[i], &b_r[j >> 1][(j & 1) * 2]);
        }
    }

    const int er = lane >> 2;
    const int ec = (lane & 3) * 2;
#pragma unroll
    for (int i = 0; i < 4; i++) {
        int mrow = m0 + wm * 64 + i * 16 + er;
#pragma unroll
        for (int j = 0; j < 4; j++) {
            int n = n0 + wn * 32 + j * 8 + ec;
            float b0 = bias[n], b1 = bias[n + 1];
            float v0 = acc[i][j][0] + b0, v1 = acc[i][j][1] + b1;
            float v2 = acc[i][j][2] + b0, v3 = acc[i][j][3] + b1;
            size_t g0 = (size_t)mrow * Ntot + n;
            size_t g1 = (size_t)(mrow + 8) * Ntot + n;
            if (EPI == 0) {
                *(float2*)(Cf + g0) = make_float2(v0, v1);
                *(float2*)(Cf + g1) = make_float2(v2, v3);
            } else {
                __half2 p;
                p.x = __float2half_rn(fmaxf(v0, 0.0f));
                p.y = __float2half_rn(fmaxf(v1, 0.0f));
                *(__half2*)(Ch + g0) = p;
                p.x = __float2half_rn(fmaxf(v2, 0.0f));
                p.y = __float2half_rn(fmaxf(v3, 0.0f));
                *(__half2*)(Ch + g1) = p;
            }
        }
    }
}

// ============================================================================
// Fused gemm2 + gemm3 + log_p finalize (512 threads)
// ============================================================================
__global__ __launch_bounds__(GTHREADS, 1)
void gemm_fused(const float* __restrict__ bd2, const float* __restrict__ bd3,
                float* __restrict__ out, float* __restrict__ out_scalar)
{
    extern __shared__ char dsm[];
    const uint32_t sbase = (smem_u32(dsm) + 1023) & ~1023u;
    const int tid = threadIdx.x;
    const int bid = blockIdx.x;

    if (bid < G2_CTAS) {
        const int mi = bid >> 2, ni = bid & 3;
        run_gemm<1>(g_h1, g_w2, bd2, nullptr, g_h2, DECH,
                    mi * 128, ni * NT, sbase, tid);
        __threadfence();
        __syncthreads();
        if (tid == 0) red_release_add1(&g_ready[mi]);
    } else if (bid < G2_CTAS + G3_CTAS) {
        const int b2 = bid - G2_CTAS;
        const int mi = b2 / 12, nj = b2 % 12;
        if (tid == 0) {
            while (ld_acq(&g_ready[mi]) < 4) __nanosleep(128);
        }
        __syncthreads();
        run_gemm<0>(g_h2, g_w3, bd3, out, nullptr, DIMX,
                    mi * 128, nj * NT, sbase, tid);
    } else {
        __shared__ float red2[512];
        red2[tid] = g_partial[tid];
        __syncthreads();
#pragma unroll
        for (int st = 256; st > 0; st >>= 1) {
            if (tid < st) red2[tid] += red2[tid + st];
            __syncthreads();
        }
        if (tid == 0) {
            float log_p_I = -logf((float)(DIMZ + 1)) * (float)B_HALF;
            *out_scalar = red2[0] + log_p_I;
        }
    }
}

// ============================================================================
extern "C" void kernel_launch(void* const* d_in, const int* in_sizes, int n_in,
                              void* d_out, int out_size) {
    const float* e1  = (const float*)d_in[0];
    const float* e2  = (const float*)d_in[1];
    const float* itv = (const float*)d_in[2];
    const float* W1  = (const float*)d_in[3];
    const float* b1  = (const float*)d_in[4];
    const float* W2  = (const float*)d_in[5];
    const float* b2  = (const float*)d_in[6];
    const float* W3  = (const float*)d_in[7];
    const float* b3  = (const float*)d_in[8];
    const float* Wd1 = (const float*)d_in[9];
    const float* bd1 = (const float*)d_in[10];
    const float* Wd2 = (const float*)d_in[11];
    const float* bd2 = (const float*)d_in[12];
    const float* Wd3 = (const float*)d_in[13];
    const float* bd3 = (const float*)d_in[14];
    float* out = (float*)d_out;

    cudaFuncSetAttribute(gemm_fused, cudaFuncAttributeMaxDynamicSharedMemorySize, SMEM_DYN);

    // prep: flow + dec1 + transposes (concurrent roles)
    prep_kernel<<<PR_TOTAL, 256>>>(e1, e2, itv, W1, b1, W2, b2, W3, b3,
                                   Wd1, bd1, Wd2, Wd3);

    // fused gemm2 + gemm3 + log_p finalize
    gemm_fused<<<G2_CTAS + G3_CTAS + 1, GTHREADS, SMEM_DYN>>>(
        bd2, bd3, out, out + ((size_t)out_size - 1));
}

// round 12
// speedup vs baseline: 7.4360x; 1.0104x over previous
#include <cuda_runtime.h>
#include <cuda_fp16.h>
#include <math.h>
#include <stdint.h>

// ============================================================================
// ILCMDecoder on GB300 (baseline-PTX tensor path: mma.sync HMMA fp16 +
// ldmatrix + cp.async; tcgen05 rejected by this harness's ptxas target).
//
// Round 12: flow smem reads vectorized to LDS.128 (4x fewer crossbar cycles,
// ~40% fewer instructions), identical hfma2 order -> log_p bit-identical.
// gemm_fused unchanged (357us; co-saturated smem-crossbar + tensor pipe).
// ============================================================================

#define B_TOT   16384
#define B_HALF  8192
#define DIMZ    16
#define HDIM    64
#define DECH    1024
#define DIMX    3072
#define KTOT    1024
#define LOG2PI  1.8378770664093453f
#define MIN_STD 0.2f
#define CLAMP_V 1000000.0f

#define G2_CTAS 512            // gemm2: 128 m-tiles x 4 n-tiles
#define G3_CTAS 1536           // gemm3: 128 m-tiles x 12 n-tiles

// prep roles (one kernel): flow | dec1 | ts3 | ts2
#define PR_FLOW   0
#define N_FLOW    512           // 16 dims x 32 chunks (256 batch each)
#define PR_DEC1   (PR_FLOW + N_FLOW)
#define N_DEC1    2048          // 8 rows per block
#define PR_TS3    (PR_DEC1 + N_DEC1)
#define N_TS3     3072
#define PR_TS2    (PR_TS3 + N_TS3)
#define N_TS2     1024
#define PR_TOTAL  (PR_TS2 + N_TS2)

// ---------------- device scratch (allocation-free) ----------------
__device__ __half g_h1[(size_t)B_TOT * DECH];
__device__ __half g_h2[(size_t)B_TOT * DECH];
__device__ __half g_w2[(size_t)DECH * DECH];   // Wd2^T fp16 [N,K]
__device__ __half g_w3[(size_t)DIMX * DECH];   // Wd3^T fp16 [N,K]
__device__ float g_partial[512];
__device__ int   g_ready[128];                 // per-m-block h2 readiness (0..4)

// ---------------- PTX helpers (baseline family features only) --------------
__device__ __forceinline__ uint32_t smem_u32(const void* p) {
    uint32_t a;
    asm("{ .reg .u64 t; cvta.to.shared.u64 t, %1; cvt.u32.u64 %0, t; }"
        : "=r"(a) : "l"(p));
    return a;
}

#define CP_ASYNC16(smem, gptr) \
    asm volatile("cp.async.cg.shared.global [%0], [%1], 16;" \
        :: "r"((uint32_t)(smem)), "l"(gptr) : "memory")
#define CP_COMMIT() asm volatile("cp.async.commit_group;" ::: "memory")
#define CP_WAIT2()  asm volatile("cp.async.wait_group 2;" ::: "memory")
#define CP_WAIT1()  asm volatile("cp.async.wait_group 1;" ::: "memory")
#define CP_WAIT0()  asm volatile("cp.async.wait_group 0;" ::: "memory")

__device__ __forceinline__ void ldsm_x4(uint32_t* r, uint32_t addr) {
    asm volatile("ldmatrix.sync.aligned.m8n8.x4.shared.b16 {%0,%1,%2,%3}, [%4];"
        : "=r"(r[0]), "=r"(r[1]), "=r"(r[2]), "=r"(r[3]) : "r"(addr));
}

__device__ __forceinline__ void mma_f16(float* d, const uint32_t* a, const uint32_t* b) {
    asm volatile(
        "mma.sync.aligned.m16n8k16.row.col.f32.f16.f16.f32 "
        "{%0,%1,%2,%3}, {%4,%5,%6,%7}, {%8,%9}, {%0,%1,%2,%3};"
        : "+f"(d[0]), "+f"(d[1]), "+f"(d[2]), "+f"(d[3])
        : "r"(a[0]), "r"(a[1]), "r"(a[2]), "r"(a[3]), "r"(b[0]), "r"(b[1]));
}

__device__ __forceinline__ int ld_acq(const int* p) {
    int v;
    asm volatile("ld.acquire.gpu.s32 %0, [%1];" : "=r"(v) : "l"(p) : "memory");
    return v;
}
__device__ __forceinline__ void red_release_add1(int* p) {
    asm volatile("red.release.gpu.global.add.s32 [%0], %1;" :: "l"(p), "r"(1) : "memory");
}

__device__ __forceinline__ float clean_clamp(float x) {
    if (isnan(x)) x = 0.0f;
    return fminf(fmaxf(x, -CLAMP_V), CLAMP_V);
}

__device__ __forceinline__ __half2 u2h2(uint32_t u) {
    __half2 h; *(uint32_t*)&h = u; return h;
}

// ============================================================================
// prep kernel: flow (512) | dec1 (2048) | ts3 (3072) | ts2 (1024)
// ============================================================================
__device__ __forceinline__ void do_tsplit(const float* __restrict__ W,
                                          __half* __restrict__ T,
                                          int K, int N, int t, int ntx,
                                          float* tile, int tid) {
    int nb = (t % ntx) * 32, kb = (t / ntx) * 32;
    int tx = tid & 31, ty0 = tid >> 5;
    for (int i2 = ty0; i2 < 32; i2 += 8)
        tile[i2 * 33 + tx] = W[(size_t)(kb + i2) * N + nb + tx];
    __syncthreads();
    for (int i2 = ty0; i2 < 32; i2 += 8)
        T[(size_t)(nb + i2) * K + kb + tx] = __float2half_rn(tile[tx * 33 + i2]);
}

__global__ __launch_bounds__(256, 3)
void prep_kernel(const float* __restrict__ e1, const float* __restrict__ e2,
                 const float* __restrict__ interv,
                 const float* __restrict__ W1, const float* __restrict__ b1,
                 const float* __restrict__ W2, const float* __restrict__ b2,
                 const float* __restrict__ W3, const float* __restrict__ b3,
                 const float* __restrict__ Wd1, const float* __restrict__ bd1,
                 const float* __restrict__ Wd2, const float* __restrict__ Wd3)
{
    __shared__ __align__(16) char smbuf[12288];
    const int bid = blockIdx.x;
    const int tid = threadIdx.x;

    if (bid < PR_DEC1) {
        // ---------------- FLOW: half2 over hidden dim, LDS.128 reads ----
        const int i  = bid >> 5;     // dim 0..15
        const int bx = bid & 31;     // batch chunk (256 elems)

        __half* sW1h = (__half*)(smbuf);            // [d][j] 16x64 (16B-aligned rows)
        __half* sW2t = (__half*)(smbuf + 2048);     // [k][j] 64x64 (transposed)
        __half* sW3h = (__half*)(smbuf + 10240);    // [k][2] 64x2
        __half* sb1h = (__half*)(smbuf + 10496);    // 64
        __half* sb2h = (__half*)(smbuf + 10624);    // 64
        float*  sb3v = (float*)(smbuf + 10752);     // 2
        float*  red  = (float*)(smbuf + 10784);     // 256

        for (int t = tid; t < DIMZ * HDIM; t += 256)
            sW1h[t] = __float2half_rn(W1[i * DIMZ * HDIM + t]);
        for (int t = tid; t < HDIM * HDIM; t += 256)   // W2[j][k] -> sW2t[k][j]
            sW2t[(t & 63) * 64 + (t >> 6)] = __float2half_rn(W2[i * HDIM * HDIM + t]);
        if (tid < HDIM * 2) sW3h[tid] = __float2half_rn(W3[i * HDIM * 2 + tid]);
        if (tid < HDIM) {
            sb1h[tid] = __float2half_rn(b1[i * HDIM + tid]);
            sb2h[tid] = __float2half_rn(b2[i * HDIM + tid]);
        }
        if (tid < 2) sb3v[tid] = b3[i * 2 + tid];
        __syncthreads();

        const int b = bx * 256 + tid;   // one batch element per thread

        __half ctxh[DIMZ];
        float e1i = 0.0f;
#pragma unroll
        for (int d = 0; d < DIMZ; d++) {
            float v = e1[(size_t)b * DIMZ + d];
            if (d == i) { e1i = v; v = 0.0f; }
            ctxh[d] = __float2half_rn(v);
        }

        const __half2 z2 = __float2half2_rn(0.0f);
        // layer 1: groups of 4 j2 (8 halves) per LDS.128
        __half2 h1p[HDIM / 2];          // 32 half2 regs
#pragma unroll
        for (int jq = 0; jq < 8; jq++) {
            uint4 bq = *(const uint4*)&sb1h[8 * jq];
            __half2 a0 = u2h2(bq.x), a1 = u2h2(bq.y), a2 = u2h2(bq.z), a3 = u2h2(bq.w);
#pragma unroll
            for (int d = 0; d < DIMZ; d++) {
                __half2 cd = __half2half2(ctxh[d]);
                uint4 w = *(const uint4*)&sW1h[d * HDIM + 8 * jq];
                a0 = __hfma2(cd, u2h2(w.x), a0);
                a1 = __hfma2(cd, u2h2(w.y), a1);
                a2 = __hfma2(cd, u2h2(w.z), a2);
                a3 = __hfma2(cd, u2h2(w.w), a3);
            }
            h1p[4 * jq + 0] = __hmax2(a0, z2);
            h1p[4 * jq + 1] = __hmax2(a1, z2);
            h1p[4 * jq + 2] = __hmax2(a2, z2);
            h1p[4 * jq + 3] = __hmax2(a3, z2);
        }

        // layers 2+3: per k, accumulate over j2 with LDS.128 operand loads
        __half2 p = __floats2half2_rn(sb3v[0], sb3v[1]);   // (p0, p1)
        const __half zh = __float2half_rn(0.0f);
#pragma unroll 4
        for (int k = 0; k < HDIM; k++) {
            __half2 acc = z2;
#pragma unroll
            for (int q = 0; q < 8; q++) {
                uint4 w = *(const uint4*)&sW2t[k * HDIM + 8 * q];
                acc = __hfma2(h1p[4 * q + 0], u2h2(w.x), acc);
                acc = __hfma2(h1p[4 * q + 1], u2h2(w.y), acc);
                acc = __hfma2(h1p[4 * q + 2], u2h2(w.z), acc);
                acc = __hfma2(h1p[4 * q + 3], u2h2(w.w), acc);
            }
            __half t = __hadd(__hadd(__low2half(acc), __high2half(acc)), sb2h[k]);
            t = __hmax(t, zh);
            p = __hfma2(__half2half2(t), *(__half2*)&sW3h[2 * k], p);
        }

        float shift = __low2float(p);
        float pv1   = __high2float(p);
        float sp = fmaxf(pv1, 0.0f) + log1pf(expf(-fabsf(pv1)));
        float scale = sp + MIN_STD;
        float z = (e2[(size_t)b * DIMZ + i] - shift) / scale;
        z = clean_clamp(z);
        float mask = interv[(size_t)b * (DIMZ + 1) + 1 + i];
        float lp2 = (-0.5f * z * z - 0.5f * LOG2PI - logf(scale)) * mask;
        float lp1 = clean_clamp(-0.5f * e1i * e1i - 0.5f * LOG2PI);

        red[tid] = lp1 + lp2;
        __syncthreads();
#pragma unroll
        for (int st = 128; st > 0; st >>= 1) {
            if (tid < st) red[tid] += red[tid + st];
            __syncthreads();
        }
        if (tid == 0) g_partial[i * 32 + bx] = red[0];

    } else if (bid < PR_TS3) {
        // ---------------- dec1: 8 rows of H1 = relu(E@Wd1+bd1) ----------
        const int db = bid - PR_DEC1;
        if (db < 128 && tid == 0) g_ready[db] = 0;

        const int rb = db * 8;
        float* se = (float*)smbuf;
        if (tid < 128) {
            int r = tid >> 4, d = tid & 15;
            int row = rb + r;
            se[tid] = (row < B_HALF) ? e1[(size_t)row * DIMZ + d]
                                     : e2[(size_t)(row - B_HALF) * DIMZ + d];
        }
        __syncthreads();

        const int c0 = tid * 4;
        float4 bv = *(const float4*)&bd1[c0];
        float acc[8][4];
#pragma unroll
        for (int r = 0; r < 8; r++) {
            acc[r][0] = bv.x; acc[r][1] = bv.y; acc[r][2] = bv.z; acc[r][3] = bv.w;
        }
#pragma unroll
        for (int d = 0; d < DIMZ; d++) {
            float4 w = *(const float4*)&Wd1[d * DECH + c0];
#pragma unroll
            for (int r = 0; r < 8; r++) {
                float ed = se[r * 16 + d];
                acc[r][0] = fmaf(ed, w.x, acc[r][0]);
                acc[r][1] = fmaf(ed, w.y, acc[r][1]);
                acc[r][2] = fmaf(ed, w.z, acc[r][2]);
                acc[r][3] = fmaf(ed, w.w, acc[r][3]);
            }
        }
#pragma unroll
        for (int r = 0; r < 8; r++) {
            __half2 ha, hb;
            ha.x = __float2half_rn(fmaxf(acc[r][0], 0.0f));
            ha.y = __float2half_rn(fmaxf(acc[r][1], 0.0f));
            hb.x = __float2half_rn(fmaxf(acc[r][2], 0.0f));
            hb.y = __float2half_rn(fmaxf(acc[r][3], 0.0f));
            __half* dst = g_h1 + (size_t)(rb + r) * DECH + c0;
            *(__half2*)(dst)     = ha;
            *(__half2*)(dst + 2) = hb;
        }
    } else if (bid < PR_TS2) {
        do_tsplit(Wd3, g_w3, DECH, DIMX, bid - PR_TS3, DIMX / 32,
                  (float*)smbuf, tid);
    } else {
        do_tsplit(Wd2, g_w2, DECH, DECH, bid - PR_TS2, DECH / 32,
                  (float*)smbuf, tid);
    }
}

// ============================================================================
// fp16 HMMA GEMM core (UNCHANGED from Round 11): 512 threads, 16 warps,
// warp tile 64x32, CTA tile 128x256, BK=64, 4-stage cp.async pipeline.
// ============================================================================
#define BK       64
#define NCHUNK  (KTOT / BK)       // 16
#define NT       256
#define A_OFF   0
#define B_OFF   16384             // A: 128 rows x 128B
#define STG_BYTES 49152           // A 16K + B 32K
#define NSTG    4
#define SMEM_DYN (NSTG * STG_BYTES + 1024)
#define GTHREADS 512

__device__ __forceinline__ uint32_t sw128(uint32_t byte) {
    return byte ^ ((byte >> 3) & 0x70);
}

__device__ __forceinline__ void load_stage(
    uint32_t stg,
    const __half* __restrict__ A, const __half* __restrict__ B,
    int m0, int n0, int kBase, int tid)
{
    const int c16 = tid & 7;
    const int rg  = tid >> 3;       // 0..63
    const int kOff = kBase + c16 * 8;
#pragma unroll
    for (int j = 0; j < 2; j++) {
        int row = rg + j * 64;
        uint32_t sw = sw128((uint32_t)row * 128 + c16 * 16);
        CP_ASYNC16(stg + A_OFF + sw, A + (size_t)(m0 + row) * KTOT + kOff);
    }
#pragma unroll
    for (int j = 0; j < 4; j++) {
        int row = rg + j * 64;
        uint32_t sw = sw128((uint32_t)row * 128 + c16 * 16);
        CP_ASYNC16(stg + B_OFF + sw, B + (size_t)(n0 + row) * KTOT + kOff);
    }
}

template <int EPI>
__device__ __forceinline__ void run_gemm(
    const __half* __restrict__ A, const __half* __restrict__ B,
    const float* __restrict__ bias,
    float* __restrict__ Cf, __half* __restrict__ Ch,
    int Ntot, int m0, int n0, uint32_t sbase, int tid)
{
    const int warp = tid >> 5;          // 0..15
    const int lane = tid & 31;
    const int wm   = warp & 1;          // 2 M-slices of 64
    const int wn   = warp >> 1;         // 8 N-slices of 32

    const int lrow = lane & 7;
    const int quad = lane >> 3;
    const int aRow = wm * 64 + (quad & 1) * 8 + lrow;
    const int aKb  = (quad >> 1) * 16;
    const int bRow = wn * 32 + (quad >> 1) * 8 + lrow;
    const int bKb  = (quad & 1) * 16;

    uint32_t aSw[4], bSw[2];
#pragma unroll
    for (int i = 0; i < 4; i++)
        aSw[i] = sw128((uint32_t)(aRow + i * 16) * 128);
#pragma unroll
    for (int g = 0; g < 2; g++)
        bSw[g] = sw128((uint32_t)(bRow + g * 16) * 128);

    float acc[4][4][4];
#pragma unroll
    for (int i = 0; i < 4; i++)
#pragma unroll
        for (int j = 0; j < 4; j++)
#pragma unroll
            for (int q = 0; q < 4; q++) acc[i][j][q] = 0.0f;

    load_stage(sbase,                 A, B, m0, n0, 0,      tid); CP_COMMIT();
    load_stage(sbase + STG_BYTES,     A, B, m0, n0, BK,     tid); CP_COMMIT();
    load_stage(sbase + 2 * STG_BYTES, A, B, m0, n0, 2 * BK, tid); CP_COMMIT();

#pragma unroll 1
    for (int c = 0; c < NCHUNK; c++) {
        if (c < NCHUNK - 2)       { CP_WAIT2(); }
        else if (c == NCHUNK - 2) { CP_WAIT1(); }
        else                      { CP_WAIT0(); }
        __syncthreads();
        if (c + 3 < NCHUNK) {
            load_stage(sbase + ((c + 3) & 3) * STG_BYTES,
                       A, B, m0, n0, (c + 3) * BK, tid);
            CP_COMMIT();
        }
        const uint32_t stg = sbase + (c & 3) * STG_BYTES;

#pragma unroll
        for (int kk = 0; kk < 4; kk++) {
            uint32_t a_r[4][4], b_r[2][4];
            const uint32_t ko = (uint32_t)(kk * 32);
#pragma unroll
            for (int i = 0; i < 4; i++)
                ldsm_x4(a_r[i], stg + A_OFF + (aSw[i] ^ (ko + aKb)));
#pragma unroll
            for (int g = 0; g < 2; g++)
                ldsm_x4(b_r[g], stg + B_OFF + (bSw[g] ^ (ko + bKb)));
#pragma unroll
            for (int i = 0; i < 4; i++)
#pragma unroll
                for (int j = 0; j < 4; j++)
                    mma_f16(acc[i][j], a_r[i], &b_r[j >> 1][(j & 1) * 2]);
        }
    }

    const int er = lane >> 2;
    const int ec = (lane & 3) * 2;
#pragma unroll
    for (int i = 0; i < 4; i++) {
        int mrow = m0 + wm * 64 + i * 16 + er;
#pragma unroll
        for (int j = 0; j < 4; j++) {
            int n = n0 + wn * 32 + j * 8 + ec;
            float b0 = bias[n], b1 = bias[n + 1];
            float v0 = acc[i][j][0] + b0, v1 = acc[i][j][1] + b1;
            float v2 = acc[i][j][2] + b0, v3 = acc[i][j][3] + b1;
            size_t g0 = (size_t)mrow * Ntot + n;
            size_t g1 = (size_t)(mrow + 8) * Ntot + n;
            if (EPI == 0) {
                *(float2*)(Cf + g0) = make_float2(v0, v1);
                *(float2*)(Cf + g1) = make_float2(v2, v3);
            } else {
                __half2 p;
                p.x = __float2half_rn(fmaxf(v0, 0.0f));
                p.y = __float2half_rn(fmaxf(v1, 0.0f));
                *(__half2*)(Ch + g0) = p;
                p.x = __float2half_rn(fmaxf(v2, 0.0f));
                p.y = __float2half_rn(fmaxf(v3, 0.0f));
                *(__half2*)(Ch + g1) = p;
            }
        }
    }
}

// ============================================================================
// Fused gemm2 + gemm3 + log_p finalize (UNCHANGED)
// ============================================================================
__global__ __launch_bounds__(GTHREADS, 1)
void gemm_fused(const float* __restrict__ bd2, const float* __restrict__ bd3,
                float* __restrict__ out, float* __restrict__ out_scalar)
{
    extern __shared__ char dsm[];
    const uint32_t sbase = (smem_u32(dsm) + 1023) & ~1023u;
    const int tid = threadIdx.x;
    const int bid = blockIdx.x;

    if (bid < G2_CTAS) {
        const int mi = bid >> 2, ni = bid & 3;
        run_gemm<1>(g_h1, g_w2, bd2, nullptr, g_h2, DECH,
                    mi * 128, ni * NT, sbase, tid);
        __threadfence();
        __syncthreads();
        if (tid == 0) red_release_add1(&g_ready[mi]);
    } else if (bid < G2_CTAS + G3_CTAS) {
        const int b2 = bid - G2_CTAS;
        const int mi = b2 / 12, nj = b2 % 12;
        if (tid == 0) {
            while (ld_acq(&g_ready[mi]) < 4) __nanosleep(128);
        }
        __syncthreads();
        run_gemm<0>(g_h2, g_w3, bd3, out, nullptr, DIMX,
                    mi * 128, nj * NT, sbase, tid);
    } else {
        __shared__ float red2[512];
        red2[tid] = g_partial[tid];
        __syncthreads();
#pragma unroll
        for (int st = 256; st > 0; st >>= 1) {
            if (tid < st) red2[tid] += red2[tid + st];
            __syncthreads();
        }
        if (tid == 0) {
            float log_p_I = -logf((float)(DIMZ + 1)) * (float)B_HALF;
            *out_scalar = red2[0] + log_p_I;
        }
    }
}

// ============================================================================
extern "C" void kernel_launch(void* const* d_in, const int* in_sizes, int n_in,
                              void* d_out, int out_size) {
    const float* e1  = (const float*)d_in[0];
    const float* e2  = (const float*)d_in[1];
    const float* itv = (const float*)d_in[2];
    const float* W1  = (const float*)d_in[3];
    const float* b1  = (const float*)d_in[4];
    const float* W2  = (const float*)d_in[5];
    const float* b2  = (const float*)d_in[6];
    const float* W3  = (const float*)d_in[7];
    const float* b3  = (const float*)d_in[8];
    const float* Wd1 = (const float*)d_in[9];
    const float* bd1 = (const float*)d_in[10];
    const float* Wd2 = (const float*)d_in[11];
    const float* bd2 = (const float*)d_in[12];
    const float* Wd3 = (const float*)d_in[13];
    const float* bd3 = (const float*)d_in[14];
    float* out = (float*)d_out;

    cudaFuncSetAttribute(gemm_fused, cudaFuncAttributeMaxDynamicSharedMemorySize, SMEM_DYN);

    // prep: flow + dec1 + transposes (concurrent roles)
    prep_kernel<<<PR_TOTAL, 256>>>(e1, e2, itv, W1, b1, W2, b2, W3, b3,
                                   Wd1, bd1, Wd2, Wd3);

    // fused gemm2 + gemm3 + log_p finalize
    gemm_fused<<<G2_CTAS + G3_CTAS + 1, GTHREADS, SMEM_DYN>>>(
        bd2, bd3, out, out + ((size_t)out_size - 1));
}